// round 9
// baseline (speedup 1.0000x reference)
#include <cuda_runtime.h>
#include <math.h>

#define BB 2
#define N1 384
#define N2 384
#define DD 128
#define HH 128
#define LL 3
#define NF 54

// ---------------- scratch (device globals; no allocation) ----------------
static __device__ float g_h1g[BB*N1*DD];
static __device__ float g_h2g[BB*N2*DD];
static __device__ float g_hX [2*BB*N1*DD];   // ping-pong h
static __device__ float g_hAX[2*BB*N1*DD];   // ping-pong hA
static __device__ float g_E  [BB*N1*N1];     // symmetric e = P + P^T
static __device__ float g_m  [BB*N1];
static __device__ float g_iz [BB*N1];
static __device__ float g_p1 [5*BB*N1*HH];
static __device__ float g_p2 [5*BB*N2*HH];
static __device__ float g_WA [LL*DD*DD];
static __device__ float g_bA [LL*DD];
static __device__ float g_pec[576];
static __device__ float g_pev[576];

__device__ __forceinline__ float sigmoidf_(float x){ return 1.f/(1.f+__expf(-x)); }

// ---------------- fused: WA=W@A, bA=Wb@A  +  node projection ----------------
__global__ __launch_bounds__(128) void k_pre_node(const float* __restrict__ W,
                                                  const float* __restrict__ Wb,
                                                  const float* __restrict__ A,
                                                  const float* __restrict__ h1,
                                                  const float* __restrict__ h2,
                                                  const float* __restrict__ nW){
    int bi = blockIdx.x, d = threadIdx.x;
    if (bi < LL*DD){
        int l = bi / DD, k = bi % DD;
        __shared__ float sw[DD];
        __shared__ float sb[DD];
        sw[d] = W[(l*DD + k)*DD + d];
        if (k == 0) sb[d] = Wb[l*DD + d];
        __syncthreads();
        const float* Al = A + l*DD*DD;
        float acc = 0.f;
        #pragma unroll 4
        for (int m = 0; m < DD; m++) acc += sw[m]*Al[m*DD + d];
        g_WA[(l*DD + k)*DD + d] = acc;
        if (k == 0){
            float bacc = 0.f;
            #pragma unroll 4
            for (int m = 0; m < DD; m++) bacc += sb[m]*Al[m*DD + d];
            g_bA[l*DD + d] = bacc;
        }
    } else {
        int r0 = (bi - LL*DD)*4;
        __shared__ float sx[4][NF];
        bool lig = (r0 < BB*N1);
        const float* src = lig ? (h1 + r0*NF) : (h2 + (r0 - BB*N1)*NF);
        for (int idx = d; idx < 4*NF; idx += 128) ((float*)sx)[idx] = src[idx];
        __syncthreads();
        float acc[4] = {0.f,0.f,0.f,0.f};
        #pragma unroll 2
        for (int k = 0; k < NF; k++){
            float wv = nW[k*DD + d];
            #pragma unroll
            for (int ii = 0; ii < 4; ii++) acc[ii] += sx[ii][k]*wv;
        }
        float* dst = lig ? (g_h1g + r0*DD) : (g_h2g + (r0 - BB*N1)*DD);
        #pragma unroll
        for (int ii = 0; ii < 4; ii++) dst[ii*DD + d] = acc[ii];
    }
}

// ---------------- stage2: gat_h layer0 (96 blocks) + protein pair-proj (240 blocks) ----------------
__global__ __launch_bounds__(128) void k_stage2(const float* __restrict__ gatW,
                                                const float* __restrict__ gatWb,
                                                const float* __restrict__ W1){
    int bi = blockIdx.x, d = threadIdx.x;
    __shared__ float sx[16][DD];
    if (bi < 96){
        int r0 = bi*8;
        #pragma unroll
        for (int ii = 0; ii < 8; ii++) sx[ii][d] = g_h1g[(r0 + ii)*DD + d];
        __syncthreads();
        float wb = gatWb[d], bav = g_bA[d];
        float h[8], ha[8];
        #pragma unroll
        for (int ii = 0; ii < 8; ii++){ h[ii] = wb; ha[ii] = bav; }
        #pragma unroll 2
        for (int k = 0; k < DD; k++){
            float wv  = gatW[k*DD + d];
            float wav = g_WA[k*DD + d];
            #pragma unroll
            for (int ii = 0; ii < 8; ii++){
                h [ii] += sx[ii][k]*wv;
                ha[ii] += sx[ii][k]*wav;
            }
        }
        #pragma unroll
        for (int ii = 0; ii < 8; ii++){
            g_hX [(r0 + ii)*DD + d] = h [ii];
            g_hAX[(r0 + ii)*DD + d] = ha[ii];
        }
    } else {
        int pi = bi - 96;
        int m  = pi / 48;
        int r0 = (pi % 48)*16;
        #pragma unroll
        for (int ii = 0; ii < 16; ii++) sx[ii][d] = g_h2g[(r0 + ii)*DD + d];
        __syncthreads();
        const float* W = W1 + m*2*DD*HH + DD*HH;   // protein half, no bias
        float acc[16];
        #pragma unroll
        for (int ii = 0; ii < 16; ii++) acc[ii] = 0.f;
        #pragma unroll 2
        for (int k = 0; k < DD; k++){
            float wv = W[k*HH + d];
            #pragma unroll
            for (int ii = 0; ii < 16; ii++) acc[ii] = fmaf(sx[ii][k], wv, acc[ii]);
        }
        #pragma unroll
        for (int ii = 0; ii < 16; ii++) g_p2[(m*BB*N2 + r0 + ii)*HH + d] = acc[ii];
    }
}

// ---------------- E = P + P^T via tile-pairs (same total FLOPs as P) ----------------
// pair (ti<=tj) of 32x32 tiles; M1 = hA(i)·h(j)^T, M2 = hA(j)·h(i)^T
// E(i,j) = M1 + M2^T ; E(j,i) = transpose — both written coalesced via smem staging.
// smem: 4 k-major tiles [128][36] + sE[32][33] + sM2[32][33]
#define ESYM_SMEM ((4*128*36 + 2*32*33)*4)
__global__ __launch_bounds__(256) void k_esym(int cur){
    extern __shared__ float sm[];
    float* sAi = sm;                // hA i-tile, k-major [k][row]
    float* sHi = sm + 128*36;      // h  i-tile
    float* sAj = sm + 2*128*36;    // hA j-tile
    float* sHj = sm + 3*128*36;    // h  j-tile
    float* sE  = sm + 4*128*36;    // [32][33]
    float* sM2 = sE + 32*33;       // [32][33]
    int b = blockIdx.y;
    // decode pair index -> (ti, tj), ti<=tj, 12x12 tiles, 78 pairs
    int p = blockIdx.x, ti = 0;
    while (p >= 12 - ti){ p -= 12 - ti; ti++; }
    int tj = ti + p;
    int i0 = ti*32, j0 = tj*32;
    const float* hb  = g_hX  + cur*BB*N1*DD;
    const float* hab = g_hAX + cur*BB*N1*DD;
    int tid = threadIdx.x;
    const float* srcAi = hab + (b*N1 + i0)*DD;
    const float* srcHi = hb  + (b*N1 + i0)*DD;
    const float* srcAj = hab + (b*N1 + j0)*DD;
    const float* srcHj = hb  + (b*N1 + j0)*DD;
    #pragma unroll
    for (int q = 0; q < 4; q++){
        int idx = tid + q*256;
        int row = idx >> 5, kq = idx & 31;
        float4 v;
        v = *(const float4*)(srcAi + row*DD + kq*4);
        sAi[(kq*4+0)*36+row]=v.x; sAi[(kq*4+1)*36+row]=v.y;
        sAi[(kq*4+2)*36+row]=v.z; sAi[(kq*4+3)*36+row]=v.w;
        v = *(const float4*)(srcHi + row*DD + kq*4);
        sHi[(kq*4+0)*36+row]=v.x; sHi[(kq*4+1)*36+row]=v.y;
        sHi[(kq*4+2)*36+row]=v.z; sHi[(kq*4+3)*36+row]=v.w;
        v = *(const float4*)(srcAj + row*DD + kq*4);
        sAj[(kq*4+0)*36+row]=v.x; sAj[(kq*4+1)*36+row]=v.y;
        sAj[(kq*4+2)*36+row]=v.z; sAj[(kq*4+3)*36+row]=v.w;
        v = *(const float4*)(srcHj + row*DD + kq*4);
        sHj[(kq*4+0)*36+row]=v.x; sHj[(kq*4+1)*36+row]=v.y;
        sHj[(kq*4+2)*36+row]=v.z; sHj[(kq*4+3)*36+row]=v.w;
    }
    __syncthreads();
    int tx = tid & 15, ty = tid >> 4;     // 16x16 threads, 2x2 outputs each
    float m1[2][2] = {{0.f,0.f},{0.f,0.f}};
    float m2[2][2] = {{0.f,0.f},{0.f,0.f}};
    #pragma unroll 8
    for (int k = 0; k < DD; k++){
        float2 ai = *(const float2*)&sAi[k*36 + ty*2];
        float2 hj = *(const float2*)&sHj[k*36 + tx*2];
        float2 aj = *(const float2*)&sAj[k*36 + ty*2];
        float2 hi = *(const float2*)&sHi[k*36 + tx*2];
        m1[0][0] = fmaf(ai.x, hj.x, m1[0][0]);
        m1[0][1] = fmaf(ai.x, hj.y, m1[0][1]);
        m1[1][0] = fmaf(ai.y, hj.x, m1[1][0]);
        m1[1][1] = fmaf(ai.y, hj.y, m1[1][1]);
        m2[0][0] = fmaf(aj.x, hi.x, m2[0][0]);
        m2[0][1] = fmaf(aj.x, hi.y, m2[0][1]);
        m2[1][0] = fmaf(aj.y, hi.x, m2[1][0]);
        m2[1][1] = fmaf(aj.y, hi.y, m2[1][1]);
    }
    // stage M2 to smem so we can form M1 + M2^T
    #pragma unroll
    for (int r = 0; r < 2; r++)
        #pragma unroll
        for (int c = 0; c < 2; c++)
            sM2[(ty*2 + r)*33 + tx*2 + c] = m2[r][c];
    __syncthreads();
    #pragma unroll
    for (int r = 0; r < 2; r++)
        #pragma unroll
        for (int c = 0; c < 2; c++){
            int a = ty*2 + r, bcol = tx*2 + c;
            sE[a*33 + bcol] = m1[r][c] + sM2[bcol*33 + a];
        }
    __syncthreads();
    // write E(i,j)[row][col] = sE[row][col], and E(j,i)[row][col] = sE[col][row]
    #pragma unroll
    for (int q = 0; q < 4; q++){
        int idx = tid + q*256;
        int row = idx >> 5, col = idx & 31;
        g_E[(size_t)(b*N1 + i0 + row)*N1 + j0 + col] = sE[row*33 + col];
        g_E[(size_t)(b*N1 + j0 + row)*N1 + i0 + col] = sE[col*33 + row];
    }
}

// ---------------- per-row stats (== per-column stats by symmetry): m, invZ ----------------
__global__ __launch_bounds__(256) void k_stats(const float* __restrict__ adj){
    int w = threadIdx.x >> 5, lane = threadIdx.x & 31;
    int rg = blockIdx.x*8 + w;                 // global row 0..767
    const float* er = g_E + (size_t)rg*N1;
    const float* ar = adj + (size_t)rg*N1;
    float ev[12];
    float mx = -INFINITY;
    #pragma unroll
    for (int t = 0; t < 12; t++){
        int i = lane + t*32;
        float a = ar[i];
        float e = (a > 0.f) ? er[i] : -9e15f;
        ev[t] = e;
        mx = fmaxf(mx, e);
    }
    #pragma unroll
    for (int o = 16; o; o >>= 1) mx = fmaxf(mx, __shfl_xor_sync(0xffffffffu, mx, o));
    float sum = 0.f;
    #pragma unroll
    for (int t = 0; t < 12; t++) sum += __expf(ev[t] - mx);
    #pragma unroll
    for (int o = 16; o; o >>= 1) sum += __shfl_xor_sync(0xffffffffu, sum, o);
    if (lane == 0){
        g_m [rg] = mx;
        g_iz[rg] = 1.f/sum;
    }
}

// ---------------- fused: att on the fly, h'=relu(att@h), gate, next-layer h/hA ----------------
__global__ __launch_bounds__(128) void k_fuse(const float* __restrict__ adj,
                                              const float* __restrict__ gW,
                                              const float* __restrict__ gb,
                                              const float* __restrict__ gatW,
                                              const float* __restrict__ gatWb,
                                              int l, int has_next){
    int r0 = blockIdx.x*8;
    int b  = r0 / N1;
    int d  = threadIdx.x;
    const float* hb = g_hX + (l & 1)*BB*N1*DD;
    __shared__ float s_att[8][N1];
    __shared__ float s_m [N1];
    __shared__ float s_iz[N1];
    __shared__ float s_g[8][DD];
    __shared__ float s_c[8];
    __shared__ float sx[8][DD];
    for (int idx = d; idx < N1; idx += 128){
        s_m [idx] = g_m [b*N1 + idx];
        s_iz[idx] = g_iz[b*N1 + idx];
    }
    __syncthreads();
    for (int idx = d; idx < 8*N1; idx += 128){
        int ii = idx / N1, j = idx % N1;
        float a = adj[(size_t)(r0 + ii)*N1 + j];
        float wv = 0.f;
        if (a > 0.f){
            float e = g_E[(size_t)(r0 + ii)*N1 + j];
            wv = __expf(e - s_m[j])*s_iz[j]*a;
        }
        s_att[ii][j] = wv;
    }
    float xd[8];
    #pragma unroll
    for (int ii = 0; ii < 8; ii++) xd[ii] = g_h1g[(r0 + ii)*DD + d];
    __syncthreads();
    float hp[8];
    #pragma unroll
    for (int ii = 0; ii < 8; ii++) hp[ii] = 0.f;
    const float* hcol = hb + b*N1*DD + d;
    #pragma unroll 4
    for (int j = 0; j < N1; j++){
        float hv = hcol[j*DD];
        #pragma unroll
        for (int ii = 0; ii < 8; ii++) hp[ii] = fmaf(s_att[ii][j], hv, hp[ii]);
    }
    float gw1 = gW[l*2*DD + d], gw2 = gW[l*2*DD + DD + d], gbv = gb[l];
    #pragma unroll
    for (int ii = 0; ii < 8; ii++){
        hp[ii] = fmaxf(hp[ii], 0.f);
        s_g[ii][d] = fmaf(xd[ii], gw1, hp[ii]*gw2);
    }
    __syncthreads();
    int w = d >> 5, lane = d & 31;
    for (int ii = w; ii < 8; ii += 4){
        float s = s_g[ii][lane] + s_g[ii][lane+32] + s_g[ii][lane+64] + s_g[ii][lane+96];
        #pragma unroll
        for (int o = 16; o; o >>= 1) s += __shfl_xor_sync(0xffffffffu, s, o);
        if (lane == 0) s_c[ii] = sigmoidf_(s + gbv);
    }
    __syncthreads();
    #pragma unroll
    for (int ii = 0; ii < 8; ii++){
        float coeff = s_c[ii];
        float v = coeff*xd[ii] + (1.f - coeff)*hp[ii];
        g_h1g[(r0 + ii)*DD + d] = v;
        sx[ii][d] = v;
    }
    if (!has_next) return;
    __syncthreads();
    int nl = l + 1;
    const float* W  = gatW + nl*DD*DD;
    const float* WA = g_WA + nl*DD*DD;
    float wb  = gatWb[nl*DD + d];
    float bav = g_bA [nl*DD + d];
    float h[8], ha[8];
    #pragma unroll
    for (int ii = 0; ii < 8; ii++){ h[ii] = wb; ha[ii] = bav; }
    #pragma unroll 2
    for (int k = 0; k < DD; k++){
        float wv  = W [k*DD + d];
        float wav = WA[k*DD + d];
        #pragma unroll
        for (int ii = 0; ii < 8; ii++){
            h [ii] += sx[ii][k]*wv;
            ha[ii] += sx[ii][k]*wav;
        }
    }
    float* ho  = g_hX  + (nl & 1)*BB*N1*DD;
    float* hao = g_hAX + (nl & 1)*BB*N1*DD;
    #pragma unroll
    for (int ii = 0; ii < 8; ii++){
        ho [(r0 + ii)*DD + d] = h [ii];
        hao[(r0 + ii)*DD + d] = ha[ii];
    }
}

// ---------------- ligand pair projections (16 rows/block, 240 blocks) ----------------
__global__ __launch_bounds__(128) void k_proj1(const float* __restrict__ W1,
                                               const float* __restrict__ b1){
    int bi = blockIdx.x;
    int m  = bi / 48;
    int r0 = (bi % 48)*16;
    int hh = threadIdx.x;
    __shared__ float sx[16][DD];
    #pragma unroll
    for (int ii = 0; ii < 16; ii++) sx[ii][hh] = g_h1g[(r0 + ii)*DD + hh];
    __syncthreads();
    const float* W = W1 + m*2*DD*HH;
    float bias = b1[m*HH + hh];
    float acc[16];
    #pragma unroll
    for (int ii = 0; ii < 16; ii++) acc[ii] = bias;
    #pragma unroll 2
    for (int k = 0; k < DD; k++){
        float wv = W[k*HH + hh];
        #pragma unroll
        for (int ii = 0; ii < 16; ii++) acc[ii] = fmaf(sx[ii][k], wv, acc[ii]);
    }
    #pragma unroll
    for (int ii = 0; ii < 16; ii++) g_p1[(m*BB*N1 + r0 + ii)*HH + hh] = acc[ii];
}

// ---------------- pair energies: 16i x 32j tile, float4 mainloop ----------------
__global__ __launch_bounds__(256) void k_pair(const float* __restrict__ dmv,
                                              const float* __restrict__ c1,
                                              const float* __restrict__ c2,
                                              const float* __restrict__ eps,
                                              const float* __restrict__ sig,
                                              const float* __restrict__ val1,
                                              const float* __restrict__ val2,
                                              const float* __restrict__ nmm1,
                                              const float* __restrict__ nmm2,
                                              const float* __restrict__ W2,
                                              const float* __restrict__ b2,
                                              const float* __restrict__ vdwc){
    int bix = blockIdx.x;          // j tile 0..11
    int biy = blockIdx.y;          // i tile 0..47
    int r0  = biy*16;
    int b   = r0 / N1;
    int i1  = r0 % N1;
    int j0  = bix*32;
    __shared__ float s_p1[16][132];
    __shared__ float s_p2[32][132];
    __shared__ float s_w2[5][128];
    __shared__ float s_b2v[5];
    __shared__ float s_red[16];
    int tid = threadIdx.x, lane = tid & 31, w = tid >> 5;
    int j  = lane;
    int ia = w*2;
    for (int idx = tid; idx < 5*DD; idx += 256) s_w2[idx/DD][idx%DD] = W2[idx];
    if (tid < 5) s_b2v[tid] = b2[tid];
    float acc[2][5];
    #pragma unroll
    for (int q = 0; q < 2; q++)
        #pragma unroll
        for (int m = 0; m < 5; m++) acc[q][m] = 0.f;
    for (int m = 0; m < 5; m++){
        __syncthreads();
        #pragma unroll
        for (int q = 0; q < 2; q++){
            int idx = tid + q*256;
            int row = idx >> 5, q4 = idx & 31;
            float4 v = *(const float4*)(g_p1 + (size_t)(m*BB*N1 + r0 + row)*HH + q4*4);
            *(float4*)&s_p1[row][q4*4] = v;
        }
        #pragma unroll
        for (int q = 0; q < 4; q++){
            int idx = tid + q*256;
            int row = idx >> 5, q4 = idx & 31;
            float4 v = *(const float4*)(g_p2 + (size_t)(m*BB*N2 + b*N2 + j0 + row)*HH + q4*4);
            *(float4*)&s_p2[row][q4*4] = v;
        }
        __syncthreads();
        float a0 = 0.f, a1 = 0.f;
        #pragma unroll
        for (int hv = 0; hv < 32; hv++){
            float4 w4  = *(const float4*)&s_w2[m][hv*4];
            float4 p2v = *(const float4*)&s_p2[j][hv*4];
            float4 pa  = *(const float4*)&s_p1[ia][hv*4];
            float4 pb  = *(const float4*)&s_p1[ia+1][hv*4];
            a0 = fmaf(fmaxf(pa.x + p2v.x, 0.f), w4.x, a0);
            a0 = fmaf(fmaxf(pa.y + p2v.y, 0.f), w4.y, a0);
            a0 = fmaf(fmaxf(pa.z + p2v.z, 0.f), w4.z, a0);
            a0 = fmaf(fmaxf(pa.w + p2v.w, 0.f), w4.w, a0);
            a1 = fmaf(fmaxf(pb.x + p2v.x, 0.f), w4.x, a1);
            a1 = fmaf(fmaxf(pb.y + p2v.y, 0.f), w4.y, a1);
            a1 = fmaf(fmaxf(pb.z + p2v.z, 0.f), w4.z, a1);
            a1 = fmaf(fmaxf(pb.w + p2v.w, 0.f), w4.w, a1);
        }
        acc[0][m] = a0; acc[1][m] = a1;
    }
    float vdwc2 = vdwc[0]*vdwc[0];
    float ec = 0.f, ev = 0.f;
    int jl = j0 + j;
    float c2v = c2[b*N2 + jl], v2v = val2[b*N2 + jl], n2v = nmm2[b*N2 + jl];
    #pragma unroll
    for (int q = 0; q < 2; q++){
        int il = i1 + ia + q;
        float v0 = acc[q][0] + s_b2v[0];
        float v1 = acc[q][1] + s_b2v[1];
        float v2 = acc[q][2] + s_b2v[2];
        float v3 = acc[q][3] + s_b2v[3];
        float v4 = acc[q][4] + s_b2v[4];
        int pix = (b*N1 + il)*N2 + jl;
        const float* dv = dmv + (size_t)pix*3;
        float dx = dv[0], dy = dv[1], dz = dv[2];
        float dm = sqrtf(dx*dx + dy*dy + dz*dz + 1e-10f);
        if (dm < 0.5f) dm = 1e10f;
        float l2dm = __log2f(dm);
        float cA  = sigmoidf_(v0);
        float cN  = 2.f*sigmoidf_(v1) + 1.f;
        float q12 = c1[b*N1 + il]*c2v;
        float e_c = cA*q12*exp2f(-cN*l2dm);
        e_c *= val1[b*N1 + il]*v2v;
        e_c = fminf(fmaxf(e_c, -100.f), 100.f);
        float vAv = (0.6f*sigmoidf_(v2) + 0.7f)*vdwc2*eps[pix];
        float vBv = tanhf(v3)*0.6f + 0.7f;
        float vNv = 2.f*sigmoidf_(v4) + 5.f;
        float dm0 = sig[pix]*vBv;
        if (dm0 < 1e-4f) dm0 = 1.f;
        float r  = exp2f(vNv*(__log2f(dm0) - l2dm));
        float e_v = vAv*(r*r - 2.f*r);
        e_v *= nmm1[b*N1 + il]*n2v;
        e_v = fminf(e_v, 100.f);
        ec += e_c; ev += e_v;
    }
    #pragma unroll
    for (int o = 16; o; o >>= 1){
        ec += __shfl_xor_sync(0xffffffffu, ec, o);
        ev += __shfl_xor_sync(0xffffffffu, ev, o);
    }
    if (lane == 0){ s_red[w] = ec; s_red[8 + w] = ev; }
    __syncthreads();
    if (tid == 0){
        float tec = 0.f, tev = 0.f;
        #pragma unroll
        for (int qq = 0; qq < 8; qq++){ tec += s_red[qq]; tev += s_red[8 + qq]; }
        g_pec[biy*12 + bix] = tec;
        g_pev[biy*12 + bix] = tev;
    }
}

// ---------------- finalize ----------------
__global__ __launch_bounds__(DD) void k_final(const float* __restrict__ valid1,
                                              const float* __restrict__ delta_uff,
                                              const float* __restrict__ duff,
                                              const float* __restrict__ iW1,
                                              const float* __restrict__ ib1,
                                              const float* __restrict__ iW2,
                                              const float* __restrict__ ib2,
                                              float* __restrict__ out){
    int b = blockIdx.x, d = threadIdx.x;
    __shared__ float s_hs[DD];
    __shared__ float s_red[DD];
    float hs = 0.f;
    for (int i = 0; i < N1; i++) hs += g_h1g[(b*N1 + i)*DD + d]*valid1[b*N1 + i];
    s_hs[d] = hs;
    __syncthreads();
    float hid = ib1[d];
    #pragma unroll 4
    for (int k = 0; k < DD; k++) hid += s_hs[k]*iW1[k*HH + d];
    hid = fmaxf(hid, 0.f);
    s_red[d] = hid*iW2[d];
    __syncthreads();
    for (int s = 64; s; s >>= 1){ if (d < s) s_red[d] += s_red[d + s]; __syncthreads(); }
    float inter = s_red[0] + ib2[0];
    __syncthreads();
    float tec = 0.f;
    for (int q = d; q < 288; q += DD) tec += g_pec[b*288 + q];
    s_red[d] = tec;
    __syncthreads();
    for (int s = 64; s; s >>= 1){ if (d < s) s_red[d] += s_red[d + s]; __syncthreads(); }
    float tecs = s_red[0];
    __syncthreads();
    float tev = 0.f;
    for (int q = d; q < 288; q += DD) tev += g_pev[b*288 + q];
    s_red[d] = tev;
    __syncthreads();
    for (int s = 64; s; s >>= 1){ if (d < s) s_red[d] += s_red[d + s]; __syncthreads(); }
    if (d == 0){
        out[b*4 + 0] = tecs;
        out[b*4 + 1] = s_red[0];
        out[b*4 + 2] = duff[0]*duff[0]*delta_uff[b];
        out[b*4 + 3] = inter;
    }
}

// ---------------- launch ----------------
// d_in follows setup_inputs() dict insertion order:
//   0:h1 1:h2 2:adj1 3:dmv 4:charge1 5:charge2 6:vdw_epsilon 7:vdw_sigma
//   8:delta_uff 9:valid1 10:valid2 11:no_metal1 12:no_metal2 13:node_W
//   14:gat_W 15:gat_Wb 16:gat_A 17:gat_gW 18:gat_gb 19:pair_W1 20:pair_b1
//   21:pair_W2 22:pair_b2 23:vdw_coeff 24:duff_coeff 25:int_W1 26:int_b1
//   27:int_W2 28:int_b2
extern "C" void kernel_launch(void* const* d_in, const int* in_sizes, int n_in,
                              void* d_out, int out_size){
    const float* h1        = (const float*)d_in[0];
    const float* h2        = (const float*)d_in[1];
    const float* adj1      = (const float*)d_in[2];
    const float* dmv       = (const float*)d_in[3];
    const float* charge1   = (const float*)d_in[4];
    const float* charge2   = (const float*)d_in[5];
    const float* eps       = (const float*)d_in[6];
    const float* sig       = (const float*)d_in[7];
    const float* delta_uff = (const float*)d_in[8];
    const float* valid1    = (const float*)d_in[9];
    const float* valid2    = (const float*)d_in[10];
    const float* nm1       = (const float*)d_in[11];
    const float* nm2       = (const float*)d_in[12];
    const float* nodeW     = (const float*)d_in[13];
    const float* gatW      = (const float*)d_in[14];
    const float* gatWb     = (const float*)d_in[15];
    const float* gatA      = (const float*)d_in[16];
    const float* gatgW     = (const float*)d_in[17];
    const float* gatgb     = (const float*)d_in[18];
    const float* pW1       = (const float*)d_in[19];
    const float* pb1       = (const float*)d_in[20];
    const float* pW2       = (const float*)d_in[21];
    const float* pb2       = (const float*)d_in[22];
    const float* vdwc      = (const float*)d_in[23];
    const float* duffc     = (const float*)d_in[24];
    const float* iW1       = (const float*)d_in[25];
    const float* ib1       = (const float*)d_in[26];
    const float* iW2       = (const float*)d_in[27];
    const float* ib2       = (const float*)d_in[28];
    float* out = (float*)d_out;

    static int attr_set = 0;
    if (!attr_set){
        cudaFuncSetAttribute(k_esym, cudaFuncAttributeMaxDynamicSharedMemorySize, ESYM_SMEM);
        attr_set = 1;
    }

    k_pre_node<<<LL*DD + (BB*(N1+N2))/4, 128>>>(gatW, gatWb, gatA, h1, h2, nodeW);
    k_stage2<<<96 + 240, 128>>>(gatW, gatWb, pW1);
    for (int l = 0; l < LL; l++){
        k_esym <<<dim3(78, BB), 256, ESYM_SMEM>>>(l & 1);
        k_stats<<<BB*N1/8, 256>>>(adj1);
        k_fuse <<<BB*N1/8, 128>>>(adj1, gatgW, gatgb, gatW, gatWb, l, (l < LL-1) ? 1 : 0);
    }
    k_proj1<<<240, 128>>>(pW1, pb1);
    k_pair<<<dim3(N2/32, BB*N1/16), 256>>>(dmv, charge1, charge2, eps, sig,
                                           valid1, valid2, nm1, nm2, pW2, pb2, vdwc);
    k_final<<<BB, DD>>>(valid1, delta_uff, duffc, iW1, ib1, iW2, ib2, out);
}

// round 11
// speedup vs baseline: 1.1185x; 1.1185x over previous
#include <cuda_runtime.h>
#include <math.h>

#define BB 2
#define N1 384
#define N2 384
#define DD 128
#define HH 128
#define LL 3
#define NF 54

// ---------------- scratch (device globals; no allocation) ----------------
static __device__ float g_h1g[BB*N1*DD];
static __device__ float g_h2g[BB*N2*DD];
static __device__ float g_hX [2*BB*N1*DD];   // ping-pong h
static __device__ float g_hAX[2*BB*N1*DD];   // ping-pong hA
static __device__ float g_P  [BB*N1*N1];
static __device__ float g_att[BB*N1*N1];
static __device__ float g_p1 [5*BB*N1*HH];
static __device__ float g_p2 [5*BB*N2*HH];
static __device__ float g_WA [LL*DD*DD];
static __device__ float g_bA [LL*DD];
static __device__ float g_pec[576];
static __device__ float g_pev[576];

__device__ __forceinline__ float sigmoidf_(float x){ return 1.f/(1.f+__expf(-x)); }

// packed f32x2 helpers (sm_100+ PTX): only add/mul/fma exist in f32x2 form.
typedef unsigned long long u64t;
__device__ __forceinline__ u64t px_add(u64t a, u64t b){
    u64t r; asm("add.rn.f32x2 %0, %1, %2;" : "=l"(r) : "l"(a), "l"(b)); return r;
}
__device__ __forceinline__ u64t px_fma(u64t a, u64t b, u64t c){
    u64t r; asm("fma.rn.f32x2 %0, %1, %2, %3;" : "=l"(r) : "l"(a), "l"(b), "l"(c)); return r;
}
// relu on a packed pair: unpack to register halves (mov.b64 = reg-pair alias, no SASS movement),
// two FMNMX, repack.
__device__ __forceinline__ u64t px_max0(u64t a){
    float x, y;
    asm("mov.b64 {%0, %1}, %2;" : "=f"(x), "=f"(y) : "l"(a));
    x = fmaxf(x, 0.f);
    y = fmaxf(y, 0.f);
    u64t r;
    asm("mov.b64 %0, {%1, %2};" : "=l"(r) : "f"(x), "f"(y));
    return r;
}
__device__ __forceinline__ float px_sum(u64t v){
    float x, y;
    asm("mov.b64 {%0, %1}, %2;" : "=f"(x), "=f"(y) : "l"(v));
    return x + y;
}

// ---------------- fused: WA=W@A, bA=Wb@A  +  node projection ----------------
__global__ __launch_bounds__(128) void k_pre_node(const float* __restrict__ W,
                                                  const float* __restrict__ Wb,
                                                  const float* __restrict__ A,
                                                  const float* __restrict__ h1,
                                                  const float* __restrict__ h2,
                                                  const float* __restrict__ nW){
    int bi = blockIdx.x, d = threadIdx.x;
    if (bi < LL*DD){
        int l = bi / DD, k = bi % DD;
        __shared__ float sw[DD];
        __shared__ float sb[DD];
        sw[d] = W[(l*DD + k)*DD + d];
        if (k == 0) sb[d] = Wb[l*DD + d];
        __syncthreads();
        const float* Al = A + l*DD*DD;
        float acc = 0.f;
        #pragma unroll 4
        for (int m = 0; m < DD; m++) acc += sw[m]*Al[m*DD + d];
        g_WA[(l*DD + k)*DD + d] = acc;
        if (k == 0){
            float bacc = 0.f;
            #pragma unroll 4
            for (int m = 0; m < DD; m++) bacc += sb[m]*Al[m*DD + d];
            g_bA[l*DD + d] = bacc;
        }
    } else {
        int r0 = (bi - LL*DD)*4;
        __shared__ float sx[4][NF];
        bool lig = (r0 < BB*N1);
        const float* src = lig ? (h1 + r0*NF) : (h2 + (r0 - BB*N1)*NF);
        for (int idx = d; idx < 4*NF; idx += 128) ((float*)sx)[idx] = src[idx];
        __syncthreads();
        float acc[4] = {0.f,0.f,0.f,0.f};
        #pragma unroll 2
        for (int k = 0; k < NF; k++){
            float wv = nW[k*DD + d];
            #pragma unroll
            for (int ii = 0; ii < 4; ii++) acc[ii] += sx[ii][k]*wv;
        }
        float* dst = lig ? (g_h1g + r0*DD) : (g_h2g + (r0 - BB*N1)*DD);
        #pragma unroll
        for (int ii = 0; ii < 4; ii++) dst[ii*DD + d] = acc[ii];
    }
}

// ---------------- stage2: gat_h layer0 (96 blocks) + protein pair-proj (240 blocks) ----------------
__global__ __launch_bounds__(128) void k_stage2(const float* __restrict__ gatW,
                                                const float* __restrict__ gatWb,
                                                const float* __restrict__ W1){
    int bi = blockIdx.x, d = threadIdx.x;
    __shared__ float sx[16][DD];
    if (bi < 96){
        int r0 = bi*8;
        #pragma unroll
        for (int ii = 0; ii < 8; ii++) sx[ii][d] = g_h1g[(r0 + ii)*DD + d];
        __syncthreads();
        float wb = gatWb[d], bav = g_bA[d];
        float h[8], ha[8];
        #pragma unroll
        for (int ii = 0; ii < 8; ii++){ h[ii] = wb; ha[ii] = bav; }
        #pragma unroll 2
        for (int k = 0; k < DD; k++){
            float wv  = gatW[k*DD + d];
            float wav = g_WA[k*DD + d];
            #pragma unroll
            for (int ii = 0; ii < 8; ii++){
                h [ii] += sx[ii][k]*wv;
                ha[ii] += sx[ii][k]*wav;
            }
        }
        #pragma unroll
        for (int ii = 0; ii < 8; ii++){
            g_hX [(r0 + ii)*DD + d] = h [ii];
            g_hAX[(r0 + ii)*DD + d] = ha[ii];
        }
    } else {
        int pi = bi - 96;
        int m  = pi / 48;
        int r0 = (pi % 48)*16;
        #pragma unroll
        for (int ii = 0; ii < 16; ii++) sx[ii][d] = g_h2g[(r0 + ii)*DD + d];
        __syncthreads();
        const float* W = W1 + m*2*DD*HH + DD*HH;   // protein half, no bias
        float acc[16];
        #pragma unroll
        for (int ii = 0; ii < 16; ii++) acc[ii] = 0.f;
        #pragma unroll 2
        for (int k = 0; k < DD; k++){
            float wv = W[k*HH + d];
            #pragma unroll
            for (int ii = 0; ii < 16; ii++) acc[ii] = fmaf(sx[ii][k], wv, acc[ii]);
        }
        #pragma unroll
        for (int ii = 0; ii < 16; ii++) g_p2[(m*BB*N2 + r0 + ii)*HH + d] = acc[ii];
    }
}

// ---------------- P = hA @ h^T : 32x64 tiles, 144 blocks ----------------
__global__ __launch_bounds__(256) void k_e(int cur){
    const float* hb  = g_hX  + cur*BB*N1*DD;
    const float* hab = g_hAX + cur*BB*N1*DD;
    int b = blockIdx.z, j0 = blockIdx.y*32, k0 = blockIdx.x*64;
    __shared__ float sA[64][36];
    __shared__ float sB[64][68];
    int tid = threadIdx.x;
    int tx = tid & 15, ty = tid >> 4;
    float acc[2][4];
    #pragma unroll
    for (int r = 0; r < 2; r++)
        #pragma unroll
        for (int c = 0; c < 4; c++) acc[r][c] = 0.f;
    const float* baseA = hab + (b*N1 + j0)*DD;
    const float* baseB = hb  + (b*N1 + k0)*DD;
    for (int ks = 0; ks < 2; ks++){
        __syncthreads();
        #pragma unroll
        for (int q = 0; q < 2; q++){
            int idx = tid + q*256;
            int row = idx & 31, kq = idx >> 5;
            float4 va = *(const float4*)(baseA + row*DD + ks*64 + kq*4);
            sA[kq*4+0][row] = va.x; sA[kq*4+1][row] = va.y;
            sA[kq*4+2][row] = va.z; sA[kq*4+3][row] = va.w;
        }
        #pragma unroll
        for (int q = 0; q < 4; q++){
            int idx = tid + q*256;
            int row = idx & 63, kq = idx >> 6;
            float4 vb = *(const float4*)(baseB + row*DD + ks*64 + kq*4);
            sB[kq*4+0][row] = vb.x; sB[kq*4+1][row] = vb.y;
            sB[kq*4+2][row] = vb.z; sB[kq*4+3][row] = vb.w;
        }
        __syncthreads();
        #pragma unroll 8
        for (int kk = 0; kk < 64; kk++){
            float2 av = *(const float2*)&sA[kk][ty*2];
            float4 bv = *(const float4*)&sB[kk][tx*4];
            acc[0][0] = fmaf(av.x, bv.x, acc[0][0]);
            acc[0][1] = fmaf(av.x, bv.y, acc[0][1]);
            acc[0][2] = fmaf(av.x, bv.z, acc[0][2]);
            acc[0][3] = fmaf(av.x, bv.w, acc[0][3]);
            acc[1][0] = fmaf(av.y, bv.x, acc[1][0]);
            acc[1][1] = fmaf(av.y, bv.y, acc[1][1]);
            acc[1][2] = fmaf(av.y, bv.z, acc[1][2]);
            acc[1][3] = fmaf(av.y, bv.w, acc[1][3]);
        }
    }
    #pragma unroll
    for (int r = 0; r < 2; r++){
        float4 o = make_float4(acc[r][0], acc[r][1], acc[r][2], acc[r][3]);
        *(float4*)&g_P[(b*N1 + j0 + ty*2 + r)*N1 + k0 + tx*4] = o;
    }
}

// ---------------- column softmax of e = P + P^T, masked by adj (8 cols/block, 96 blocks) ----------------
__global__ __launch_bounds__(256) void k_soft(const float* __restrict__ adj){
    __shared__ float sCol[N1][9];
    __shared__ float sRow[8][385];
    int b  = blockIdx.y;
    int c0 = blockIdx.x*8;
    int tid = threadIdx.x;
    for (int idx = tid; idx < N1*8; idx += 256){
        int r = idx >> 3, c = idx & 7;
        float p = g_P[(b*N1 + r)*N1 + c0 + c];
        float a = adj[(b*N1 + r)*N1 + c0 + c];
        sCol[r][c] = (a > 0.f) ? p : -9e15f;
    }
    for (int idx = tid; idx < 8*N1; idx += 256){
        int cc = idx / N1, r = idx % N1;
        sRow[cc][r] = g_P[(b*N1 + c0 + cc)*N1 + r];
    }
    __syncthreads();
    int w = tid >> 5, lane = tid & 31;
    {   // warp w owns column w
        int cc = w;
        float ev[12];
        float mx = -INFINITY;
        #pragma unroll
        for (int t = 0; t < 12; t++){
            int r = lane + t*32;
            float e = sCol[r][cc];
            if (e > -8e15f) e += sRow[cc][r];
            ev[t] = e;
            mx = fmaxf(mx, e);
        }
        #pragma unroll
        for (int o = 16; o; o >>= 1) mx = fmaxf(mx, __shfl_xor_sync(0xffffffffu, mx, o));
        float sum = 0.f;
        #pragma unroll
        for (int t = 0; t < 12; t++){
            float x = __expf(ev[t] - mx);
            ev[t] = x; sum += x;
        }
        #pragma unroll
        for (int o = 16; o; o >>= 1) sum += __shfl_xor_sync(0xffffffffu, sum, o);
        float inv = 1.f/sum;
        #pragma unroll
        for (int t = 0; t < 12; t++) sCol[lane + t*32][cc] = ev[t]*inv;
    }
    __syncthreads();
    for (int idx = tid; idx < N1*8; idx += 256){
        int r = idx >> 3, c = idx & 7;
        float a = adj[(b*N1 + r)*N1 + c0 + c];
        g_att[(b*N1 + r)*N1 + c0 + c] = sCol[r][c]*a;
    }
}

// ---------------- fused: h'=relu(att@h), gated residual, then next-layer h/hA ----------------
__global__ __launch_bounds__(128) void k_fuse(const float* __restrict__ gW,
                                              const float* __restrict__ gb,
                                              const float* __restrict__ gatW,
                                              const float* __restrict__ gatWb,
                                              int l, int has_next){
    int r0 = blockIdx.x*8;
    int b  = r0 / N1;
    int d  = threadIdx.x;
    const float* hb = g_hX + (l & 1)*BB*N1*DD;
    __shared__ float s_att[8][N1];
    __shared__ float s_g[8][DD];
    __shared__ float s_c[8];
    __shared__ float sx[8][DD];
    for (int idx = d; idx < 8*N1; idx += DD){
        int ii = idx / N1, j = idx % N1;
        s_att[ii][j] = g_att[(r0 + ii)*N1 + j];
    }
    float xd[8];
    #pragma unroll
    for (int ii = 0; ii < 8; ii++) xd[ii] = g_h1g[(r0 + ii)*DD + d];
    __syncthreads();
    float hp[8];
    #pragma unroll
    for (int ii = 0; ii < 8; ii++) hp[ii] = 0.f;
    const float* hcol = hb + b*N1*DD + d;
    #pragma unroll 4
    for (int j = 0; j < N1; j++){
        float hv = hcol[j*DD];
        #pragma unroll
        for (int ii = 0; ii < 8; ii++) hp[ii] = fmaf(s_att[ii][j], hv, hp[ii]);
    }
    float gw1 = gW[l*2*DD + d], gw2 = gW[l*2*DD + DD + d], gbv = gb[l];
    #pragma unroll
    for (int ii = 0; ii < 8; ii++){
        hp[ii] = fmaxf(hp[ii], 0.f);
        s_g[ii][d] = fmaf(xd[ii], gw1, hp[ii]*gw2);
    }
    __syncthreads();
    int w = d >> 5, lane = d & 31;
    for (int ii = w; ii < 8; ii += 4){
        float s = s_g[ii][lane] + s_g[ii][lane+32] + s_g[ii][lane+64] + s_g[ii][lane+96];
        #pragma unroll
        for (int o = 16; o; o >>= 1) s += __shfl_xor_sync(0xffffffffu, s, o);
        if (lane == 0) s_c[ii] = sigmoidf_(s + gbv);
    }
    __syncthreads();
    #pragma unroll
    for (int ii = 0; ii < 8; ii++){
        float coeff = s_c[ii];
        float v = coeff*xd[ii] + (1.f - coeff)*hp[ii];
        g_h1g[(r0 + ii)*DD + d] = v;
        sx[ii][d] = v;
    }
    if (!has_next) return;
    __syncthreads();
    int nl = l + 1;
    const float* W  = gatW + nl*DD*DD;
    const float* WA = g_WA + nl*DD*DD;
    float wb  = gatWb[nl*DD + d];
    float bav = g_bA [nl*DD + d];
    float h[8], ha[8];
    #pragma unroll
    for (int ii = 0; ii < 8; ii++){ h[ii] = wb; ha[ii] = bav; }
    #pragma unroll 2
    for (int k = 0; k < DD; k++){
        float wv  = W [k*DD + d];
        float wav = WA[k*DD + d];
        #pragma unroll
        for (int ii = 0; ii < 8; ii++){
            h [ii] += sx[ii][k]*wv;
            ha[ii] += sx[ii][k]*wav;
        }
    }
    float* ho  = g_hX  + (nl & 1)*BB*N1*DD;
    float* hao = g_hAX + (nl & 1)*BB*N1*DD;
    #pragma unroll
    for (int ii = 0; ii < 8; ii++){
        ho [(r0 + ii)*DD + d] = h [ii];
        hao[(r0 + ii)*DD + d] = ha[ii];
    }
}

// ---------------- ligand pair projections (16 rows/block, 240 blocks) ----------------
__global__ __launch_bounds__(128) void k_proj1(const float* __restrict__ W1,
                                               const float* __restrict__ b1){
    int bi = blockIdx.x;
    int m  = bi / 48;
    int r0 = (bi % 48)*16;
    int hh = threadIdx.x;
    __shared__ float sx[16][DD];
    #pragma unroll
    for (int ii = 0; ii < 16; ii++) sx[ii][hh] = g_h1g[(r0 + ii)*DD + hh];
    __syncthreads();
    const float* W = W1 + m*2*DD*HH;
    float bias = b1[m*HH + hh];
    float acc[16];
    #pragma unroll
    for (int ii = 0; ii < 16; ii++) acc[ii] = bias;
    #pragma unroll 2
    for (int k = 0; k < DD; k++){
        float wv = W[k*HH + hh];
        #pragma unroll
        for (int ii = 0; ii < 16; ii++) acc[ii] = fmaf(sx[ii][k], wv, acc[ii]);
    }
    #pragma unroll
    for (int ii = 0; ii < 16; ii++) g_p1[(m*BB*N1 + r0 + ii)*HH + hh] = acc[ii];
}

// ---------------- pair energies: 16i x 32j tile, packed f32x2 mainloop ----------------
__global__ __launch_bounds__(256) void k_pair(const float* __restrict__ dmv,
                                              const float* __restrict__ c1,
                                              const float* __restrict__ c2,
                                              const float* __restrict__ eps,
                                              const float* __restrict__ sig,
                                              const float* __restrict__ val1,
                                              const float* __restrict__ val2,
                                              const float* __restrict__ nmm1,
                                              const float* __restrict__ nmm2,
                                              const float* __restrict__ W2,
                                              const float* __restrict__ b2,
                                              const float* __restrict__ vdwc){
    int bix = blockIdx.x;          // j tile 0..11
    int biy = blockIdx.y;          // i tile 0..47
    int r0  = biy*16;
    int b   = r0 / N1;
    int i1  = r0 % N1;
    int j0  = bix*32;
    __shared__ __align__(16) float s_p1[16][132];
    __shared__ __align__(16) float s_p2[32][132];
    __shared__ __align__(16) float s_w2[5][128];
    __shared__ float s_b2v[5];
    __shared__ float s_red[16];
    int tid = threadIdx.x, lane = tid & 31, w = tid >> 5;
    int j  = lane;
    int ia = w*2;
    for (int idx = tid; idx < 5*DD; idx += 256) s_w2[idx/DD][idx%DD] = W2[idx];
    if (tid < 5) s_b2v[tid] = b2[tid];
    float acc[2][5];
    for (int m = 0; m < 5; m++){
        __syncthreads();
        #pragma unroll
        for (int q = 0; q < 2; q++){
            int idx = tid + q*256;
            int row = idx >> 5, q4 = idx & 31;
            float4 v = *(const float4*)(g_p1 + (size_t)(m*BB*N1 + r0 + row)*HH + q4*4);
            *(float4*)&s_p1[row][q4*4] = v;
        }
        #pragma unroll
        for (int q = 0; q < 4; q++){
            int idx = tid + q*256;
            int row = idx >> 5, q4 = idx & 31;
            float4 v = *(const float4*)(g_p2 + (size_t)(m*BB*N2 + b*N2 + j0 + row)*HH + q4*4);
            *(float4*)&s_p2[row][q4*4] = v;
        }
        __syncthreads();
        u64t a0l = 0ULL, a0h = 0ULL, a1l = 0ULL, a1h = 0ULL;
        #pragma unroll
        for (int hv = 0; hv < 32; hv++){
            ulonglong2 w4  = *(const ulonglong2*)&s_w2[m][hv*4];
            ulonglong2 p2v = *(const ulonglong2*)&s_p2[j][hv*4];
            ulonglong2 pa  = *(const ulonglong2*)&s_p1[ia][hv*4];
            ulonglong2 pb  = *(const ulonglong2*)&s_p1[ia+1][hv*4];
            a0l = px_fma(px_max0(px_add(pa.x, p2v.x)), w4.x, a0l);
            a0h = px_fma(px_max0(px_add(pa.y, p2v.y)), w4.y, a0h);
            a1l = px_fma(px_max0(px_add(pb.x, p2v.x)), w4.x, a1l);
            a1h = px_fma(px_max0(px_add(pb.y, p2v.y)), w4.y, a1h);
        }
        acc[0][m] = px_sum(a0l) + px_sum(a0h);
        acc[1][m] = px_sum(a1l) + px_sum(a1h);
    }
    float vdwc2 = vdwc[0]*vdwc[0];
    float ec = 0.f, ev = 0.f;
    int jl = j0 + j;
    float c2v = c2[b*N2 + jl], v2v = val2[b*N2 + jl], n2v = nmm2[b*N2 + jl];
    #pragma unroll
    for (int q = 0; q < 2; q++){
        int il = i1 + ia + q;
        float v0 = acc[q][0] + s_b2v[0];
        float v1 = acc[q][1] + s_b2v[1];
        float v2 = acc[q][2] + s_b2v[2];
        float v3 = acc[q][3] + s_b2v[3];
        float v4 = acc[q][4] + s_b2v[4];
        int pix = (b*N1 + il)*N2 + jl;
        const float* dv = dmv + (size_t)pix*3;
        float dx = dv[0], dy = dv[1], dz = dv[2];
        float dm = sqrtf(dx*dx + dy*dy + dz*dz + 1e-10f);
        if (dm < 0.5f) dm = 1e10f;
        float l2dm = __log2f(dm);
        float cA  = sigmoidf_(v0);
        float cN  = 2.f*sigmoidf_(v1) + 1.f;
        float q12 = c1[b*N1 + il]*c2v;
        float e_c = cA*q12*exp2f(-cN*l2dm);
        e_c *= val1[b*N1 + il]*v2v;
        e_c = fminf(fmaxf(e_c, -100.f), 100.f);
        float vAv = (0.6f*sigmoidf_(v2) + 0.7f)*vdwc2*eps[pix];
        float vBv = tanhf(v3)*0.6f + 0.7f;
        float vNv = 2.f*sigmoidf_(v4) + 5.f;
        float dm0 = sig[pix]*vBv;
        if (dm0 < 1e-4f) dm0 = 1.f;
        float r  = exp2f(vNv*(__log2f(dm0) - l2dm));
        float e_v = vAv*(r*r - 2.f*r);
        e_v *= nmm1[b*N1 + il]*n2v;
        e_v = fminf(e_v, 100.f);
        ec += e_c; ev += e_v;
    }
    #pragma unroll
    for (int o = 16; o; o >>= 1){
        ec += __shfl_xor_sync(0xffffffffu, ec, o);
        ev += __shfl_xor_sync(0xffffffffu, ev, o);
    }
    if (lane == 0){ s_red[w] = ec; s_red[8 + w] = ev; }
    __syncthreads();
    if (tid == 0){
        float tec = 0.f, tev = 0.f;
        #pragma unroll
        for (int qq = 0; qq < 8; qq++){ tec += s_red[qq]; tev += s_red[8 + qq]; }
        g_pec[biy*12 + bix] = tec;
        g_pev[biy*12 + bix] = tev;
    }
}

// ---------------- finalize ----------------
__global__ __launch_bounds__(DD) void k_final(const float* __restrict__ valid1,
                                              const float* __restrict__ delta_uff,
                                              const float* __restrict__ duff,
                                              const float* __restrict__ iW1,
                                              const float* __restrict__ ib1,
                                              const float* __restrict__ iW2,
                                              const float* __restrict__ ib2,
                                              float* __restrict__ out){
    int b = blockIdx.x, d = threadIdx.x;
    __shared__ float s_hs[DD];
    __shared__ float s_red[DD];
    float hs = 0.f;
    for (int i = 0; i < N1; i++) hs += g_h1g[(b*N1 + i)*DD + d]*valid1[b*N1 + i];
    s_hs[d] = hs;
    __syncthreads();
    float hid = ib1[d];
    #pragma unroll 4
    for (int k = 0; k < DD; k++) hid += s_hs[k]*iW1[k*HH + d];
    hid = fmaxf(hid, 0.f);
    s_red[d] = hid*iW2[d];
    __syncthreads();
    for (int s = 64; s; s >>= 1){ if (d < s) s_red[d] += s_red[d + s]; __syncthreads(); }
    float inter = s_red[0] + ib2[0];
    __syncthreads();
    float tec = 0.f;
    for (int q = d; q < 288; q += DD) tec += g_pec[b*288 + q];
    s_red[d] = tec;
    __syncthreads();
    for (int s = 64; s; s >>= 1){ if (d < s) s_red[d] += s_red[d + s]; __syncthreads(); }
    float tecs = s_red[0];
    __syncthreads();
    float tev = 0.f;
    for (int q = d; q < 288; q += DD) tev += g_pev[b*288 + q];
    s_red[d] = tev;
    __syncthreads();
    for (int s = 64; s; s >>= 1){ if (d < s) s_red[d] += s_red[d + s]; __syncthreads(); }
    if (d == 0){
        out[b*4 + 0] = tecs;
        out[b*4 + 1] = s_red[0];
        out[b*4 + 2] = duff[0]*duff[0]*delta_uff[b];
        out[b*4 + 3] = inter;
    }
}

// ---------------- launch ----------------
// d_in follows setup_inputs() dict insertion order:
//   0:h1 1:h2 2:adj1 3:dmv 4:charge1 5:charge2 6:vdw_epsilon 7:vdw_sigma
//   8:delta_uff 9:valid1 10:valid2 11:no_metal1 12:no_metal2 13:node_W
//   14:gat_W 15:gat_Wb 16:gat_A 17:gat_gW 18:gat_gb 19:pair_W1 20:pair_b1
//   21:pair_W2 22:pair_b2 23:vdw_coeff 24:duff_coeff 25:int_W1 26:int_b1
//   27:int_W2 28:int_b2
extern "C" void kernel_launch(void* const* d_in, const int* in_sizes, int n_in,
                              void* d_out, int out_size){
    const float* h1        = (const float*)d_in[0];
    const float* h2        = (const float*)d_in[1];
    const float* adj1      = (const float*)d_in[2];
    const float* dmv       = (const float*)d_in[3];
    const float* charge1   = (const float*)d_in[4];
    const float* charge2   = (const float*)d_in[5];
    const float* eps       = (const float*)d_in[6];
    const float* sig       = (const float*)d_in[7];
    const float* delta_uff = (const float*)d_in[8];
    const float* valid1    = (const float*)d_in[9];
    const float* valid2    = (const float*)d_in[10];
    const float* nm1       = (const float*)d_in[11];
    const float* nm2       = (const float*)d_in[12];
    const float* nodeW     = (const float*)d_in[13];
    const float* gatW      = (const float*)d_in[14];
    const float* gatWb     = (const float*)d_in[15];
    const float* gatA      = (const float*)d_in[16];
    const float* gatgW     = (const float*)d_in[17];
    const float* gatgb     = (const float*)d_in[18];
    const float* pW1       = (const float*)d_in[19];
    const float* pb1       = (const float*)d_in[20];
    const float* pW2       = (const float*)d_in[21];
    const float* pb2       = (const float*)d_in[22];
    const float* vdwc      = (const float*)d_in[23];
    const float* duffc     = (const float*)d_in[24];
    const float* iW1       = (const float*)d_in[25];
    const float* ib1       = (const float*)d_in[26];
    const float* iW2       = (const float*)d_in[27];
    const float* ib2       = (const float*)d_in[28];
    float* out = (float*)d_out;

    k_pre_node<<<LL*DD + (BB*(N1+N2))/4, 128>>>(gatW, gatWb, gatA, h1, h2, nodeW);
    k_stage2<<<96 + 240, 128>>>(gatW, gatWb, pW1);
    for (int l = 0; l < LL; l++){
        k_e   <<<dim3(N1/64, N1/32, BB), 256>>>(l & 1);
        k_soft<<<dim3(N1/8, BB), 256>>>(adj1);
        k_fuse<<<BB*N1/8, 128>>>(gatgW, gatgb, gatW, gatWb, l, (l < LL-1) ? 1 : 0);
    }
    k_proj1<<<240, 128>>>(pW1, pb1);
    k_pair<<<dim3(N2/32, BB*N1/16), 256>>>(dmv, charge1, charge2, eps, sig,
                                           valid1, valid2, nm1, nm2, pW2, pb2, vdwc);
    k_final<<<BB, DD>>>(valid1, delta_uff, duffc, iW1, ib1, iW2, ib2, out);
}

// round 12
// speedup vs baseline: 1.1447x; 1.0235x over previous
#include <cuda_runtime.h>
#include <math.h>

#define BB 2
#define N1 384
#define N2 384
#define DD 128
#define HH 128
#define LL 3
#define NF 54

// ---------------- scratch (device globals; no allocation) ----------------
static __device__ float g_h1g[BB*N1*DD];
static __device__ float g_h2g[BB*N2*DD];
static __device__ float g_hX [2*BB*N1*DD];   // ping-pong h
static __device__ float g_hAX[2*BB*N1*DD];   // ping-pong hA
static __device__ float g_P  [BB*N1*N1];
static __device__ float g_PT [BB*N1*N1];
static __device__ float g_m  [BB*N1];
static __device__ float g_iz [BB*N1];
static __device__ float g_p1 [5*BB*N1*HH];
static __device__ float g_p2 [5*BB*N2*HH];
static __device__ float g_WA [LL*DD*DD];
static __device__ float g_bA [LL*DD];
static __device__ float g_pec[576];
static __device__ float g_pev[576];

__device__ __forceinline__ float sigmoidf_(float x){ return 1.f/(1.f+__expf(-x)); }

// packed f32x2 helpers (sm_100+ PTX): only add/mul/fma exist in f32x2 form.
typedef unsigned long long u64t;
__device__ __forceinline__ u64t px_add(u64t a, u64t b){
    u64t r; asm("add.rn.f32x2 %0, %1, %2;" : "=l"(r) : "l"(a), "l"(b)); return r;
}
__device__ __forceinline__ u64t px_fma(u64t a, u64t b, u64t c){
    u64t r; asm("fma.rn.f32x2 %0, %1, %2, %3;" : "=l"(r) : "l"(a), "l"(b), "l"(c)); return r;
}
__device__ __forceinline__ u64t px_max0(u64t a){
    float x, y;
    asm("mov.b64 {%0, %1}, %2;" : "=f"(x), "=f"(y) : "l"(a));
    x = fmaxf(x, 0.f);
    y = fmaxf(y, 0.f);
    u64t r;
    asm("mov.b64 %0, {%1, %2};" : "=l"(r) : "f"(x), "f"(y));
    return r;
}
__device__ __forceinline__ float px_sum(u64t v){
    float x, y;
    asm("mov.b64 {%0, %1}, %2;" : "=f"(x), "=f"(y) : "l"(v));
    return x + y;
}

// ---------------- fused: WA=W@A, bA=Wb@A  +  node projection ----------------
__global__ __launch_bounds__(128) void k_pre_node(const float* __restrict__ W,
                                                  const float* __restrict__ Wb,
                                                  const float* __restrict__ A,
                                                  const float* __restrict__ h1,
                                                  const float* __restrict__ h2,
                                                  const float* __restrict__ nW){
    int bi = blockIdx.x, d = threadIdx.x;
    if (bi < LL*DD){
        int l = bi / DD, k = bi % DD;
        __shared__ float sw[DD];
        __shared__ float sb[DD];
        sw[d] = W[(l*DD + k)*DD + d];
        if (k == 0) sb[d] = Wb[l*DD + d];
        __syncthreads();
        const float* Al = A + l*DD*DD;
        float acc = 0.f;
        #pragma unroll 4
        for (int m = 0; m < DD; m++) acc += sw[m]*Al[m*DD + d];
        g_WA[(l*DD + k)*DD + d] = acc;
        if (k == 0){
            float bacc = 0.f;
            #pragma unroll 4
            for (int m = 0; m < DD; m++) bacc += sb[m]*Al[m*DD + d];
            g_bA[l*DD + d] = bacc;
        }
    } else {
        int r0 = (bi - LL*DD)*4;
        __shared__ float sx[4][NF];
        bool lig = (r0 < BB*N1);
        const float* src = lig ? (h1 + r0*NF) : (h2 + (r0 - BB*N1)*NF);
        for (int idx = d; idx < 4*NF; idx += 128) ((float*)sx)[idx] = src[idx];
        __syncthreads();
        float acc[4] = {0.f,0.f,0.f,0.f};
        #pragma unroll 2
        for (int k = 0; k < NF; k++){
            float wv = nW[k*DD + d];
            #pragma unroll
            for (int ii = 0; ii < 4; ii++) acc[ii] += sx[ii][k]*wv;
        }
        float* dst = lig ? (g_h1g + r0*DD) : (g_h2g + (r0 - BB*N1)*DD);
        #pragma unroll
        for (int ii = 0; ii < 4; ii++) dst[ii*DD + d] = acc[ii];
    }
}

// ---------------- stage2: gat_h layer0 (96 blocks) + protein pair-proj (240 blocks) ----------------
__global__ __launch_bounds__(128) void k_stage2(const float* __restrict__ gatW,
                                                const float* __restrict__ gatWb,
                                                const float* __restrict__ W1){
    int bi = blockIdx.x, d = threadIdx.x;
    __shared__ float sx[16][DD];
    if (bi < 96){
        int r0 = bi*8;
        #pragma unroll
        for (int ii = 0; ii < 8; ii++) sx[ii][d] = g_h1g[(r0 + ii)*DD + d];
        __syncthreads();
        float wb = gatWb[d], bav = g_bA[d];
        float h[8], ha[8];
        #pragma unroll
        for (int ii = 0; ii < 8; ii++){ h[ii] = wb; ha[ii] = bav; }
        #pragma unroll 2
        for (int k = 0; k < DD; k++){
            float wv  = gatW[k*DD + d];
            float wav = g_WA[k*DD + d];
            #pragma unroll
            for (int ii = 0; ii < 8; ii++){
                h [ii] += sx[ii][k]*wv;
                ha[ii] += sx[ii][k]*wav;
            }
        }
        #pragma unroll
        for (int ii = 0; ii < 8; ii++){
            g_hX [(r0 + ii)*DD + d] = h [ii];
            g_hAX[(r0 + ii)*DD + d] = ha[ii];
        }
    } else {
        int pi = bi - 96;
        int m  = pi / 48;
        int r0 = (pi % 48)*16;
        #pragma unroll
        for (int ii = 0; ii < 16; ii++) sx[ii][d] = g_h2g[(r0 + ii)*DD + d];
        __syncthreads();
        const float* W = W1 + m*2*DD*HH + DD*HH;   // protein half, no bias
        float acc[16];
        #pragma unroll
        for (int ii = 0; ii < 16; ii++) acc[ii] = 0.f;
        #pragma unroll 2
        for (int k = 0; k < DD; k++){
            float wv = W[k*HH + d];
            #pragma unroll
            for (int ii = 0; ii < 16; ii++) acc[ii] = fmaf(sx[ii][k], wv, acc[ii]);
        }
        #pragma unroll
        for (int ii = 0; ii < 16; ii++) g_p2[(m*BB*N2 + r0 + ii)*HH + d] = acc[ii];
    }
}

// ---------------- P = hA @ h^T (and coalesced P^T) : 32x64 tiles, 144 blocks ----------------
__global__ __launch_bounds__(256) void k_e(int cur){
    const float* hb  = g_hX  + cur*BB*N1*DD;
    const float* hab = g_hAX + cur*BB*N1*DD;
    int b = blockIdx.z, j0 = blockIdx.y*32, k0 = blockIdx.x*64;
    __shared__ __align__(16) float sA[64][36];
    __shared__ __align__(16) float sB[64][68];
    int tid = threadIdx.x;
    int tx = tid & 15, ty = tid >> 4;
    float acc[2][4];
    #pragma unroll
    for (int r = 0; r < 2; r++)
        #pragma unroll
        for (int c = 0; c < 4; c++) acc[r][c] = 0.f;
    const float* baseA = hab + (b*N1 + j0)*DD;
    const float* baseB = hb  + (b*N1 + k0)*DD;
    for (int ks = 0; ks < 2; ks++){
        __syncthreads();
        #pragma unroll
        for (int q = 0; q < 2; q++){
            int idx = tid + q*256;
            int row = idx & 31, kq = idx >> 5;
            float4 va = *(const float4*)(baseA + row*DD + ks*64 + kq*4);
            sA[kq*4+0][row] = va.x; sA[kq*4+1][row] = va.y;
            sA[kq*4+2][row] = va.z; sA[kq*4+3][row] = va.w;
        }
        #pragma unroll
        for (int q = 0; q < 4; q++){
            int idx = tid + q*256;
            int row = idx & 63, kq = idx >> 6;
            float4 vb = *(const float4*)(baseB + row*DD + ks*64 + kq*4);
            sB[kq*4+0][row] = vb.x; sB[kq*4+1][row] = vb.y;
            sB[kq*4+2][row] = vb.z; sB[kq*4+3][row] = vb.w;
        }
        __syncthreads();
        #pragma unroll 8
        for (int kk = 0; kk < 64; kk++){
            float2 av = *(const float2*)&sA[kk][ty*2];
            float4 bv = *(const float4*)&sB[kk][tx*4];
            acc[0][0] = fmaf(av.x, bv.x, acc[0][0]);
            acc[0][1] = fmaf(av.x, bv.y, acc[0][1]);
            acc[0][2] = fmaf(av.x, bv.z, acc[0][2]);
            acc[0][3] = fmaf(av.x, bv.w, acc[0][3]);
            acc[1][0] = fmaf(av.y, bv.x, acc[1][0]);
            acc[1][1] = fmaf(av.y, bv.y, acc[1][1]);
            acc[1][2] = fmaf(av.y, bv.z, acc[1][2]);
            acc[1][3] = fmaf(av.y, bv.w, acc[1][3]);
        }
    }
    #pragma unroll
    for (int r = 0; r < 2; r++){
        float4 o = make_float4(acc[r][0], acc[r][1], acc[r][2], acc[r][3]);
        *(float4*)&g_P[(size_t)(b*N1 + j0 + ty*2 + r)*N1 + k0 + tx*4] = o;
    }
    // stage transposed tile into retired sA, then write PT rows coalesced
    __syncthreads();
    float* sT = &sA[0][0];     // 64*36 floats, row stride 36 (16B-aligned rows)
    #pragma unroll
    for (int r = 0; r < 2; r++)
        #pragma unroll
        for (int c = 0; c < 4; c++)
            sT[(tx*4 + c)*36 + ty*2 + r] = acc[r][c];
    __syncthreads();
    #pragma unroll
    for (int q = 0; q < 2; q++){
        int idx = tid + q*256;
        int row = idx >> 3;        // 0..63 (k-tile row)
        int cq  = idx & 7;         // float4 column index 0..7
        float4 v = *(const float4*)&sT[row*36 + cq*4];
        *(float4*)&g_PT[(size_t)(b*N1 + k0 + row)*N1 + j0 + cq*4] = v;
    }
}

// ---------------- column stats via symmetry: m[j], invZ[j] from row j of e ----------------
__global__ __launch_bounds__(256) void k_stats(const float* __restrict__ adj){
    int w = threadIdx.x >> 5, lane = threadIdx.x & 31;
    int rg = blockIdx.x*8 + w;                 // global row 0..767
    const float* pr  = g_P  + (size_t)rg*N1;
    const float* ptr = g_PT + (size_t)rg*N1;
    const float* ar  = adj  + (size_t)rg*N1;
    float ev[12];
    float mx = -INFINITY;
    #pragma unroll
    for (int t = 0; t < 12; t++){
        int i = lane + t*32;
        float a = ar[i];
        float e = (a > 0.f) ? (pr[i] + ptr[i]) : -9e15f;
        ev[t] = e;
        mx = fmaxf(mx, e);
    }
    #pragma unroll
    for (int o = 16; o; o >>= 1) mx = fmaxf(mx, __shfl_xor_sync(0xffffffffu, mx, o));
    float sum = 0.f;
    #pragma unroll
    for (int t = 0; t < 12; t++) sum += __expf(ev[t] - mx);
    #pragma unroll
    for (int o = 16; o; o >>= 1) sum += __shfl_xor_sync(0xffffffffu, sum, o);
    if (lane == 0){
        g_m [rg] = mx;
        g_iz[rg] = 1.f/sum;
    }
}

// ---------------- fused: att on the fly, h'=relu(att@h), gate, next-layer h/hA ----------------
__global__ __launch_bounds__(128) void k_fuse(const float* __restrict__ adj,
                                              const float* __restrict__ gW,
                                              const float* __restrict__ gb,
                                              const float* __restrict__ gatW,
                                              const float* __restrict__ gatWb,
                                              int l, int has_next){
    int r0 = blockIdx.x*8;
    int b  = r0 / N1;
    int d  = threadIdx.x;
    const float* hb = g_hX + (l & 1)*BB*N1*DD;
    __shared__ float s_att[8][N1];
    __shared__ float s_m [N1];
    __shared__ float s_iz[N1];
    __shared__ float s_g[8][DD];
    __shared__ float s_c[8];
    __shared__ float sx[8][DD];
    for (int idx = d; idx < N1; idx += 128){
        s_m [idx] = g_m [b*N1 + idx];
        s_iz[idx] = g_iz[b*N1 + idx];
    }
    float xd[8];
    #pragma unroll
    for (int ii = 0; ii < 8; ii++) xd[ii] = g_h1g[(r0 + ii)*DD + d];
    __syncthreads();
    for (int idx = d; idx < 8*N1; idx += 128){
        int ii = idx / N1, j = idx % N1;
        float a = adj[(size_t)(r0 + ii)*N1 + j];
        float wv = 0.f;
        if (a > 0.f){
            float e = g_P[(size_t)(r0 + ii)*N1 + j] + g_PT[(size_t)(r0 + ii)*N1 + j];
            wv = __expf(e - s_m[j])*s_iz[j]*a;
        }
        s_att[ii][j] = wv;
    }
    __syncthreads();
    float hp[8];
    #pragma unroll
    for (int ii = 0; ii < 8; ii++) hp[ii] = 0.f;
    const float* hcol = hb + b*N1*DD + d;
    #pragma unroll 4
    for (int j = 0; j < N1; j++){
        float hv = hcol[j*DD];
        #pragma unroll
        for (int ii = 0; ii < 8; ii++) hp[ii] = fmaf(s_att[ii][j], hv, hp[ii]);
    }
    float gw1 = gW[l*2*DD + d], gw2 = gW[l*2*DD + DD + d], gbv = gb[l];
    #pragma unroll
    for (int ii = 0; ii < 8; ii++){
        hp[ii] = fmaxf(hp[ii], 0.f);
        s_g[ii][d] = fmaf(xd[ii], gw1, hp[ii]*gw2);
    }
    __syncthreads();
    int w = d >> 5, lane = d & 31;
    for (int ii = w; ii < 8; ii += 4){
        float s = s_g[ii][lane] + s_g[ii][lane+32] + s_g[ii][lane+64] + s_g[ii][lane+96];
        #pragma unroll
        for (int o = 16; o; o >>= 1) s += __shfl_xor_sync(0xffffffffu, s, o);
        if (lane == 0) s_c[ii] = sigmoidf_(s + gbv);
    }
    __syncthreads();
    #pragma unroll
    for (int ii = 0; ii < 8; ii++){
        float coeff = s_c[ii];
        float v = coeff*xd[ii] + (1.f - coeff)*hp[ii];
        g_h1g[(r0 + ii)*DD + d] = v;
        sx[ii][d] = v;
    }
    if (!has_next) return;
    __syncthreads();
    int nl = l + 1;
    const float* W  = gatW + nl*DD*DD;
    const float* WA = g_WA + nl*DD*DD;
    float wb  = gatWb[nl*DD + d];
    float bav = g_bA [nl*DD + d];
    float h[8], ha[8];
    #pragma unroll
    for (int ii = 0; ii < 8; ii++){ h[ii] = wb; ha[ii] = bav; }
    #pragma unroll 2
    for (int k = 0; k < DD; k++){
        float wv  = W [k*DD + d];
        float wav = WA[k*DD + d];
        #pragma unroll
        for (int ii = 0; ii < 8; ii++){
            h [ii] += sx[ii][k]*wv;
            ha[ii] += sx[ii][k]*wav;
        }
    }
    float* ho  = g_hX  + (nl & 1)*BB*N1*DD;
    float* hao = g_hAX + (nl & 1)*BB*N1*DD;
    #pragma unroll
    for (int ii = 0; ii < 8; ii++){
        ho [(r0 + ii)*DD + d] = h [ii];
        hao[(r0 + ii)*DD + d] = ha[ii];
    }
}

// ---------------- ligand pair projections (16 rows/block, 240 blocks) ----------------
__global__ __launch_bounds__(128) void k_proj1(const float* __restrict__ W1,
                                               const float* __restrict__ b1){
    int bi = blockIdx.x;
    int m  = bi / 48;
    int r0 = (bi % 48)*16;
    int hh = threadIdx.x;
    __shared__ float sx[16][DD];
    #pragma unroll
    for (int ii = 0; ii < 16; ii++) sx[ii][hh] = g_h1g[(r0 + ii)*DD + hh];
    __syncthreads();
    const float* W = W1 + m*2*DD*HH;
    float bias = b1[m*HH + hh];
    float acc[16];
    #pragma unroll
    for (int ii = 0; ii < 16; ii++) acc[ii] = bias;
    #pragma unroll 2
    for (int k = 0; k < DD; k++){
        float wv = W[k*HH + hh];
        #pragma unroll
        for (int ii = 0; ii < 16; ii++) acc[ii] = fmaf(sx[ii][k], wv, acc[ii]);
    }
    #pragma unroll
    for (int ii = 0; ii < 16; ii++) g_p1[(m*BB*N1 + r0 + ii)*HH + hh] = acc[ii];
}

// ---------------- pair energies: 16i x 32j tile, packed f32x2 mainloop ----------------
__global__ __launch_bounds__(256) void k_pair(const float* __restrict__ dmv,
                                              const float* __restrict__ c1,
                                              const float* __restrict__ c2,
                                              const float* __restrict__ eps,
                                              const float* __restrict__ sig,
                                              const float* __restrict__ val1,
                                              const float* __restrict__ val2,
                                              const float* __restrict__ nmm1,
                                              const float* __restrict__ nmm2,
                                              const float* __restrict__ W2,
                                              const float* __restrict__ b2,
                                              const float* __restrict__ vdwc){
    int bix = blockIdx.x;          // j tile 0..11
    int biy = blockIdx.y;          // i tile 0..47
    int r0  = biy*16;
    int b   = r0 / N1;
    int i1  = r0 % N1;
    int j0  = bix*32;
    __shared__ __align__(16) float s_p1[16][132];
    __shared__ __align__(16) float s_p2[32][132];
    __shared__ __align__(16) float s_w2[5][128];
    __shared__ float s_b2v[5];
    __shared__ float s_red[16];
    int tid = threadIdx.x, lane = tid & 31, w = tid >> 5;
    int j  = lane;
    int ia = w*2;
    for (int idx = tid; idx < 5*DD; idx += 256) s_w2[idx/DD][idx%DD] = W2[idx];
    if (tid < 5) s_b2v[tid] = b2[tid];
    float acc[2][5];
    for (int m = 0; m < 5; m++){
        __syncthreads();
        #pragma unroll
        for (int q = 0; q < 2; q++){
            int idx = tid + q*256;
            int row = idx >> 5, q4 = idx & 31;
            float4 v = *(const float4*)(g_p1 + (size_t)(m*BB*N1 + r0 + row)*HH + q4*4);
            *(float4*)&s_p1[row][q4*4] = v;
        }
        #pragma unroll
        for (int q = 0; q < 4; q++){
            int idx = tid + q*256;
            int row = idx >> 5, q4 = idx & 31;
            float4 v = *(const float4*)(g_p2 + (size_t)(m*BB*N2 + b*N2 + j0 + row)*HH + q4*4);
            *(float4*)&s_p2[row][q4*4] = v;
        }
        __syncthreads();
        u64t a0l = 0ULL, a0h = 0ULL, a1l = 0ULL, a1h = 0ULL;
        #pragma unroll
        for (int hv = 0; hv < 32; hv++){
            ulonglong2 w4  = *(const ulonglong2*)&s_w2[m][hv*4];
            ulonglong2 p2v = *(const ulonglong2*)&s_p2[j][hv*4];
            ulonglong2 pa  = *(const ulonglong2*)&s_p1[ia][hv*4];
            ulonglong2 pb  = *(const ulonglong2*)&s_p1[ia+1][hv*4];
            a0l = px_fma(px_max0(px_add(pa.x, p2v.x)), w4.x, a0l);
            a0h = px_fma(px_max0(px_add(pa.y, p2v.y)), w4.y, a0h);
            a1l = px_fma(px_max0(px_add(pb.x, p2v.x)), w4.x, a1l);
            a1h = px_fma(px_max0(px_add(pb.y, p2v.y)), w4.y, a1h);
        }
        acc[0][m] = px_sum(a0l) + px_sum(a0h);
        acc[1][m] = px_sum(a1l) + px_sum(a1h);
    }
    float vdwc2 = vdwc[0]*vdwc[0];
    float ec = 0.f, ev = 0.f;
    int jl = j0 + j;
    float c2v = c2[b*N2 + jl], v2v = val2[b*N2 + jl], n2v = nmm2[b*N2 + jl];
    #pragma unroll
    for (int q = 0; q < 2; q++){
        int il = i1 + ia + q;
        float v0 = acc[q][0] + s_b2v[0];
        float v1 = acc[q][1] + s_b2v[1];
        float v2 = acc[q][2] + s_b2v[2];
        float v3 = acc[q][3] + s_b2v[3];
        float v4 = acc[q][4] + s_b2v[4];
        int pix = (b*N1 + il)*N2 + jl;
        const float* dv = dmv + (size_t)pix*3;
        float dx = dv[0], dy = dv[1], dz = dv[2];
        float dm = sqrtf(dx*dx + dy*dy + dz*dz + 1e-10f);
        if (dm < 0.5f) dm = 1e10f;
        float l2dm = __log2f(dm);
        float cA  = sigmoidf_(v0);
        float cN  = 2.f*sigmoidf_(v1) + 1.f;
        float q12 = c1[b*N1 + il]*c2v;
        float e_c = cA*q12*exp2f(-cN*l2dm);
        e_c *= val1[b*N1 + il]*v2v;
        e_c = fminf(fmaxf(e_c, -100.f), 100.f);
        float vAv = (0.6f*sigmoidf_(v2) + 0.7f)*vdwc2*eps[pix];
        float vBv = tanhf(v3)*0.6f + 0.7f;
        float vNv = 2.f*sigmoidf_(v4) + 5.f;
        float dm0 = sig[pix]*vBv;
        if (dm0 < 1e-4f) dm0 = 1.f;
        float r  = exp2f(vNv*(__log2f(dm0) - l2dm));
        float e_v = vAv*(r*r - 2.f*r);
        e_v *= nmm1[b*N1 + il]*n2v;
        e_v = fminf(e_v, 100.f);
        ec += e_c; ev += e_v;
    }
    #pragma unroll
    for (int o = 16; o; o >>= 1){
        ec += __shfl_xor_sync(0xffffffffu, ec, o);
        ev += __shfl_xor_sync(0xffffffffu, ev, o);
    }
    if (lane == 0){ s_red[w] = ec; s_red[8 + w] = ev; }
    __syncthreads();
    if (tid == 0){
        float tec = 0.f, tev = 0.f;
        #pragma unroll
        for (int qq = 0; qq < 8; qq++){ tec += s_red[qq]; tev += s_red[8 + qq]; }
        g_pec[biy*12 + bix] = tec;
        g_pev[biy*12 + bix] = tev;
    }
}

// ---------------- finalize ----------------
__global__ __launch_bounds__(DD) void k_final(const float* __restrict__ valid1,
                                              const float* __restrict__ delta_uff,
                                              const float* __restrict__ duff,
                                              const float* __restrict__ iW1,
                                              const float* __restrict__ ib1,
                                              const float* __restrict__ iW2,
                                              const float* __restrict__ ib2,
                                              float* __restrict__ out){
    int b = blockIdx.x, d = threadIdx.x;
    __shared__ float s_hs[DD];
    __shared__ float s_red[DD];
    float hs = 0.f;
    for (int i = 0; i < N1; i++) hs += g_h1g[(b*N1 + i)*DD + d]*valid1[b*N1 + i];
    s_hs[d] = hs;
    __syncthreads();
    float hid = ib1[d];
    #pragma unroll 4
    for (int k = 0; k < DD; k++) hid += s_hs[k]*iW1[k*HH + d];
    hid = fmaxf(hid, 0.f);
    s_red[d] = hid*iW2[d];
    __syncthreads();
    for (int s = 64; s; s >>= 1){ if (d < s) s_red[d] += s_red[d + s]; __syncthreads(); }
    float inter = s_red[0] + ib2[0];
    __syncthreads();
    float tec = 0.f;
    for (int q = d; q < 288; q += DD) tec += g_pec[b*288 + q];
    s_red[d] = tec;
    __syncthreads();
    for (int s = 64; s; s >>= 1){ if (d < s) s_red[d] += s_red[d + s]; __syncthreads(); }
    float tecs = s_red[0];
    __syncthreads();
    float tev = 0.f;
    for (int q = d; q < 288; q += DD) tev += g_pev[b*288 + q];
    s_red[d] = tev;
    __syncthreads();
    for (int s = 64; s; s >>= 1){ if (d < s) s_red[d] += s_red[d + s]; __syncthreads(); }
    if (d == 0){
        out[b*4 + 0] = tecs;
        out[b*4 + 1] = s_red[0];
        out[b*4 + 2] = duff[0]*duff[0]*delta_uff[b];
        out[b*4 + 3] = inter;
    }
}

// ---------------- launch ----------------
// d_in follows setup_inputs() dict insertion order:
//   0:h1 1:h2 2:adj1 3:dmv 4:charge1 5:charge2 6:vdw_epsilon 7:vdw_sigma
//   8:delta_uff 9:valid1 10:valid2 11:no_metal1 12:no_metal2 13:node_W
//   14:gat_W 15:gat_Wb 16:gat_A 17:gat_gW 18:gat_gb 19:pair_W1 20:pair_b1
//   21:pair_W2 22:pair_b2 23:vdw_coeff 24:duff_coeff 25:int_W1 26:int_b1
//   27:int_W2 28:int_b2
extern "C" void kernel_launch(void* const* d_in, const int* in_sizes, int n_in,
                              void* d_out, int out_size){
    const float* h1        = (const float*)d_in[0];
    const float* h2        = (const float*)d_in[1];
    const float* adj1      = (const float*)d_in[2];
    const float* dmv       = (const float*)d_in[3];
    const float* charge1   = (const float*)d_in[4];
    const float* charge2   = (const float*)d_in[5];
    const float* eps       = (const float*)d_in[6];
    const float* sig       = (const float*)d_in[7];
    const float* delta_uff = (const float*)d_in[8];
    const float* valid1    = (const float*)d_in[9];
    const float* valid2    = (const float*)d_in[10];
    const float* nm1       = (const float*)d_in[11];
    const float* nm2       = (const float*)d_in[12];
    const float* nodeW     = (const float*)d_in[13];
    const float* gatW      = (const float*)d_in[14];
    const float* gatWb     = (const float*)d_in[15];
    const float* gatA      = (const float*)d_in[16];
    const float* gatgW     = (const float*)d_in[17];
    const float* gatgb     = (const float*)d_in[18];
    const float* pW1       = (const float*)d_in[19];
    const float* pb1       = (const float*)d_in[20];
    const float* pW2       = (const float*)d_in[21];
    const float* pb2       = (const float*)d_in[22];
    const float* vdwc      = (const float*)d_in[23];
    const float* duffc     = (const float*)d_in[24];
    const float* iW1       = (const float*)d_in[25];
    const float* ib1       = (const float*)d_in[26];
    const float* iW2       = (const float*)d_in[27];
    const float* ib2       = (const float*)d_in[28];
    float* out = (float*)d_out;

    k_pre_node<<<LL*DD + (BB*(N1+N2))/4, 128>>>(gatW, gatWb, gatA, h1, h2, nodeW);
    k_stage2<<<96 + 240, 128>>>(gatW, gatWb, pW1);
    for (int l = 0; l < LL; l++){
        k_e    <<<dim3(N1/64, N1/32, BB), 256>>>(l & 1);
        k_stats<<<BB*N1/8, 256>>>(adj1);
        k_fuse <<<BB*N1/8, 128>>>(adj1, gatgW, gatgb, gatW, gatWb, l, (l < LL-1) ? 1 : 0);
    }
    k_proj1<<<240, 128>>>(pW1, pb1);
    k_pair<<<dim3(N2/32, BB*N1/16), 256>>>(dmv, charge1, charge2, eps, sig,
                                           valid1, valid2, nm1, nm2, pW2, pb2, vdwc);
    k_final<<<BB, DD>>>(valid1, delta_uff, duffc, iW1, ib1, iW2, ib2, out);
}

// round 13
// speedup vs baseline: 1.1671x; 1.0196x over previous
#include <cuda_runtime.h>
#include <math.h>

#define BB 2
#define N1 384
#define N2 384
#define DD 128
#define HH 128
#define LL 3
#define NF 54

// ---------------- scratch (device globals; no allocation) ----------------
static __device__ float g_h1g[BB*N1*DD];
static __device__ float g_h2g[BB*N2*DD];
static __device__ float g_hX [2*BB*N1*DD];   // ping-pong h
static __device__ float g_hAX[2*BB*N1*DD];   // ping-pong hA
static __device__ float g_P  [BB*N1*N1];
static __device__ float g_PT [BB*N1*N1];
static __device__ float g_m  [BB*N1];
static __device__ float g_iz [BB*N1];
static __device__ float g_p1 [5*BB*N1*HH];
static __device__ float g_p2 [5*BB*N2*HH];
static __device__ float g_WA [LL*DD*DD];
static __device__ float g_bA [LL*DD];
static __device__ float g_pec[576];
static __device__ float g_pev[576];

__device__ __forceinline__ float sigmoidf_(float x){ return 1.f/(1.f+__expf(-x)); }

// packed f32x2 helpers (sm_100+ PTX): only add/mul/fma exist in f32x2 form.
typedef unsigned long long u64t;
__device__ __forceinline__ u64t px_add(u64t a, u64t b){
    u64t r; asm("add.rn.f32x2 %0, %1, %2;" : "=l"(r) : "l"(a), "l"(b)); return r;
}
__device__ __forceinline__ u64t px_fma(u64t a, u64t b, u64t c){
    u64t r; asm("fma.rn.f32x2 %0, %1, %2, %3;" : "=l"(r) : "l"(a), "l"(b), "l"(c)); return r;
}
__device__ __forceinline__ u64t px_max0(u64t a){
    float x, y;
    asm("mov.b64 {%0, %1}, %2;" : "=f"(x), "=f"(y) : "l"(a));
    x = fmaxf(x, 0.f);
    y = fmaxf(y, 0.f);
    u64t r;
    asm("mov.b64 %0, {%1, %2};" : "=l"(r) : "f"(x), "f"(y));
    return r;
}
__device__ __forceinline__ float px_sum(u64t v){
    float x, y;
    asm("mov.b64 {%0, %1}, %2;" : "=f"(x), "=f"(y) : "l"(v));
    return x + y;
}

// ---------------- fused: WA=W@A, bA=Wb@A  +  node projection ----------------
__global__ __launch_bounds__(128) void k_pre_node(const float* __restrict__ W,
                                                  const float* __restrict__ Wb,
                                                  const float* __restrict__ A,
                                                  const float* __restrict__ h1,
                                                  const float* __restrict__ h2,
                                                  const float* __restrict__ nW){
    int bi = blockIdx.x, d = threadIdx.x;
    if (bi < LL*DD){
        int l = bi / DD, k = bi % DD;
        __shared__ float sw[DD];
        __shared__ float sb[DD];
        sw[d] = W[(l*DD + k)*DD + d];
        if (k == 0) sb[d] = Wb[l*DD + d];
        __syncthreads();
        const float* Al = A + l*DD*DD;
        float acc = 0.f;
        #pragma unroll 4
        for (int m = 0; m < DD; m++) acc += sw[m]*Al[m*DD + d];
        g_WA[(l*DD + k)*DD + d] = acc;
        if (k == 0){
            float bacc = 0.f;
            #pragma unroll 4
            for (int m = 0; m < DD; m++) bacc += sb[m]*Al[m*DD + d];
            g_bA[l*DD + d] = bacc;
        }
    } else {
        int r0 = (bi - LL*DD)*4;
        __shared__ float sx[4][NF];
        bool lig = (r0 < BB*N1);
        const float* src = lig ? (h1 + r0*NF) : (h2 + (r0 - BB*N1)*NF);
        for (int idx = d; idx < 4*NF; idx += 128) ((float*)sx)[idx] = src[idx];
        __syncthreads();
        float acc[4] = {0.f,0.f,0.f,0.f};
        #pragma unroll 2
        for (int k = 0; k < NF; k++){
            float wv = nW[k*DD + d];
            #pragma unroll
            for (int ii = 0; ii < 4; ii++) acc[ii] += sx[ii][k]*wv;
        }
        float* dst = lig ? (g_h1g + r0*DD) : (g_h2g + (r0 - BB*N1)*DD);
        #pragma unroll
        for (int ii = 0; ii < 4; ii++) dst[ii*DD + d] = acc[ii];
    }
}

// ---------------- stage2: gat_h layer0 (192 blocks, 4 rows) + protein pair-proj (240 blocks) ----------------
__global__ __launch_bounds__(128) void k_stage2(const float* __restrict__ gatW,
                                                const float* __restrict__ gatWb,
                                                const float* __restrict__ W1){
    int bi = blockIdx.x, d = threadIdx.x;
    __shared__ float sx[16][DD];
    if (bi < 192){
        int r0 = bi*4;
        #pragma unroll
        for (int ii = 0; ii < 4; ii++) sx[ii][d] = g_h1g[(r0 + ii)*DD + d];
        __syncthreads();
        float wb = gatWb[d], bav = g_bA[d];
        float h[4], ha[4];
        #pragma unroll
        for (int ii = 0; ii < 4; ii++){ h[ii] = wb; ha[ii] = bav; }
        #pragma unroll 2
        for (int k = 0; k < DD; k++){
            float wv  = gatW[k*DD + d];
            float wav = g_WA[k*DD + d];
            #pragma unroll
            for (int ii = 0; ii < 4; ii++){
                h [ii] += sx[ii][k]*wv;
                ha[ii] += sx[ii][k]*wav;
            }
        }
        #pragma unroll
        for (int ii = 0; ii < 4; ii++){
            g_hX [(r0 + ii)*DD + d] = h [ii];
            g_hAX[(r0 + ii)*DD + d] = ha[ii];
        }
    } else {
        int pi = bi - 192;
        int m  = pi / 48;
        int r0 = (pi % 48)*16;
        #pragma unroll
        for (int ii = 0; ii < 16; ii++) sx[ii][d] = g_h2g[(r0 + ii)*DD + d];
        __syncthreads();
        const float* W = W1 + m*2*DD*HH + DD*HH;   // protein half, no bias
        float acc[16];
        #pragma unroll
        for (int ii = 0; ii < 16; ii++) acc[ii] = 0.f;
        #pragma unroll 2
        for (int k = 0; k < DD; k++){
            float wv = W[k*HH + d];
            #pragma unroll
            for (int ii = 0; ii < 16; ii++) acc[ii] = fmaf(sx[ii][k], wv, acc[ii]);
        }
        #pragma unroll
        for (int ii = 0; ii < 16; ii++) g_p2[(m*BB*N2 + r0 + ii)*HH + d] = acc[ii];
    }
}

// ---------------- P = hA @ h^T (and coalesced P^T) : 32x64 tiles, 144 blocks ----------------
__global__ __launch_bounds__(256) void k_e(int cur){
    const float* hb  = g_hX  + cur*BB*N1*DD;
    const float* hab = g_hAX + cur*BB*N1*DD;
    int b = blockIdx.z, j0 = blockIdx.y*32, k0 = blockIdx.x*64;
    __shared__ __align__(16) float sA[64][36];
    __shared__ __align__(16) float sB[64][68];
    int tid = threadIdx.x;
    int tx = tid & 15, ty = tid >> 4;
    float acc[2][4];
    #pragma unroll
    for (int r = 0; r < 2; r++)
        #pragma unroll
        for (int c = 0; c < 4; c++) acc[r][c] = 0.f;
    const float* baseA = hab + (b*N1 + j0)*DD;
    const float* baseB = hb  + (b*N1 + k0)*DD;
    for (int ks = 0; ks < 2; ks++){
        __syncthreads();
        #pragma unroll
        for (int q = 0; q < 2; q++){
            int idx = tid + q*256;
            int row = idx & 31, kq = idx >> 5;
            float4 va = *(const float4*)(baseA + row*DD + ks*64 + kq*4);
            sA[kq*4+0][row] = va.x; sA[kq*4+1][row] = va.y;
            sA[kq*4+2][row] = va.z; sA[kq*4+3][row] = va.w;
        }
        #pragma unroll
        for (int q = 0; q < 4; q++){
            int idx = tid + q*256;
            int row = idx & 63, kq = idx >> 6;
            float4 vb = *(const float4*)(baseB + row*DD + ks*64 + kq*4);
            sB[kq*4+0][row] = vb.x; sB[kq*4+1][row] = vb.y;
            sB[kq*4+2][row] = vb.z; sB[kq*4+3][row] = vb.w;
        }
        __syncthreads();
        #pragma unroll 8
        for (int kk = 0; kk < 64; kk++){
            float2 av = *(const float2*)&sA[kk][ty*2];
            float4 bv = *(const float4*)&sB[kk][tx*4];
            acc[0][0] = fmaf(av.x, bv.x, acc[0][0]);
            acc[0][1] = fmaf(av.x, bv.y, acc[0][1]);
            acc[0][2] = fmaf(av.x, bv.z, acc[0][2]);
            acc[0][3] = fmaf(av.x, bv.w, acc[0][3]);
            acc[1][0] = fmaf(av.y, bv.x, acc[1][0]);
            acc[1][1] = fmaf(av.y, bv.y, acc[1][1]);
            acc[1][2] = fmaf(av.y, bv.z, acc[1][2]);
            acc[1][3] = fmaf(av.y, bv.w, acc[1][3]);
        }
    }
    #pragma unroll
    for (int r = 0; r < 2; r++){
        float4 o = make_float4(acc[r][0], acc[r][1], acc[r][2], acc[r][3]);
        *(float4*)&g_P[(size_t)(b*N1 + j0 + ty*2 + r)*N1 + k0 + tx*4] = o;
    }
    // stage transposed tile into retired sA, then write PT rows coalesced
    __syncthreads();
    float* sT = &sA[0][0];     // 64*36 floats, row stride 36 (16B-aligned rows)
    #pragma unroll
    for (int r = 0; r < 2; r++)
        #pragma unroll
        for (int c = 0; c < 4; c++)
            sT[(tx*4 + c)*36 + ty*2 + r] = acc[r][c];
    __syncthreads();
    #pragma unroll
    for (int q = 0; q < 2; q++){
        int idx = tid + q*256;
        int row = idx >> 3;        // 0..63 (k-tile row)
        int cq  = idx & 7;         // float4 column index 0..7
        float4 v = *(const float4*)&sT[row*36 + cq*4];
        *(float4*)&g_PT[(size_t)(b*N1 + k0 + row)*N1 + j0 + cq*4] = v;
    }
}

// ---------------- column stats via symmetry: m[j], invZ[j] from row j of e ----------------
__global__ __launch_bounds__(256) void k_stats(const float* __restrict__ adj){
    int w = threadIdx.x >> 5, lane = threadIdx.x & 31;
    int rg = blockIdx.x*8 + w;                 // global row 0..767
    const float* pr  = g_P  + (size_t)rg*N1;
    const float* ptr = g_PT + (size_t)rg*N1;
    const float* ar  = adj  + (size_t)rg*N1;
    float ev[12];
    float mx = -INFINITY;
    #pragma unroll
    for (int t = 0; t < 12; t++){
        int i = lane + t*32;
        float a = ar[i];
        float e = (a > 0.f) ? (pr[i] + ptr[i]) : -9e15f;
        ev[t] = e;
        mx = fmaxf(mx, e);
    }
    #pragma unroll
    for (int o = 16; o; o >>= 1) mx = fmaxf(mx, __shfl_xor_sync(0xffffffffu, mx, o));
    float sum = 0.f;
    #pragma unroll
    for (int t = 0; t < 12; t++) sum += __expf(ev[t] - mx);
    #pragma unroll
    for (int o = 16; o; o >>= 1) sum += __shfl_xor_sync(0xffffffffu, sum, o);
    if (lane == 0){
        g_m [rg] = mx;
        g_iz[rg] = 1.f/sum;
    }
}

// ---------------- fused: att on the fly, h'=relu(att@h), gate, next-layer h/hA (4 rows, 192 blocks) ----------------
__global__ __launch_bounds__(128) void k_fuse(const float* __restrict__ adj,
                                              const float* __restrict__ gW,
                                              const float* __restrict__ gb,
                                              const float* __restrict__ gatW,
                                              const float* __restrict__ gatWb,
                                              int l, int has_next){
    int r0 = blockIdx.x*4;
    int b  = r0 / N1;
    int d  = threadIdx.x;
    const float* hb = g_hX + (l & 1)*BB*N1*DD;
    __shared__ float s_att[4][N1];
    __shared__ float s_m [N1];
    __shared__ float s_iz[N1];
    __shared__ float s_g[4][DD];
    __shared__ float s_c[4];
    __shared__ float sx[4][DD];
    for (int idx = d; idx < N1; idx += 128){
        s_m [idx] = g_m [b*N1 + idx];
        s_iz[idx] = g_iz[b*N1 + idx];
    }
    float xd[4];
    #pragma unroll
    for (int ii = 0; ii < 4; ii++) xd[ii] = g_h1g[(r0 + ii)*DD + d];
    __syncthreads();
    for (int idx = d; idx < 4*N1; idx += 128){
        int ii = idx / N1, j = idx % N1;
        float a = adj[(size_t)(r0 + ii)*N1 + j];
        float wv = 0.f;
        if (a > 0.f){
            float e = g_P[(size_t)(r0 + ii)*N1 + j] + g_PT[(size_t)(r0 + ii)*N1 + j];
            wv = __expf(e - s_m[j])*s_iz[j]*a;
        }
        s_att[ii][j] = wv;
    }
    __syncthreads();
    float hp[4] = {0.f,0.f,0.f,0.f};
    const float* hcol = hb + b*N1*DD + d;
    #pragma unroll 4
    for (int j = 0; j < N1; j++){
        float hv = hcol[j*DD];
        #pragma unroll
        for (int ii = 0; ii < 4; ii++) hp[ii] = fmaf(s_att[ii][j], hv, hp[ii]);
    }
    float gw1 = gW[l*2*DD + d], gw2 = gW[l*2*DD + DD + d], gbv = gb[l];
    #pragma unroll
    for (int ii = 0; ii < 4; ii++){
        hp[ii] = fmaxf(hp[ii], 0.f);
        s_g[ii][d] = fmaf(xd[ii], gw1, hp[ii]*gw2);
    }
    __syncthreads();
    int w = d >> 5, lane = d & 31;
    {   // warp w reduces row w (4 warps, 4 rows)
        float s = s_g[w][lane] + s_g[w][lane+32] + s_g[w][lane+64] + s_g[w][lane+96];
        #pragma unroll
        for (int o = 16; o; o >>= 1) s += __shfl_xor_sync(0xffffffffu, s, o);
        if (lane == 0) s_c[w] = sigmoidf_(s + gbv);
    }
    __syncthreads();
    #pragma unroll
    for (int ii = 0; ii < 4; ii++){
        float coeff = s_c[ii];
        float v = coeff*xd[ii] + (1.f - coeff)*hp[ii];
        g_h1g[(r0 + ii)*DD + d] = v;
        sx[ii][d] = v;
    }
    if (!has_next) return;
    __syncthreads();
    int nl = l + 1;
    const float* W  = gatW + nl*DD*DD;
    const float* WA = g_WA + nl*DD*DD;
    float wb  = gatWb[nl*DD + d];
    float bav = g_bA [nl*DD + d];
    float h[4], ha[4];
    #pragma unroll
    for (int ii = 0; ii < 4; ii++){ h[ii] = wb; ha[ii] = bav; }
    #pragma unroll 2
    for (int k = 0; k < DD; k++){
        float wv  = W [k*DD + d];
        float wav = WA[k*DD + d];
        #pragma unroll
        for (int ii = 0; ii < 4; ii++){
            h [ii] += sx[ii][k]*wv;
            ha[ii] += sx[ii][k]*wav;
        }
    }
    float* ho  = g_hX  + (nl & 1)*BB*N1*DD;
    float* hao = g_hAX + (nl & 1)*BB*N1*DD;
    #pragma unroll
    for (int ii = 0; ii < 4; ii++){
        ho [(r0 + ii)*DD + d] = h [ii];
        hao[(r0 + ii)*DD + d] = ha[ii];
    }
}

// ---------------- ligand pair projections (16 rows/block, 240 blocks) ----------------
__global__ __launch_bounds__(128) void k_proj1(const float* __restrict__ W1,
                                               const float* __restrict__ b1){
    int bi = blockIdx.x;
    int m  = bi / 48;
    int r0 = (bi % 48)*16;
    int hh = threadIdx.x;
    __shared__ float sx[16][DD];
    #pragma unroll
    for (int ii = 0; ii < 16; ii++) sx[ii][hh] = g_h1g[(r0 + ii)*DD + hh];
    __syncthreads();
    const float* W = W1 + m*2*DD*HH;
    float bias = b1[m*HH + hh];
    float acc[16];
    #pragma unroll
    for (int ii = 0; ii < 16; ii++) acc[ii] = bias;
    #pragma unroll 2
    for (int k = 0; k < DD; k++){
        float wv = W[k*HH + hh];
        #pragma unroll
        for (int ii = 0; ii < 16; ii++) acc[ii] = fmaf(sx[ii][k], wv, acc[ii]);
    }
    #pragma unroll
    for (int ii = 0; ii < 16; ii++) g_p1[(m*BB*N1 + r0 + ii)*HH + hh] = acc[ii];
}

// ---------------- pair energies: 16i x 32j tile, packed f32x2 mainloop ----------------
__global__ __launch_bounds__(256) void k_pair(const float* __restrict__ dmv,
                                              const float* __restrict__ c1,
                                              const float* __restrict__ c2,
                                              const float* __restrict__ eps,
                                              const float* __restrict__ sig,
                                              const float* __restrict__ val1,
                                              const float* __restrict__ val2,
                                              const float* __restrict__ nmm1,
                                              const float* __restrict__ nmm2,
                                              const float* __restrict__ W2,
                                              const float* __restrict__ b2,
                                              const float* __restrict__ vdwc){
    int bix = blockIdx.x;          // j tile 0..11
    int biy = blockIdx.y;          // i tile 0..47
    int r0  = biy*16;
    int b   = r0 / N1;
    int i1  = r0 % N1;
    int j0  = bix*32;
    __shared__ __align__(16) float s_p1[16][132];
    __shared__ __align__(16) float s_p2[32][132];
    __shared__ __align__(16) float s_w2[5][128];
    __shared__ float s_b2v[5];
    __shared__ float s_red[16];
    int tid = threadIdx.x, lane = tid & 31, w = tid >> 5;
    int j  = lane;
    int ia = w*2;
    for (int idx = tid; idx < 5*DD; idx += 256) s_w2[idx/DD][idx%DD] = W2[idx];
    if (tid < 5) s_b2v[tid] = b2[tid];
    float acc[2][5];
    for (int m = 0; m < 5; m++){
        __syncthreads();
        #pragma unroll
        for (int q = 0; q < 2; q++){
            int idx = tid + q*256;
            int row = idx >> 5, q4 = idx & 31;
            float4 v = *(const float4*)(g_p1 + (size_t)(m*BB*N1 + r0 + row)*HH + q4*4);
            *(float4*)&s_p1[row][q4*4] = v;
        }
        #pragma unroll
        for (int q = 0; q < 4; q++){
            int idx = tid + q*256;
            int row = idx >> 5, q4 = idx & 31;
            float4 v = *(const float4*)(g_p2 + (size_t)(m*BB*N2 + b*N2 + j0 + row)*HH + q4*4);
            *(float4*)&s_p2[row][q4*4] = v;
        }
        __syncthreads();
        u64t a0l = 0ULL, a0h = 0ULL, a1l = 0ULL, a1h = 0ULL;
        #pragma unroll
        for (int hv = 0; hv < 32; hv++){
            ulonglong2 w4  = *(const ulonglong2*)&s_w2[m][hv*4];
            ulonglong2 p2v = *(const ulonglong2*)&s_p2[j][hv*4];
            ulonglong2 pa  = *(const ulonglong2*)&s_p1[ia][hv*4];
            ulonglong2 pb  = *(const ulonglong2*)&s_p1[ia+1][hv*4];
            a0l = px_fma(px_max0(px_add(pa.x, p2v.x)), w4.x, a0l);
            a0h = px_fma(px_max0(px_add(pa.y, p2v.y)), w4.y, a0h);
            a1l = px_fma(px_max0(px_add(pb.x, p2v.x)), w4.x, a1l);
            a1h = px_fma(px_max0(px_add(pb.y, p2v.y)), w4.y, a1h);
        }
        acc[0][m] = px_sum(a0l) + px_sum(a0h);
        acc[1][m] = px_sum(a1l) + px_sum(a1h);
    }
    float vdwc2 = vdwc[0]*vdwc[0];
    float ec = 0.f, ev = 0.f;
    int jl = j0 + j;
    float c2v = c2[b*N2 + jl], v2v = val2[b*N2 + jl], n2v = nmm2[b*N2 + jl];
    #pragma unroll
    for (int q = 0; q < 2; q++){
        int il = i1 + ia + q;
        float v0 = acc[q][0] + s_b2v[0];
        float v1 = acc[q][1] + s_b2v[1];
        float v2 = acc[q][2] + s_b2v[2];
        float v3 = acc[q][3] + s_b2v[3];
        float v4 = acc[q][4] + s_b2v[4];
        int pix = (b*N1 + il)*N2 + jl;
        const float* dv = dmv + (size_t)pix*3;
        float dx = dv[0], dy = dv[1], dz = dv[2];
        float dm = sqrtf(dx*dx + dy*dy + dz*dz + 1e-10f);
        if (dm < 0.5f) dm = 1e10f;
        float l2dm = __log2f(dm);
        float cA  = sigmoidf_(v0);
        float cN  = 2.f*sigmoidf_(v1) + 1.f;
        float q12 = c1[b*N1 + il]*c2v;
        float e_c = cA*q12*exp2f(-cN*l2dm);
        e_c *= val1[b*N1 + il]*v2v;
        e_c = fminf(fmaxf(e_c, -100.f), 100.f);
        float vAv = (0.6f*sigmoidf_(v2) + 0.7f)*vdwc2*eps[pix];
        float vBv = tanhf(v3)*0.6f + 0.7f;
        float vNv = 2.f*sigmoidf_(v4) + 5.f;
        float dm0 = sig[pix]*vBv;
        if (dm0 < 1e-4f) dm0 = 1.f;
        float r  = exp2f(vNv*(__log2f(dm0) - l2dm));
        float e_v = vAv*(r*r - 2.f*r);
        e_v *= nmm1[b*N1 + il]*n2v;
        e_v = fminf(e_v, 100.f);
        ec += e_c; ev += e_v;
    }
    #pragma unroll
    for (int o = 16; o; o >>= 1){
        ec += __shfl_xor_sync(0xffffffffu, ec, o);
        ev += __shfl_xor_sync(0xffffffffu, ev, o);
    }
    if (lane == 0){ s_red[w] = ec; s_red[8 + w] = ev; }
    __syncthreads();
    if (tid == 0){
        float tec = 0.f, tev = 0.f;
        #pragma unroll
        for (int qq = 0; qq < 8; qq++){ tec += s_red[qq]; tev += s_red[8 + qq]; }
        g_pec[biy*12 + bix] = tec;
        g_pev[biy*12 + bix] = tev;
    }
}

// ---------------- finalize ----------------
__global__ __launch_bounds__(DD) void k_final(const float* __restrict__ valid1,
                                              const float* __restrict__ delta_uff,
                                              const float* __restrict__ duff,
                                              const float* __restrict__ iW1,
                                              const float* __restrict__ ib1,
                                              const float* __restrict__ iW2,
                                              const float* __restrict__ ib2,
                                              float* __restrict__ out){
    int b = blockIdx.x, d = threadIdx.x;
    __shared__ float s_hs[DD];
    __shared__ float s_red[DD];
    float hs = 0.f;
    for (int i = 0; i < N1; i++) hs += g_h1g[(b*N1 + i)*DD + d]*valid1[b*N1 + i];
    s_hs[d] = hs;
    __syncthreads();
    float hid = ib1[d];
    #pragma unroll 4
    for (int k = 0; k < DD; k++) hid += s_hs[k]*iW1[k*HH + d];
    hid = fmaxf(hid, 0.f);
    s_red[d] = hid*iW2[d];
    __syncthreads();
    for (int s = 64; s; s >>= 1){ if (d < s) s_red[d] += s_red[d + s]; __syncthreads(); }
    float inter = s_red[0] + ib2[0];
    __syncthreads();
    float tec = 0.f;
    for (int q = d; q < 288; q += DD) tec += g_pec[b*288 + q];
    s_red[d] = tec;
    __syncthreads();
    for (int s = 64; s; s >>= 1){ if (d < s) s_red[d] += s_red[d + s]; __syncthreads(); }
    float tecs = s_red[0];
    __syncthreads();
    float tev = 0.f;
    for (int q = d; q < 288; q += DD) tev += g_pev[b*288 + q];
    s_red[d] = tev;
    __syncthreads();
    for (int s = 64; s; s >>= 1){ if (d < s) s_red[d] += s_red[d + s]; __syncthreads(); }
    if (d == 0){
        out[b*4 + 0] = tecs;
        out[b*4 + 1] = s_red[0];
        out[b*4 + 2] = duff[0]*duff[0]*delta_uff[b];
        out[b*4 + 3] = inter;
    }
}

// ---------------- launch ----------------
// d_in follows setup_inputs() dict insertion order:
//   0:h1 1:h2 2:adj1 3:dmv 4:charge1 5:charge2 6:vdw_epsilon 7:vdw_sigma
//   8:delta_uff 9:valid1 10:valid2 11:no_metal1 12:no_metal2 13:node_W
//   14:gat_W 15:gat_Wb 16:gat_A 17:gat_gW 18:gat_gb 19:pair_W1 20:pair_b1
//   21:pair_W2 22:pair_b2 23:vdw_coeff 24:duff_coeff 25:int_W1 26:int_b1
//   27:int_W2 28:int_b2
extern "C" void kernel_launch(void* const* d_in, const int* in_sizes, int n_in,
                              void* d_out, int out_size){
    const float* h1        = (const float*)d_in[0];
    const float* h2        = (const float*)d_in[1];
    const float* adj1      = (const float*)d_in[2];
    const float* dmv       = (const float*)d_in[3];
    const float* charge1   = (const float*)d_in[4];
    const float* charge2   = (const float*)d_in[5];
    const float* eps       = (const float*)d_in[6];
    const float* sig       = (const float*)d_in[7];
    const float* delta_uff = (const float*)d_in[8];
    const float* valid1    = (const float*)d_in[9];
    const float* valid2    = (const float*)d_in[10];
    const float* nm1       = (const float*)d_in[11];
    const float* nm2       = (const float*)d_in[12];
    const float* nodeW     = (const float*)d_in[13];
    const float* gatW      = (const float*)d_in[14];
    const float* gatWb     = (const float*)d_in[15];
    const float* gatA      = (const float*)d_in[16];
    const float* gatgW     = (const float*)d_in[17];
    const float* gatgb     = (const float*)d_in[18];
    const float* pW1       = (const float*)d_in[19];
    const float* pb1       = (const float*)d_in[20];
    const float* pW2       = (const float*)d_in[21];
    const float* pb2       = (const float*)d_in[22];
    const float* vdwc      = (const float*)d_in[23];
    const float* duffc     = (const float*)d_in[24];
    const float* iW1       = (const float*)d_in[25];
    const float* ib1       = (const float*)d_in[26];
    const float* iW2       = (const float*)d_in[27];
    const float* ib2       = (const float*)d_in[28];
    float* out = (float*)d_out;

    k_pre_node<<<LL*DD + (BB*(N1+N2))/4, 128>>>(gatW, gatWb, gatA, h1, h2, nodeW);
    k_stage2<<<192 + 240, 128>>>(gatW, gatWb, pW1);
    for (int l = 0; l < LL; l++){
        k_e    <<<dim3(N1/64, N1/32, BB), 256>>>(l & 1);
        k_stats<<<BB*N1/8, 256>>>(adj1);
        k_fuse <<<BB*N1/4, 128>>>(adj1, gatgW, gatgb, gatW, gatWb, l, (l < LL-1) ? 1 : 0);
    }
    k_proj1<<<240, 128>>>(pW1, pb1);
    k_pair<<<dim3(N2/32, BB*N1/16), 256>>>(dmv, charge1, charge2, eps, sig,
                                           valid1, valid2, nm1, nm2, pW2, pb2, vdwc);
    k_final<<<BB, DD>>>(valid1, delta_uff, duffc, iW1, ib1, iW2, ib2, out);
}

// round 14
// speedup vs baseline: 1.3156x; 1.1273x over previous
#include <cuda_runtime.h>
#include <math.h>

#define BB 2
#define N1 384
#define N2 384
#define DD 128
#define HH 128
#define LL 3
#define NF 54

// ---------------- scratch (device globals; no allocation) ----------------
static __device__ float g_h1g[BB*N1*DD];
static __device__ float g_h2g[BB*N2*DD];
static __device__ float g_hX [2*BB*N1*DD];   // ping-pong h
static __device__ float g_hAX[2*BB*N1*DD];   // ping-pong hA
static __device__ float g_P  [BB*N1*N1];
static __device__ float g_PT [BB*N1*N1];
static __device__ float g_m  [BB*N1];
static __device__ float g_iz [BB*N1];
static __device__ float g_p1 [5*BB*N1*HH];
static __device__ float g_p2 [5*BB*N2*HH];
static __device__ float g_WA [LL*DD*DD];
static __device__ float g_bA [LL*DD];
static __device__ float g_pec[576];
static __device__ float g_pev[576];

__device__ __forceinline__ float sigmoidf_(float x){ return 1.f/(1.f+__expf(-x)); }

// packed f32x2 helpers (sm_100+ PTX): only add/mul/fma exist in f32x2 form.
typedef unsigned long long u64t;
__device__ __forceinline__ u64t px_add(u64t a, u64t b){
    u64t r; asm("add.rn.f32x2 %0, %1, %2;" : "=l"(r) : "l"(a), "l"(b)); return r;
}
__device__ __forceinline__ u64t px_fma(u64t a, u64t b, u64t c){
    u64t r; asm("fma.rn.f32x2 %0, %1, %2, %3;" : "=l"(r) : "l"(a), "l"(b), "l"(c)); return r;
}
__device__ __forceinline__ u64t px_max0(u64t a){
    float x, y;
    asm("mov.b64 {%0, %1}, %2;" : "=f"(x), "=f"(y) : "l"(a));
    x = fmaxf(x, 0.f);
    y = fmaxf(y, 0.f);
    u64t r;
    asm("mov.b64 %0, {%1, %2};" : "=l"(r) : "f"(x), "f"(y));
    return r;
}
__device__ __forceinline__ float px_sum(u64t v){
    float x, y;
    asm("mov.b64 {%0, %1}, %2;" : "=f"(x), "=f"(y) : "l"(v));
    return x + y;
}

// ---------------- fused: WA=W@A, bA=Wb@A  +  node projection ----------------
__global__ __launch_bounds__(128) void k_pre_node(const float* __restrict__ W,
                                                  const float* __restrict__ Wb,
                                                  const float* __restrict__ A,
                                                  const float* __restrict__ h1,
                                                  const float* __restrict__ h2,
                                                  const float* __restrict__ nW){
    int bi = blockIdx.x, d = threadIdx.x;
    if (bi < LL*DD){
        int l = bi / DD, k = bi % DD;
        __shared__ float sw[DD];
        __shared__ float sb[DD];
        sw[d] = W[(l*DD + k)*DD + d];
        if (k == 0) sb[d] = Wb[l*DD + d];
        __syncthreads();
        const float* Al = A + l*DD*DD;
        float acc = 0.f;
        #pragma unroll 4
        for (int m = 0; m < DD; m++) acc += sw[m]*Al[m*DD + d];
        g_WA[(l*DD + k)*DD + d] = acc;
        if (k == 0){
            float bacc = 0.f;
            #pragma unroll 4
            for (int m = 0; m < DD; m++) bacc += sb[m]*Al[m*DD + d];
            g_bA[l*DD + d] = bacc;
        }
    } else {
        int r0 = (bi - LL*DD)*4;
        __shared__ float sx[4][NF];
        bool lig = (r0 < BB*N1);
        const float* src = lig ? (h1 + r0*NF) : (h2 + (r0 - BB*N1)*NF);
        for (int idx = d; idx < 4*NF; idx += 128) ((float*)sx)[idx] = src[idx];
        __syncthreads();
        float acc[4] = {0.f,0.f,0.f,0.f};
        #pragma unroll 2
        for (int k = 0; k < NF; k++){
            float wv = nW[k*DD + d];
            #pragma unroll
            for (int ii = 0; ii < 4; ii++) acc[ii] += sx[ii][k]*wv;
        }
        float* dst = lig ? (g_h1g + r0*DD) : (g_h2g + (r0 - BB*N1)*DD);
        #pragma unroll
        for (int ii = 0; ii < 4; ii++) dst[ii*DD + d] = acc[ii];
    }
}

// ---------------- stage2: gat_h layer0 (192 blocks, 4 rows) + protein pair-proj (240 blocks) ----------------
__global__ __launch_bounds__(128) void k_stage2(const float* __restrict__ gatW,
                                                const float* __restrict__ gatWb,
                                                const float* __restrict__ W1){
    int bi = blockIdx.x, d = threadIdx.x;
    __shared__ float sx[16][DD];
    if (bi < 192){
        int r0 = bi*4;
        #pragma unroll
        for (int ii = 0; ii < 4; ii++) sx[ii][d] = g_h1g[(r0 + ii)*DD + d];
        __syncthreads();
        float wb = gatWb[d], bav = g_bA[d];
        float h[4], ha[4];
        #pragma unroll
        for (int ii = 0; ii < 4; ii++){ h[ii] = wb; ha[ii] = bav; }
        #pragma unroll 2
        for (int k = 0; k < DD; k++){
            float wv  = gatW[k*DD + d];
            float wav = g_WA[k*DD + d];
            #pragma unroll
            for (int ii = 0; ii < 4; ii++){
                h [ii] += sx[ii][k]*wv;
                ha[ii] += sx[ii][k]*wav;
            }
        }
        #pragma unroll
        for (int ii = 0; ii < 4; ii++){
            g_hX [(r0 + ii)*DD + d] = h [ii];
            g_hAX[(r0 + ii)*DD + d] = ha[ii];
        }
    } else {
        int pi = bi - 192;
        int m  = pi / 48;
        int r0 = (pi % 48)*16;
        #pragma unroll
        for (int ii = 0; ii < 16; ii++) sx[ii][d] = g_h2g[(r0 + ii)*DD + d];
        __syncthreads();
        const float* W = W1 + m*2*DD*HH + DD*HH;   // protein half, no bias
        float acc[16];
        #pragma unroll
        for (int ii = 0; ii < 16; ii++) acc[ii] = 0.f;
        #pragma unroll 2
        for (int k = 0; k < DD; k++){
            float wv = W[k*HH + d];
            #pragma unroll
            for (int ii = 0; ii < 16; ii++) acc[ii] = fmaf(sx[ii][k], wv, acc[ii]);
        }
        #pragma unroll
        for (int ii = 0; ii < 16; ii++) g_p2[(m*BB*N2 + r0 + ii)*HH + d] = acc[ii];
    }
}

// ---------------- P = hA @ h^T (and coalesced P^T) : 32x64 tiles, 144 blocks ----------------
__global__ __launch_bounds__(256) void k_e(int cur){
    const float* hb  = g_hX  + cur*BB*N1*DD;
    const float* hab = g_hAX + cur*BB*N1*DD;
    int b = blockIdx.z, j0 = blockIdx.y*32, k0 = blockIdx.x*64;
    __shared__ __align__(16) float sA[64][36];
    __shared__ __align__(16) float sB[64][68];
    int tid = threadIdx.x;
    int tx = tid & 15, ty = tid >> 4;
    float acc[2][4];
    #pragma unroll
    for (int r = 0; r < 2; r++)
        #pragma unroll
        for (int c = 0; c < 4; c++) acc[r][c] = 0.f;
    const float* baseA = hab + (b*N1 + j0)*DD;
    const float* baseB = hb  + (b*N1 + k0)*DD;
    for (int ks = 0; ks < 2; ks++){
        __syncthreads();
        #pragma unroll
        for (int q = 0; q < 2; q++){
            int idx = tid + q*256;
            int row = idx & 31, kq = idx >> 5;
            float4 va = *(const float4*)(baseA + row*DD + ks*64 + kq*4);
            sA[kq*4+0][row] = va.x; sA[kq*4+1][row] = va.y;
            sA[kq*4+2][row] = va.z; sA[kq*4+3][row] = va.w;
        }
        #pragma unroll
        for (int q = 0; q < 4; q++){
            int idx = tid + q*256;
            int row = idx & 63, kq = idx >> 6;
            float4 vb = *(const float4*)(baseB + row*DD + ks*64 + kq*4);
            sB[kq*4+0][row] = vb.x; sB[kq*4+1][row] = vb.y;
            sB[kq*4+2][row] = vb.z; sB[kq*4+3][row] = vb.w;
        }
        __syncthreads();
        #pragma unroll 8
        for (int kk = 0; kk < 64; kk++){
            float2 av = *(const float2*)&sA[kk][ty*2];
            float4 bv = *(const float4*)&sB[kk][tx*4];
            acc[0][0] = fmaf(av.x, bv.x, acc[0][0]);
            acc[0][1] = fmaf(av.x, bv.y, acc[0][1]);
            acc[0][2] = fmaf(av.x, bv.z, acc[0][2]);
            acc[0][3] = fmaf(av.x, bv.w, acc[0][3]);
            acc[1][0] = fmaf(av.y, bv.x, acc[1][0]);
            acc[1][1] = fmaf(av.y, bv.y, acc[1][1]);
            acc[1][2] = fmaf(av.y, bv.z, acc[1][2]);
            acc[1][3] = fmaf(av.y, bv.w, acc[1][3]);
        }
    }
    #pragma unroll
    for (int r = 0; r < 2; r++){
        float4 o = make_float4(acc[r][0], acc[r][1], acc[r][2], acc[r][3]);
        *(float4*)&g_P[(size_t)(b*N1 + j0 + ty*2 + r)*N1 + k0 + tx*4] = o;
    }
    // stage transposed tile into retired sA, then write PT rows coalesced
    __syncthreads();
    float* sT = &sA[0][0];     // 64*36 floats, row stride 36 (16B-aligned rows)
    #pragma unroll
    for (int r = 0; r < 2; r++)
        #pragma unroll
        for (int c = 0; c < 4; c++)
            sT[(tx*4 + c)*36 + ty*2 + r] = acc[r][c];
    __syncthreads();
    #pragma unroll
    for (int q = 0; q < 2; q++){
        int idx = tid + q*256;
        int row = idx >> 3;        // 0..63 (k-tile row)
        int cq  = idx & 7;         // float4 column index 0..7
        float4 v = *(const float4*)&sT[row*36 + cq*4];
        *(float4*)&g_PT[(size_t)(b*N1 + k0 + row)*N1 + j0 + cq*4] = v;
    }
}

// ---------------- column stats via symmetry: m[j], invZ[j] from row j of e ----------------
__global__ __launch_bounds__(256) void k_stats(const float* __restrict__ adj){
    int w = threadIdx.x >> 5, lane = threadIdx.x & 31;
    int rg = blockIdx.x*8 + w;                 // global row 0..767
    const float* pr  = g_P  + (size_t)rg*N1;
    const float* ptr = g_PT + (size_t)rg*N1;
    const float* ar  = adj  + (size_t)rg*N1;
    float ev[12];
    float mx = -INFINITY;
    #pragma unroll
    for (int t = 0; t < 12; t++){
        int i = lane + t*32;
        float a = ar[i];
        float e = (a > 0.f) ? (pr[i] + ptr[i]) : -9e15f;
        ev[t] = e;
        mx = fmaxf(mx, e);
    }
    #pragma unroll
    for (int o = 16; o; o >>= 1) mx = fmaxf(mx, __shfl_xor_sync(0xffffffffu, mx, o));
    float sum = 0.f;
    #pragma unroll
    for (int t = 0; t < 12; t++) sum += __expf(ev[t] - mx);
    #pragma unroll
    for (int o = 16; o; o >>= 1) sum += __shfl_xor_sync(0xffffffffu, sum, o);
    if (lane == 0){
        g_m [rg] = mx;
        g_iz[rg] = 1.f/sum;
    }
}

// ---------------- fused: att on the fly, h'=relu(att@h) via smem-tiled h, gate, next h/hA ----------------
// dynamic smem layout (floats):
//   s_h   [2][64][128]  : 16384
//   s_att [4][384]      : 1536
//   s_m   [384]         : 384
//   s_iz  [384]         : 384
//   s_g   [4][128]      : 512
//   sx    [4][128]      : 512
//   s_c   [4]           : 4
#define FUSE_SMEM ((16384 + 1536 + 384 + 384 + 512 + 512 + 4)*4)
__global__ __launch_bounds__(128) void k_fuse(const float* __restrict__ adj,
                                              const float* __restrict__ gW,
                                              const float* __restrict__ gb,
                                              const float* __restrict__ gatW,
                                              const float* __restrict__ gatWb,
                                              int l, int has_next){
    extern __shared__ __align__(16) float sm[];
    float* s_h   = sm;                  // [2][64][128]
    float* s_att = sm + 16384;          // [4][384]
    float* s_m   = sm + 16384 + 1536;
    float* s_iz  = s_m + 384;
    float* s_g   = s_iz + 384;          // [4][128]
    float* sx    = s_g + 512;           // [4][128]
    float* s_c   = sx + 512;            // [4]
    int r0 = blockIdx.x*4;
    int b  = r0 / N1;
    int d  = threadIdx.x;
    const float* hb = g_hX + (l & 1)*BB*N1*DD;
    const float* hbase = hb + b*N1*DD;
    // stage tile 0 + load m/iz + xd
    #pragma unroll
    for (int q = 0; q < 16; q++){
        int idx = d + q*128;
        int row = idx >> 5, cq = idx & 31;
        *(float4*)&s_h[(size_t)row*DD + cq*4] = *(const float4*)(hbase + row*DD + cq*4);
    }
    for (int idx = d; idx < N1; idx += 128){
        s_m [idx] = g_m [b*N1 + idx];
        s_iz[idx] = g_iz[b*N1 + idx];
    }
    float xd[4];
    #pragma unroll
    for (int ii = 0; ii < 4; ii++) xd[ii] = g_h1g[(r0 + ii)*DD + d];
    __syncthreads();
    // build attention row weights on the fly (needs s_m/s_iz)
    for (int idx = d; idx < 4*N1; idx += 128){
        int ii = idx / N1, j = idx % N1;
        float a = adj[(size_t)(r0 + ii)*N1 + j];
        float wv = 0.f;
        if (a > 0.f){
            float e = g_P[(size_t)(r0 + ii)*N1 + j] + g_PT[(size_t)(r0 + ii)*N1 + j];
            wv = __expf(e - s_m[j])*s_iz[j]*a;
        }
        s_att[ii*N1 + j] = wv;
    }
    __syncthreads();
    // mainloop over 6 tiles of 64 rows, double-buffered
    float hp[4] = {0.f,0.f,0.f,0.f};
    for (int t = 0; t < 6; t++){
        if (t < 5){
            const float* src = hbase + (t + 1)*64*DD;
            float* dst = s_h + ((t + 1) & 1)*64*DD;
            #pragma unroll
            for (int q = 0; q < 16; q++){
                int idx = d + q*128;
                int row = idx >> 5, cq = idx & 31;
                *(float4*)&dst[(size_t)row*DD + cq*4] = *(const float4*)(src + row*DD + cq*4);
            }
        }
        const float* cur = s_h + (t & 1)*64*DD;
        const float* aw  = s_att + t*64;     // s_att[ii][t*64 + jj]
        #pragma unroll 4
        for (int jj = 0; jj < 64; jj++){
            float hv = cur[jj*DD + d];
            #pragma unroll
            for (int ii = 0; ii < 4; ii++)
                hp[ii] = fmaf(aw[ii*N1 + jj], hv, hp[ii]);
        }
        __syncthreads();
    }
    float gw1 = gW[l*2*DD + d], gw2 = gW[l*2*DD + DD + d], gbv = gb[l];
    #pragma unroll
    for (int ii = 0; ii < 4; ii++){
        hp[ii] = fmaxf(hp[ii], 0.f);
        s_g[ii*DD + d] = fmaf(xd[ii], gw1, hp[ii]*gw2);
    }
    __syncthreads();
    int w = d >> 5, lane = d & 31;
    {   // warp w reduces row w (4 warps, 4 rows)
        float s = s_g[w*DD + lane] + s_g[w*DD + lane+32] + s_g[w*DD + lane+64] + s_g[w*DD + lane+96];
        #pragma unroll
        for (int o = 16; o; o >>= 1) s += __shfl_xor_sync(0xffffffffu, s, o);
        if (lane == 0) s_c[w] = sigmoidf_(s + gbv);
    }
    __syncthreads();
    #pragma unroll
    for (int ii = 0; ii < 4; ii++){
        float coeff = s_c[ii];
        float v = coeff*xd[ii] + (1.f - coeff)*hp[ii];
        g_h1g[(r0 + ii)*DD + d] = v;
        sx[ii*DD + d] = v;
    }
    if (!has_next) return;
    __syncthreads();
    int nl = l + 1;
    const float* W  = gatW + nl*DD*DD;
    const float* WA = g_WA + nl*DD*DD;
    float wb  = gatWb[nl*DD + d];
    float bav = g_bA [nl*DD + d];
    float h[4], ha[4];
    #pragma unroll
    for (int ii = 0; ii < 4; ii++){ h[ii] = wb; ha[ii] = bav; }
    #pragma unroll 2
    for (int k = 0; k < DD; k++){
        float wv  = W [k*DD + d];
        float wav = WA[k*DD + d];
        #pragma unroll
        for (int ii = 0; ii < 4; ii++){
            h [ii] += sx[ii*DD + k]*wv;
            ha[ii] += sx[ii*DD + k]*wav;
        }
    }
    float* ho  = g_hX  + (nl & 1)*BB*N1*DD;
    float* hao = g_hAX + (nl & 1)*BB*N1*DD;
    #pragma unroll
    for (int ii = 0; ii < 4; ii++){
        ho [(r0 + ii)*DD + d] = h [ii];
        hao[(r0 + ii)*DD + d] = ha[ii];
    }
}

// ---------------- ligand pair projections (16 rows/block, 240 blocks) ----------------
__global__ __launch_bounds__(128) void k_proj1(const float* __restrict__ W1,
                                               const float* __restrict__ b1){
    int bi = blockIdx.x;
    int m  = bi / 48;
    int r0 = (bi % 48)*16;
    int hh = threadIdx.x;
    __shared__ float sx[16][DD];
    #pragma unroll
    for (int ii = 0; ii < 16; ii++) sx[ii][hh] = g_h1g[(r0 + ii)*DD + hh];
    __syncthreads();
    const float* W = W1 + m*2*DD*HH;
    float bias = b1[m*HH + hh];
    float acc[16];
    #pragma unroll
    for (int ii = 0; ii < 16; ii++) acc[ii] = bias;
    #pragma unroll 2
    for (int k = 0; k < DD; k++){
        float wv = W[k*HH + hh];
        #pragma unroll
        for (int ii = 0; ii < 16; ii++) acc[ii] = fmaf(sx[ii][k], wv, acc[ii]);
    }
    #pragma unroll
    for (int ii = 0; ii < 16; ii++) g_p1[(m*BB*N1 + r0 + ii)*HH + hh] = acc[ii];
}

// ---------------- pair energies: 16i x 32j tile, packed f32x2 mainloop ----------------
__global__ __launch_bounds__(256) void k_pair(const float* __restrict__ dmv,
                                              const float* __restrict__ c1,
                                              const float* __restrict__ c2,
                                              const float* __restrict__ eps,
                                              const float* __restrict__ sig,
                                              const float* __restrict__ val1,
                                              const float* __restrict__ val2,
                                              const float* __restrict__ nmm1,
                                              const float* __restrict__ nmm2,
                                              const float* __restrict__ W2,
                                              const float* __restrict__ b2,
                                              const float* __restrict__ vdwc){
    int bix = blockIdx.x;          // j tile 0..11
    int biy = blockIdx.y;          // i tile 0..47
    int r0  = biy*16;
    int b   = r0 / N1;
    int i1  = r0 % N1;
    int j0  = bix*32;
    __shared__ __align__(16) float s_p1[16][132];
    __shared__ __align__(16) float s_p2[32][132];
    __shared__ __align__(16) float s_w2[5][128];
    __shared__ float s_b2v[5];
    __shared__ float s_red[16];
    int tid = threadIdx.x, lane = tid & 31, w = tid >> 5;
    int j  = lane;
    int ia = w*2;
    for (int idx = tid; idx < 5*DD; idx += 256) s_w2[idx/DD][idx%DD] = W2[idx];
    if (tid < 5) s_b2v[tid] = b2[tid];
    float acc[2][5];
    for (int m = 0; m < 5; m++){
        __syncthreads();
        #pragma unroll
        for (int q = 0; q < 2; q++){
            int idx = tid + q*256;
            int row = idx >> 5, q4 = idx & 31;
            float4 v = *(const float4*)(g_p1 + (size_t)(m*BB*N1 + r0 + row)*HH + q4*4);
            *(float4*)&s_p1[row][q4*4] = v;
        }
        #pragma unroll
        for (int q = 0; q < 4; q++){
            int idx = tid + q*256;
            int row = idx >> 5, q4 = idx & 31;
            float4 v = *(const float4*)(g_p2 + (size_t)(m*BB*N2 + b*N2 + j0 + row)*HH + q4*4);
            *(float4*)&s_p2[row][q4*4] = v;
        }
        __syncthreads();
        u64t a0l = 0ULL, a0h = 0ULL, a1l = 0ULL, a1h = 0ULL;
        #pragma unroll
        for (int hv = 0; hv < 32; hv++){
            ulonglong2 w4  = *(const ulonglong2*)&s_w2[m][hv*4];
            ulonglong2 p2v = *(const ulonglong2*)&s_p2[j][hv*4];
            ulonglong2 pa  = *(const ulonglong2*)&s_p1[ia][hv*4];
            ulonglong2 pb  = *(const ulonglong2*)&s_p1[ia+1][hv*4];
            a0l = px_fma(px_max0(px_add(pa.x, p2v.x)), w4.x, a0l);
            a0h = px_fma(px_max0(px_add(pa.y, p2v.y)), w4.y, a0h);
            a1l = px_fma(px_max0(px_add(pb.x, p2v.x)), w4.x, a1l);
            a1h = px_fma(px_max0(px_add(pb.y, p2v.y)), w4.y, a1h);
        }
        acc[0][m] = px_sum(a0l) + px_sum(a0h);
        acc[1][m] = px_sum(a1l) + px_sum(a1h);
    }
    float vdwc2 = vdwc[0]*vdwc[0];
    float ec = 0.f, ev = 0.f;
    int jl = j0 + j;
    float c2v = c2[b*N2 + jl], v2v = val2[b*N2 + jl], n2v = nmm2[b*N2 + jl];
    #pragma unroll
    for (int q = 0; q < 2; q++){
        int il = i1 + ia + q;
        float v0 = acc[q][0] + s_b2v[0];
        float v1 = acc[q][1] + s_b2v[1];
        float v2 = acc[q][2] + s_b2v[2];
        float v3 = acc[q][3] + s_b2v[3];
        float v4 = acc[q][4] + s_b2v[4];
        int pix = (b*N1 + il)*N2 + jl;
        const float* dv = dmv + (size_t)pix*3;
        float dx = dv[0], dy = dv[1], dz = dv[2];
        float dm = sqrtf(dx*dx + dy*dy + dz*dz + 1e-10f);
        if (dm < 0.5f) dm = 1e10f;
        float l2dm = __log2f(dm);
        float cA  = sigmoidf_(v0);
        float cN  = 2.f*sigmoidf_(v1) + 1.f;
        float q12 = c1[b*N1 + il]*c2v;
        float e_c = cA*q12*exp2f(-cN*l2dm);
        e_c *= val1[b*N1 + il]*v2v;
        e_c = fminf(fmaxf(e_c, -100.f), 100.f);
        float vAv = (0.6f*sigmoidf_(v2) + 0.7f)*vdwc2*eps[pix];
        float vBv = tanhf(v3)*0.6f + 0.7f;
        float vNv = 2.f*sigmoidf_(v4) + 5.f;
        float dm0 = sig[pix]*vBv;
        if (dm0 < 1e-4f) dm0 = 1.f;
        float r  = exp2f(vNv*(__log2f(dm0) - l2dm));
        float e_v = vAv*(r*r - 2.f*r);
        e_v *= nmm1[b*N1 + il]*n2v;
        e_v = fminf(e_v, 100.f);
        ec += e_c; ev += e_v;
    }
    #pragma unroll
    for (int o = 16; o; o >>= 1){
        ec += __shfl_xor_sync(0xffffffffu, ec, o);
        ev += __shfl_xor_sync(0xffffffffu, ev, o);
    }
    if (lane == 0){ s_red[w] = ec; s_red[8 + w] = ev; }
    __syncthreads();
    if (tid == 0){
        float tec = 0.f, tev = 0.f;
        #pragma unroll
        for (int qq = 0; qq < 8; qq++){ tec += s_red[qq]; tev += s_red[8 + qq]; }
        g_pec[biy*12 + bix] = tec;
        g_pev[biy*12 + bix] = tev;
    }
}

// ---------------- finalize ----------------
__global__ __launch_bounds__(DD) void k_final(const float* __restrict__ valid1,
                                              const float* __restrict__ delta_uff,
                                              const float* __restrict__ duff,
                                              const float* __restrict__ iW1,
                                              const float* __restrict__ ib1,
                                              const float* __restrict__ iW2,
                                              const float* __restrict__ ib2,
                                              float* __restrict__ out){
    int b = blockIdx.x, d = threadIdx.x;
    __shared__ float s_hs[DD];
    __shared__ float s_red[DD];
    float hs = 0.f;
    for (int i = 0; i < N1; i++) hs += g_h1g[(b*N1 + i)*DD + d]*valid1[b*N1 + i];
    s_hs[d] = hs;
    __syncthreads();
    float hid = ib1[d];
    #pragma unroll 4
    for (int k = 0; k < DD; k++) hid += s_hs[k]*iW1[k*HH + d];
    hid = fmaxf(hid, 0.f);
    s_red[d] = hid*iW2[d];
    __syncthreads();
    for (int s = 64; s; s >>= 1){ if (d < s) s_red[d] += s_red[d + s]; __syncthreads(); }
    float inter = s_red[0] + ib2[0];
    __syncthreads();
    float tec = 0.f;
    for (int q = d; q < 288; q += DD) tec += g_pec[b*288 + q];
    s_red[d] = tec;
    __syncthreads();
    for (int s = 64; s; s >>= 1){ if (d < s) s_red[d] += s_red[d + s]; __syncthreads(); }
    float tecs = s_red[0];
    __syncthreads();
    float tev = 0.f;
    for (int q = d; q < 288; q += DD) tev += g_pev[b*288 + q];
    s_red[d] = tev;
    __syncthreads();
    for (int s = 64; s; s >>= 1){ if (d < s) s_red[d] += s_red[d + s]; __syncthreads(); }
    if (d == 0){
        out[b*4 + 0] = tecs;
        out[b*4 + 1] = s_red[0];
        out[b*4 + 2] = duff[0]*duff[0]*delta_uff[b];
        out[b*4 + 3] = inter;
    }
}

// ---------------- launch ----------------
// d_in follows setup_inputs() dict insertion order:
//   0:h1 1:h2 2:adj1 3:dmv 4:charge1 5:charge2 6:vdw_epsilon 7:vdw_sigma
//   8:delta_uff 9:valid1 10:valid2 11:no_metal1 12:no_metal2 13:node_W
//   14:gat_W 15:gat_Wb 16:gat_A 17:gat_gW 18:gat_gb 19:pair_W1 20:pair_b1
//   21:pair_W2 22:pair_b2 23:vdw_coeff 24:duff_coeff 25:int_W1 26:int_b1
//   27:int_W2 28:int_b2
extern "C" void kernel_launch(void* const* d_in, const int* in_sizes, int n_in,
                              void* d_out, int out_size){
    const float* h1        = (const float*)d_in[0];
    const float* h2        = (const float*)d_in[1];
    const float* adj1      = (const float*)d_in[2];
    const float* dmv       = (const float*)d_in[3];
    const float* charge1   = (const float*)d_in[4];
    const float* charge2   = (const float*)d_in[5];
    const float* eps       = (const float*)d_in[6];
    const float* sig       = (const float*)d_in[7];
    const float* delta_uff = (const float*)d_in[8];
    const float* valid1    = (const float*)d_in[9];
    const float* valid2    = (const float*)d_in[10];
    const float* nm1       = (const float*)d_in[11];
    const float* nm2       = (const float*)d_in[12];
    const float* nodeW     = (const float*)d_in[13];
    const float* gatW      = (const float*)d_in[14];
    const float* gatWb     = (const float*)d_in[15];
    const float* gatA      = (const float*)d_in[16];
    const float* gatgW     = (const float*)d_in[17];
    const float* gatgb     = (const float*)d_in[18];
    const float* pW1       = (const float*)d_in[19];
    const float* pb1       = (const float*)d_in[20];
    const float* pW2       = (const float*)d_in[21];
    const float* pb2       = (const float*)d_in[22];
    const float* vdwc      = (const float*)d_in[23];
    const float* duffc     = (const float*)d_in[24];
    const float* iW1       = (const float*)d_in[25];
    const float* ib1       = (const float*)d_in[26];
    const float* iW2       = (const float*)d_in[27];
    const float* ib2       = (const float*)d_in[28];
    float* out = (float*)d_out;

    static int attr_set = 0;
    if (!attr_set){
        cudaFuncSetAttribute(k_fuse, cudaFuncAttributeMaxDynamicSharedMemorySize, FUSE_SMEM);
        attr_set = 1;
    }

    k_pre_node<<<LL*DD + (BB*(N1+N2))/4, 128>>>(gatW, gatWb, gatA, h1, h2, nodeW);
    k_stage2<<<192 + 240, 128>>>(gatW, gatWb, pW1);
    for (int l = 0; l < LL; l++){
        k_e    <<<dim3(N1/64, N1/32, BB), 256>>>(l & 1);
        k_stats<<<BB*N1/8, 256>>>(adj1);
        k_fuse <<<BB*N1/4, 128, FUSE_SMEM>>>(adj1, gatgW, gatgb, gatW, gatWb, l, (l < LL-1) ? 1 : 0);
    }
    k_proj1<<<240, 128>>>(pW1, pb1);
    k_pair<<<dim3(N2/32, BB*N1/16), 256>>>(dmv, charge1, charge2, eps, sig,
                                           valid1, valid2, nm1, nm2, pW2, pb2, vdwc);
    k_final<<<BB, DD>>>(valid1, delta_uff, duffc, iW1, ib1, iW2, ib2, out);
}

// round 15
// speedup vs baseline: 1.4586x; 1.1087x over previous
#include <cuda_runtime.h>
#include <math.h>

#define BB 2
#define N1 384
#define N2 384
#define DD 128
#define HH 128
#define LL 3
#define NF 54

// ---------------- scratch (device globals; no allocation) ----------------
static __device__ float g_h1g[BB*N1*DD];
static __device__ float g_h2g[BB*N2*DD];
static __device__ float g_hX [2*BB*N1*DD];   // ping-pong h
static __device__ float g_hAX[2*BB*N1*DD];   // ping-pong hA
static __device__ float g_P  [BB*N1*N1];
static __device__ float g_PT [BB*N1*N1];
static __device__ float g_m  [BB*N1];
static __device__ float g_iz [BB*N1];
static __device__ float g_p1 [5*BB*N1*HH];
static __device__ float g_p2 [5*BB*N2*HH];
static __device__ float g_WA [LL*DD*DD];
static __device__ float g_bA [LL*DD];
static __device__ float g_pec[288];
static __device__ float g_pev[288];

__device__ __forceinline__ float sigmoidf_(float x){ return 1.f/(1.f+__expf(-x)); }

// packed f32x2 helpers (sm_100+ PTX): only add/mul/fma exist in f32x2 form.
typedef unsigned long long u64t;
__device__ __forceinline__ u64t px_add(u64t a, u64t b){
    u64t r; asm("add.rn.f32x2 %0, %1, %2;" : "=l"(r) : "l"(a), "l"(b)); return r;
}
__device__ __forceinline__ u64t px_fma(u64t a, u64t b, u64t c){
    u64t r; asm("fma.rn.f32x2 %0, %1, %2, %3;" : "=l"(r) : "l"(a), "l"(b), "l"(c)); return r;
}
__device__ __forceinline__ u64t px_max0(u64t a){
    float x, y;
    asm("mov.b64 {%0, %1}, %2;" : "=f"(x), "=f"(y) : "l"(a));
    x = fmaxf(x, 0.f);
    y = fmaxf(y, 0.f);
    u64t r;
    asm("mov.b64 %0, {%1, %2};" : "=l"(r) : "f"(x), "f"(y));
    return r;
}
__device__ __forceinline__ float px_sum(u64t v){
    float x, y;
    asm("mov.b64 {%0, %1}, %2;" : "=f"(x), "=f"(y) : "l"(v));
    return x + y;
}

// ---------------- fused: WA=W@A, bA=Wb@A  +  node projection ----------------
__global__ __launch_bounds__(128) void k_pre_node(const float* __restrict__ W,
                                                  const float* __restrict__ Wb,
                                                  const float* __restrict__ A,
                                                  const float* __restrict__ h1,
                                                  const float* __restrict__ h2,
                                                  const float* __restrict__ nW){
    int bi = blockIdx.x, d = threadIdx.x;
    if (bi < LL*DD){
        int l = bi / DD, k = bi % DD;
        __shared__ float sw[DD];
        __shared__ float sb[DD];
        sw[d] = W[(l*DD + k)*DD + d];
        if (k == 0) sb[d] = Wb[l*DD + d];
        __syncthreads();
        const float* Al = A + l*DD*DD;
        float acc = 0.f;
        #pragma unroll 4
        for (int m = 0; m < DD; m++) acc += sw[m]*Al[m*DD + d];
        g_WA[(l*DD + k)*DD + d] = acc;
        if (k == 0){
            float bacc = 0.f;
            #pragma unroll 4
            for (int m = 0; m < DD; m++) bacc += sb[m]*Al[m*DD + d];
            g_bA[l*DD + d] = bacc;
        }
    } else {
        int r0 = (bi - LL*DD)*4;
        __shared__ float sx[4][NF];
        bool lig = (r0 < BB*N1);
        const float* src = lig ? (h1 + r0*NF) : (h2 + (r0 - BB*N1)*NF);
        for (int idx = d; idx < 4*NF; idx += 128) ((float*)sx)[idx] = src[idx];
        __syncthreads();
        float acc[4] = {0.f,0.f,0.f,0.f};
        #pragma unroll 2
        for (int k = 0; k < NF; k++){
            float wv = nW[k*DD + d];
            #pragma unroll
            for (int ii = 0; ii < 4; ii++) acc[ii] += sx[ii][k]*wv;
        }
        float* dst = lig ? (g_h1g + r0*DD) : (g_h2g + (r0 - BB*N1)*DD);
        #pragma unroll
        for (int ii = 0; ii < 4; ii++) dst[ii*DD + d] = acc[ii];
    }
}

// ---------------- stage2: gat_h layer0 (192 blocks, 4 rows) + protein pair-proj (240 blocks) ----------------
__global__ __launch_bounds__(128) void k_stage2(const float* __restrict__ gatW,
                                                const float* __restrict__ gatWb,
                                                const float* __restrict__ W1){
    int bi = blockIdx.x, d = threadIdx.x;
    __shared__ float sx[16][DD];
    if (bi < 192){
        int r0 = bi*4;
        #pragma unroll
        for (int ii = 0; ii < 4; ii++) sx[ii][d] = g_h1g[(r0 + ii)*DD + d];
        __syncthreads();
        float wb = gatWb[d], bav = g_bA[d];
        float h[4], ha[4];
        #pragma unroll
        for (int ii = 0; ii < 4; ii++){ h[ii] = wb; ha[ii] = bav; }
        #pragma unroll 2
        for (int k = 0; k < DD; k++){
            float wv  = gatW[k*DD + d];
            float wav = g_WA[k*DD + d];
            #pragma unroll
            for (int ii = 0; ii < 4; ii++){
                h [ii] += sx[ii][k]*wv;
                ha[ii] += sx[ii][k]*wav;
            }
        }
        #pragma unroll
        for (int ii = 0; ii < 4; ii++){
            g_hX [(r0 + ii)*DD + d] = h [ii];
            g_hAX[(r0 + ii)*DD + d] = ha[ii];
        }
    } else {
        int pi = bi - 192;
        int m  = pi / 48;
        int r0 = (pi % 48)*16;
        #pragma unroll
        for (int ii = 0; ii < 16; ii++) sx[ii][d] = g_h2g[(r0 + ii)*DD + d];
        __syncthreads();
        const float* W = W1 + m*2*DD*HH + DD*HH;   // protein half, no bias
        float acc[16];
        #pragma unroll
        for (int ii = 0; ii < 16; ii++) acc[ii] = 0.f;
        #pragma unroll 2
        for (int k = 0; k < DD; k++){
            float wv = W[k*HH + d];
            #pragma unroll
            for (int ii = 0; ii < 16; ii++) acc[ii] = fmaf(sx[ii][k], wv, acc[ii]);
        }
        #pragma unroll
        for (int ii = 0; ii < 16; ii++) g_p2[(m*BB*N2 + r0 + ii)*HH + d] = acc[ii];
    }
}

// ---------------- P = hA @ h^T (and coalesced P^T) : 32x64 tiles, 144 blocks ----------------
__global__ __launch_bounds__(256) void k_e(int cur){
    const float* hb  = g_hX  + cur*BB*N1*DD;
    const float* hab = g_hAX + cur*BB*N1*DD;
    int b = blockIdx.z, j0 = blockIdx.y*32, k0 = blockIdx.x*64;
    __shared__ __align__(16) float sA[64][36];
    __shared__ __align__(16) float sB[64][68];
    int tid = threadIdx.x;
    int tx = tid & 15, ty = tid >> 4;
    float acc[2][4];
    #pragma unroll
    for (int r = 0; r < 2; r++)
        #pragma unroll
        for (int c = 0; c < 4; c++) acc[r][c] = 0.f;
    const float* baseA = hab + (b*N1 + j0)*DD;
    const float* baseB = hb  + (b*N1 + k0)*DD;
    for (int ks = 0; ks < 2; ks++){
        __syncthreads();
        #pragma unroll
        for (int q = 0; q < 2; q++){
            int idx = tid + q*256;
            int row = idx & 31, kq = idx >> 5;
            float4 va = *(const float4*)(baseA + row*DD + ks*64 + kq*4);
            sA[kq*4+0][row] = va.x; sA[kq*4+1][row] = va.y;
            sA[kq*4+2][row] = va.z; sA[kq*4+3][row] = va.w;
        }
        #pragma unroll
        for (int q = 0; q < 4; q++){
            int idx = tid + q*256;
            int row = idx & 63, kq = idx >> 6;
            float4 vb = *(const float4*)(baseB + row*DD + ks*64 + kq*4);
            sB[kq*4+0][row] = vb.x; sB[kq*4+1][row] = vb.y;
            sB[kq*4+2][row] = vb.z; sB[kq*4+3][row] = vb.w;
        }
        __syncthreads();
        #pragma unroll 8
        for (int kk = 0; kk < 64; kk++){
            float2 av = *(const float2*)&sA[kk][ty*2];
            float4 bv = *(const float4*)&sB[kk][tx*4];
            acc[0][0] = fmaf(av.x, bv.x, acc[0][0]);
            acc[0][1] = fmaf(av.x, bv.y, acc[0][1]);
            acc[0][2] = fmaf(av.x, bv.z, acc[0][2]);
            acc[0][3] = fmaf(av.x, bv.w, acc[0][3]);
            acc[1][0] = fmaf(av.y, bv.x, acc[1][0]);
            acc[1][1] = fmaf(av.y, bv.y, acc[1][1]);
            acc[1][2] = fmaf(av.y, bv.z, acc[1][2]);
            acc[1][3] = fmaf(av.y, bv.w, acc[1][3]);
        }
    }
    #pragma unroll
    for (int r = 0; r < 2; r++){
        float4 o = make_float4(acc[r][0], acc[r][1], acc[r][2], acc[r][3]);
        *(float4*)&g_P[(size_t)(b*N1 + j0 + ty*2 + r)*N1 + k0 + tx*4] = o;
    }
    // stage transposed tile into retired sA, then write PT rows coalesced
    __syncthreads();
    float* sT = &sA[0][0];     // 64*36 floats, row stride 36 (16B-aligned rows)
    #pragma unroll
    for (int r = 0; r < 2; r++)
        #pragma unroll
        for (int c = 0; c < 4; c++)
            sT[(tx*4 + c)*36 + ty*2 + r] = acc[r][c];
    __syncthreads();
    #pragma unroll
    for (int q = 0; q < 2; q++){
        int idx = tid + q*256;
        int row = idx >> 3;        // 0..63 (k-tile row)
        int cq  = idx & 7;         // float4 column index 0..7
        float4 v = *(const float4*)&sT[row*36 + cq*4];
        *(float4*)&g_PT[(size_t)(b*N1 + k0 + row)*N1 + j0 + cq*4] = v;
    }
}

// ---------------- column stats via symmetry: m[j], invZ[j] from row j of e (float4) ----------------
__global__ __launch_bounds__(256) void k_stats(const float* __restrict__ adj){
    int w = threadIdx.x >> 5, lane = threadIdx.x & 31;
    int rg = blockIdx.x*8 + w;                 // global row 0..767
    const float4* pr  = (const float4*)(g_P  + (size_t)rg*N1);
    const float4* ptr = (const float4*)(g_PT + (size_t)rg*N1);
    const float4* ar  = (const float4*)(adj  + (size_t)rg*N1);
    float ev[12];
    float mx = -INFINITY;
    #pragma unroll
    for (int t = 0; t < 3; t++){
        int i4 = lane + t*32;
        float4 a = ar[i4], p = pr[i4], q = ptr[i4];
        float e0 = (a.x > 0.f) ? (p.x + q.x) : -9e15f;
        float e1 = (a.y > 0.f) ? (p.y + q.y) : -9e15f;
        float e2 = (a.z > 0.f) ? (p.z + q.z) : -9e15f;
        float e3 = (a.w > 0.f) ? (p.w + q.w) : -9e15f;
        ev[t*4+0] = e0; ev[t*4+1] = e1; ev[t*4+2] = e2; ev[t*4+3] = e3;
        mx = fmaxf(mx, fmaxf(fmaxf(e0, e1), fmaxf(e2, e3)));
    }
    #pragma unroll
    for (int o = 16; o; o >>= 1) mx = fmaxf(mx, __shfl_xor_sync(0xffffffffu, mx, o));
    float sum = 0.f;
    #pragma unroll
    for (int t = 0; t < 12; t++) sum += __expf(ev[t] - mx);
    #pragma unroll
    for (int o = 16; o; o >>= 1) sum += __shfl_xor_sync(0xffffffffu, sum, o);
    if (lane == 0){
        g_m [rg] = mx;
        g_iz[rg] = 1.f/sum;
    }
}

// ---------------- fused: att on the fly, h'=relu(att@h) via smem-tiled h, gate, next h/hA ----------------
#define FUSE_SMEM ((16384 + 1536 + 384 + 384 + 512 + 512 + 4)*4)
__global__ __launch_bounds__(128) void k_fuse(const float* __restrict__ adj,
                                              const float* __restrict__ gW,
                                              const float* __restrict__ gb,
                                              const float* __restrict__ gatW,
                                              const float* __restrict__ gatWb,
                                              int l, int has_next){
    extern __shared__ __align__(16) float sm[];
    float* s_h   = sm;                  // [2][64][128]
    float* s_att = sm + 16384;          // [4][384]
    float* s_m   = sm + 16384 + 1536;
    float* s_iz  = s_m + 384;
    float* s_g   = s_iz + 384;          // [4][128]
    float* sx    = s_g + 512;           // [4][128]
    float* s_c   = sx + 512;            // [4]
    int r0 = blockIdx.x*4;
    int b  = r0 / N1;
    int d  = threadIdx.x;
    const float* hb = g_hX + (l & 1)*BB*N1*DD;
    const float* hbase = hb + b*N1*DD;
    #pragma unroll
    for (int q = 0; q < 16; q++){
        int idx = d + q*128;
        int row = idx >> 5, cq = idx & 31;
        *(float4*)&s_h[(size_t)row*DD + cq*4] = *(const float4*)(hbase + row*DD + cq*4);
    }
    for (int idx = d; idx < N1; idx += 128){
        s_m [idx] = g_m [b*N1 + idx];
        s_iz[idx] = g_iz[b*N1 + idx];
    }
    float xd[4];
    #pragma unroll
    for (int ii = 0; ii < 4; ii++) xd[ii] = g_h1g[(r0 + ii)*DD + d];
    __syncthreads();
    // build attention weights on the fly (float4 streams)
    #pragma unroll
    for (int t = 0; t < 3; t++){
        int idx4 = d + t*128;          // 0..383, covers 4*96
        int ii = idx4 / 96, j4 = idx4 % 96;
        int j  = j4*4;
        float4 a = *(const float4*)(adj  + (size_t)(r0 + ii)*N1 + j);
        float4 p = *(const float4*)(g_P  + (size_t)(r0 + ii)*N1 + j);
        float4 q = *(const float4*)(g_PT + (size_t)(r0 + ii)*N1 + j);
        float4 wv;
        wv.x = (a.x > 0.f) ? __expf(p.x + q.x - s_m[j+0])*s_iz[j+0]*a.x : 0.f;
        wv.y = (a.y > 0.f) ? __expf(p.y + q.y - s_m[j+1])*s_iz[j+1]*a.y : 0.f;
        wv.z = (a.z > 0.f) ? __expf(p.z + q.z - s_m[j+2])*s_iz[j+2]*a.z : 0.f;
        wv.w = (a.w > 0.f) ? __expf(p.w + q.w - s_m[j+3])*s_iz[j+3]*a.w : 0.f;
        *(float4*)&s_att[ii*N1 + j] = wv;
    }
    __syncthreads();
    float hp[4] = {0.f,0.f,0.f,0.f};
    for (int t = 0; t < 6; t++){
        if (t < 5){
            const float* src = hbase + (t + 1)*64*DD;
            float* dst = s_h + ((t + 1) & 1)*64*DD;
            #pragma unroll
            for (int q = 0; q < 16; q++){
                int idx = d + q*128;
                int row = idx >> 5, cq = idx & 31;
                *(float4*)&dst[(size_t)row*DD + cq*4] = *(const float4*)(src + row*DD + cq*4);
            }
        }
        const float* cur = s_h + (t & 1)*64*DD;
        const float* aw  = s_att + t*64;
        #pragma unroll 4
        for (int jj = 0; jj < 64; jj++){
            float hv = cur[jj*DD + d];
            #pragma unroll
            for (int ii = 0; ii < 4; ii++)
                hp[ii] = fmaf(aw[ii*N1 + jj], hv, hp[ii]);
        }
        __syncthreads();
    }
    float gw1 = gW[l*2*DD + d], gw2 = gW[l*2*DD + DD + d], gbv = gb[l];
    #pragma unroll
    for (int ii = 0; ii < 4; ii++){
        hp[ii] = fmaxf(hp[ii], 0.f);
        s_g[ii*DD + d] = fmaf(xd[ii], gw1, hp[ii]*gw2);
    }
    __syncthreads();
    int w = d >> 5, lane = d & 31;
    {
        float s = s_g[w*DD + lane] + s_g[w*DD + lane+32] + s_g[w*DD + lane+64] + s_g[w*DD + lane+96];
        #pragma unroll
        for (int o = 16; o; o >>= 1) s += __shfl_xor_sync(0xffffffffu, s, o);
        if (lane == 0) s_c[w] = sigmoidf_(s + gbv);
    }
    __syncthreads();
    #pragma unroll
    for (int ii = 0; ii < 4; ii++){
        float coeff = s_c[ii];
        float v = coeff*xd[ii] + (1.f - coeff)*hp[ii];
        g_h1g[(r0 + ii)*DD + d] = v;
        sx[ii*DD + d] = v;
    }
    if (!has_next) return;
    __syncthreads();
    int nl = l + 1;
    const float* W  = gatW + nl*DD*DD;
    const float* WA = g_WA + nl*DD*DD;
    float wb  = gatWb[nl*DD + d];
    float bav = g_bA [nl*DD + d];
    float h[4], ha[4];
    #pragma unroll
    for (int ii = 0; ii < 4; ii++){ h[ii] = wb; ha[ii] = bav; }
    #pragma unroll 2
    for (int k = 0; k < DD; k++){
        float wv  = W [k*DD + d];
        float wav = WA[k*DD + d];
        #pragma unroll
        for (int ii = 0; ii < 4; ii++){
            h [ii] += sx[ii*DD + k]*wv;
            ha[ii] += sx[ii*DD + k]*wav;
        }
    }
    float* ho  = g_hX  + (nl & 1)*BB*N1*DD;
    float* hao = g_hAX + (nl & 1)*BB*N1*DD;
    #pragma unroll
    for (int ii = 0; ii < 4; ii++){
        ho [(r0 + ii)*DD + d] = h [ii];
        hao[(r0 + ii)*DD + d] = ha[ii];
    }
}

// ---------------- ligand pair projections (16 rows/block, 240 blocks) ----------------
__global__ __launch_bounds__(128) void k_proj1(const float* __restrict__ W1,
                                               const float* __restrict__ b1){
    int bi = blockIdx.x;
    int m  = bi / 48;
    int r0 = (bi % 48)*16;
    int hh = threadIdx.x;
    __shared__ float sx[16][DD];
    #pragma unroll
    for (int ii = 0; ii < 16; ii++) sx[ii][hh] = g_h1g[(r0 + ii)*DD + hh];
    __syncthreads();
    const float* W = W1 + m*2*DD*HH;
    float bias = b1[m*HH + hh];
    float acc[16];
    #pragma unroll
    for (int ii = 0; ii < 16; ii++) acc[ii] = bias;
    #pragma unroll 2
    for (int k = 0; k < DD; k++){
        float wv = W[k*HH + hh];
        #pragma unroll
        for (int ii = 0; ii < 16; ii++) acc[ii] = fmaf(sx[ii][k], wv, acc[ii]);
    }
    #pragma unroll
    for (int ii = 0; ii < 16; ii++) g_p1[(m*BB*N1 + r0 + ii)*HH + hh] = acc[ii];
}

// ---------------- pair energies: 32i x 32j tile, 4 i-rows per warp, f32x2 mainloop ----------------
__global__ __launch_bounds__(256) void k_pair(const float* __restrict__ dmv,
                                              const float* __restrict__ c1,
                                              const float* __restrict__ c2,
                                              const float* __restrict__ eps,
                                              const float* __restrict__ sig,
                                              const float* __restrict__ val1,
                                              const float* __restrict__ val2,
                                              const float* __restrict__ nmm1,
                                              const float* __restrict__ nmm2,
                                              const float* __restrict__ W2,
                                              const float* __restrict__ b2,
                                              const float* __restrict__ vdwc){
    int bix = blockIdx.x;          // j tile 0..11
    int biy = blockIdx.y;          // i tile 0..23 (32 rows each)
    int r0  = biy*32;
    int b   = r0 / N1;
    int i1  = r0 % N1;
    int j0  = bix*32;
    __shared__ __align__(16) float s_p1[32][132];
    __shared__ __align__(16) float s_p2[32][132];
    __shared__ __align__(16) float s_w2[5][128];
    __shared__ float s_b2v[5];
    __shared__ float s_red[16];
    int tid = threadIdx.x, lane = tid & 31, w = tid >> 5;
    int j  = lane;
    int ia = w*4;
    for (int idx = tid; idx < 5*DD; idx += 256) s_w2[idx/DD][idx%DD] = W2[idx];
    if (tid < 5) s_b2v[tid] = b2[tid];
    float acc[4][5];
    for (int m = 0; m < 5; m++){
        __syncthreads();
        #pragma unroll
        for (int q = 0; q < 4; q++){
            int idx = tid + q*256;
            int row = idx >> 5, q4 = idx & 31;
            float4 v = *(const float4*)(g_p1 + (size_t)(m*BB*N1 + r0 + row)*HH + q4*4);
            *(float4*)&s_p1[row][q4*4] = v;
        }
        #pragma unroll
        for (int q = 0; q < 4; q++){
            int idx = tid + q*256;
            int row = idx >> 5, q4 = idx & 31;
            float4 v = *(const float4*)(g_p2 + (size_t)(m*BB*N2 + b*N2 + j0 + row)*HH + q4*4);
            *(float4*)&s_p2[row][q4*4] = v;
        }
        __syncthreads();
        u64t al[4], ah[4];
        #pragma unroll
        for (int r = 0; r < 4; r++){ al[r] = 0ULL; ah[r] = 0ULL; }
        #pragma unroll
        for (int hv = 0; hv < 32; hv++){
            ulonglong2 w4  = *(const ulonglong2*)&s_w2[m][hv*4];
            ulonglong2 p2v = *(const ulonglong2*)&s_p2[j][hv*4];
            #pragma unroll
            for (int r = 0; r < 4; r++){
                ulonglong2 pa = *(const ulonglong2*)&s_p1[ia + r][hv*4];
                al[r] = px_fma(px_max0(px_add(pa.x, p2v.x)), w4.x, al[r]);
                ah[r] = px_fma(px_max0(px_add(pa.y, p2v.y)), w4.y, ah[r]);
            }
        }
        #pragma unroll
        for (int r = 0; r < 4; r++)
            acc[r][m] = px_sum(al[r]) + px_sum(ah[r]);
    }
    float vdwc2 = vdwc[0]*vdwc[0];
    float ec = 0.f, ev = 0.f;
    int jl = j0 + j;
    float c2v = c2[b*N2 + jl], v2v = val2[b*N2 + jl], n2v = nmm2[b*N2 + jl];
    #pragma unroll
    for (int q = 0; q < 4; q++){
        int il = i1 + ia + q;
        float v0 = acc[q][0] + s_b2v[0];
        float v1 = acc[q][1] + s_b2v[1];
        float v2 = acc[q][2] + s_b2v[2];
        float v3 = acc[q][3] + s_b2v[3];
        float v4 = acc[q][4] + s_b2v[4];
        int pix = (b*N1 + il)*N2 + jl;
        const float* dv = dmv + (size_t)pix*3;
        float dx = dv[0], dy = dv[1], dz = dv[2];
        float dm = sqrtf(dx*dx + dy*dy + dz*dz + 1e-10f);
        if (dm < 0.5f) dm = 1e10f;
        float l2dm = __log2f(dm);
        float cA  = sigmoidf_(v0);
        float cN  = 2.f*sigmoidf_(v1) + 1.f;
        float q12 = c1[b*N1 + il]*c2v;
        float e_c = cA*q12*exp2f(-cN*l2dm);
        e_c *= val1[b*N1 + il]*v2v;
        e_c = fminf(fmaxf(e_c, -100.f), 100.f);
        float vAv = (0.6f*sigmoidf_(v2) + 0.7f)*vdwc2*eps[pix];
        float vBv = tanhf(v3)*0.6f + 0.7f;
        float vNv = 2.f*sigmoidf_(v4) + 5.f;
        float dm0 = sig[pix]*vBv;
        if (dm0 < 1e-4f) dm0 = 1.f;
        float r  = exp2f(vNv*(__log2f(dm0) - l2dm));
        float e_v = vAv*(r*r - 2.f*r);
        e_v *= nmm1[b*N1 + il]*n2v;
        e_v = fminf(e_v, 100.f);
        ec += e_c; ev += e_v;
    }
    #pragma unroll
    for (int o = 16; o; o >>= 1){
        ec += __shfl_xor_sync(0xffffffffu, ec, o);
        ev += __shfl_xor_sync(0xffffffffu, ev, o);
    }
    if (lane == 0){ s_red[w] = ec; s_red[8 + w] = ev; }
    __syncthreads();
    if (tid == 0){
        float tec = 0.f, tev = 0.f;
        #pragma unroll
        for (int qq = 0; qq < 8; qq++){ tec += s_red[qq]; tev += s_red[8 + qq]; }
        g_pec[biy*12 + bix] = tec;
        g_pev[biy*12 + bix] = tev;
    }
}

// ---------------- finalize ----------------
__global__ __launch_bounds__(DD) void k_final(const float* __restrict__ valid1,
                                              const float* __restrict__ delta_uff,
                                              const float* __restrict__ duff,
                                              const float* __restrict__ iW1,
                                              const float* __restrict__ ib1,
                                              const float* __restrict__ iW2,
                                              const float* __restrict__ ib2,
                                              float* __restrict__ out){
    int b = blockIdx.x, d = threadIdx.x;
    __shared__ float s_hs[DD];
    __shared__ float s_red[DD];
    float hs = 0.f;
    for (int i = 0; i < N1; i++) hs += g_h1g[(b*N1 + i)*DD + d]*valid1[b*N1 + i];
    s_hs[d] = hs;
    __syncthreads();
    float hid = ib1[d];
    #pragma unroll 4
    for (int k = 0; k < DD; k++) hid += s_hs[k]*iW1[k*HH + d];
    hid = fmaxf(hid, 0.f);
    s_red[d] = hid*iW2[d];
    __syncthreads();
    for (int s = 64; s; s >>= 1){ if (d < s) s_red[d] += s_red[d + s]; __syncthreads(); }
    float inter = s_red[0] + ib2[0];
    __syncthreads();
    float tec = 0.f;
    for (int q = d; q < 144; q += DD) tec += g_pec[b*144 + q];
    s_red[d] = tec;
    __syncthreads();
    for (int s = 64; s; s >>= 1){ if (d < s) s_red[d] += s_red[d + s]; __syncthreads(); }
    float tecs = s_red[0];
    __syncthreads();
    float tev = 0.f;
    for (int q = d; q < 144; q += DD) tev += g_pev[b*144 + q];
    s_red[d] = tev;
    __syncthreads();
    for (int s = 64; s; s >>= 1){ if (d < s) s_red[d] += s_red[d + s]; __syncthreads(); }
    if (d == 0){
        out[b*4 + 0] = tecs;
        out[b*4 + 1] = s_red[0];
        out[b*4 + 2] = duff[0]*duff[0]*delta_uff[b];
        out[b*4 + 3] = inter;
    }
}

// ---------------- launch ----------------
// d_in follows setup_inputs() dict insertion order:
//   0:h1 1:h2 2:adj1 3:dmv 4:charge1 5:charge2 6:vdw_epsilon 7:vdw_sigma
//   8:delta_uff 9:valid1 10:valid2 11:no_metal1 12:no_metal2 13:node_W
//   14:gat_W 15:gat_Wb 16:gat_A 17:gat_gW 18:gat_gb 19:pair_W1 20:pair_b1
//   21:pair_W2 22:pair_b2 23:vdw_coeff 24:duff_coeff 25:int_W1 26:int_b1
//   27:int_W2 28:int_b2
extern "C" void kernel_launch(void* const* d_in, const int* in_sizes, int n_in,
                              void* d_out, int out_size){
    const float* h1        = (const float*)d_in[0];
    const float* h2        = (const float*)d_in[1];
    const float* adj1      = (const float*)d_in[2];
    const float* dmv       = (const float*)d_in[3];
    const float* charge1   = (const float*)d_in[4];
    const float* charge2   = (const float*)d_in[5];
    const float* eps       = (const float*)d_in[6];
    const float* sig       = (const float*)d_in[7];
    const float* delta_uff = (const float*)d_in[8];
    const float* valid1    = (const float*)d_in[9];
    const float* valid2    = (const float*)d_in[10];
    const float* nm1       = (const float*)d_in[11];
    const float* nm2       = (const float*)d_in[12];
    const float* nodeW     = (const float*)d_in[13];
    const float* gatW      = (const float*)d_in[14];
    const float* gatWb     = (const float*)d_in[15];
    const float* gatA      = (const float*)d_in[16];
    const float* gatgW     = (const float*)d_in[17];
    const float* gatgb     = (const float*)d_in[18];
    const float* pW1       = (const float*)d_in[19];
    const float* pb1       = (const float*)d_in[20];
    const float* pW2       = (const float*)d_in[21];
    const float* pb2       = (const float*)d_in[22];
    const float* vdwc      = (const float*)d_in[23];
    const float* duffc     = (const float*)d_in[24];
    const float* iW1       = (const float*)d_in[25];
    const float* ib1       = (const float*)d_in[26];
    const float* iW2       = (const float*)d_in[27];
    const float* ib2       = (const float*)d_in[28];
    float* out = (float*)d_out;

    static int attr_set = 0;
    if (!attr_set){
        cudaFuncSetAttribute(k_fuse, cudaFuncAttributeMaxDynamicSharedMemorySize, FUSE_SMEM);
        attr_set = 1;
    }

    k_pre_node<<<LL*DD + (BB*(N1+N2))/4, 128>>>(gatW, gatWb, gatA, h1, h2, nodeW);
    k_stage2<<<192 + 240, 128>>>(gatW, gatWb, pW1);
    for (int l = 0; l < LL; l++){
        k_e    <<<dim3(N1/64, N1/32, BB), 256>>>(l & 1);
        k_stats<<<BB*N1/8, 256>>>(adj1);
        k_fuse <<<BB*N1/4, 128, FUSE_SMEM>>>(adj1, gatgW, gatgb, gatW, gatWb, l, (l < LL-1) ? 1 : 0);
    }
    k_proj1<<<240, 128>>>(pW1, pb1);
    k_pair<<<dim3(N2/32, BB*N1/32), 256>>>(dmv, charge1, charge2, eps, sig,
                                           valid1, valid2, nm1, nm2, pW2, pb2, vdwc);
    k_final<<<BB, DD>>>(valid1, delta_uff, duffc, iW1, ib1, iW2, ib2, out);
}

// round 16
// speedup vs baseline: 1.6941x; 1.1615x over previous
#include <cuda_runtime.h>
#include <math.h>

#define BB 2
#define N1 384
#define N2 384
#define DD 128
#define HH 128
#define LL 3
#define NF 54

// ---------------- scratch (device globals; no allocation) ----------------
static __device__ float g_h1g[BB*N1*DD];
static __device__ float g_h2g[BB*N2*DD];
static __device__ float g_hX [2*BB*N1*DD];   // ping-pong h
static __device__ float g_hAX[2*BB*N1*DD];   // ping-pong hA
static __device__ float g_P  [BB*N1*N1];
static __device__ float g_PT [BB*N1*N1];
static __device__ float g_m  [BB*N1];
static __device__ float g_iz [BB*N1];
static __device__ float g_p1 [5*BB*N1*HH];
static __device__ float g_p2 [5*BB*N2*HH];
static __device__ float g_WA [LL*DD*DD];
static __device__ float g_bA [LL*DD];
static __device__ float g_pec[288];
static __device__ float g_pev[288];

__device__ __forceinline__ float sigmoidf_(float x){ return 1.f/(1.f+__expf(-x)); }

// packed f32x2 helpers (sm_100+ PTX): only add/mul/fma exist in f32x2 form.
typedef unsigned long long u64t;
__device__ __forceinline__ u64t px_add(u64t a, u64t b){
    u64t r; asm("add.rn.f32x2 %0, %1, %2;" : "=l"(r) : "l"(a), "l"(b)); return r;
}
__device__ __forceinline__ u64t px_fma(u64t a, u64t b, u64t c){
    u64t r; asm("fma.rn.f32x2 %0, %1, %2, %3;" : "=l"(r) : "l"(a), "l"(b), "l"(c)); return r;
}
__device__ __forceinline__ u64t px_max0(u64t a){
    float x, y;
    asm("mov.b64 {%0, %1}, %2;" : "=f"(x), "=f"(y) : "l"(a));
    x = fmaxf(x, 0.f);
    y = fmaxf(y, 0.f);
    u64t r;
    asm("mov.b64 %0, {%1, %2};" : "=l"(r) : "f"(x), "f"(y));
    return r;
}
__device__ __forceinline__ float px_sum(u64t v){
    float x, y;
    asm("mov.b64 {%0, %1}, %2;" : "=f"(x), "=f"(y) : "l"(v));
    return x + y;
}

// ---------------- fused: WA=W@A, bA=Wb@A  +  node projection ----------------
__global__ __launch_bounds__(128) void k_pre_node(const float* __restrict__ W,
                                                  const float* __restrict__ Wb,
                                                  const float* __restrict__ A,
                                                  const float* __restrict__ h1,
                                                  const float* __restrict__ h2,
                                                  const float* __restrict__ nW){
    int bi = blockIdx.x, d = threadIdx.x;
    if (bi < LL*DD){
        int l = bi / DD, k = bi % DD;
        __shared__ float sw[DD];
        __shared__ float sb[DD];
        sw[d] = W[(l*DD + k)*DD + d];
        if (k == 0) sb[d] = Wb[l*DD + d];
        __syncthreads();
        const float* Al = A + l*DD*DD;
        float acc = 0.f;
        #pragma unroll 8
        for (int m = 0; m < DD; m++) acc += sw[m]*Al[m*DD + d];
        g_WA[(l*DD + k)*DD + d] = acc;
        if (k == 0){
            float bacc = 0.f;
            #pragma unroll 4
            for (int m = 0; m < DD; m++) bacc += sb[m]*Al[m*DD + d];
            g_bA[l*DD + d] = bacc;
        }
    } else {
        int r0 = (bi - LL*DD)*4;
        __shared__ float sx[4][NF];
        bool lig = (r0 < BB*N1);
        const float* src = lig ? (h1 + r0*NF) : (h2 + (r0 - BB*N1)*NF);
        for (int idx = d; idx < 4*NF; idx += 128) ((float*)sx)[idx] = src[idx];
        __syncthreads();
        float acc[4] = {0.f,0.f,0.f,0.f};
        #pragma unroll 2
        for (int k = 0; k < NF; k++){
            float wv = nW[k*DD + d];
            #pragma unroll
            for (int ii = 0; ii < 4; ii++) acc[ii] += sx[ii][k]*wv;
        }
        float* dst = lig ? (g_h1g + r0*DD) : (g_h2g + (r0 - BB*N1)*DD);
        #pragma unroll
        for (int ii = 0; ii < 4; ii++) dst[ii*DD + d] = acc[ii];
    }
}

// ---------------- stage2: gat_h layer0 (192 blocks, 4 rows) + protein pair-proj (240 blocks) ----------------
__global__ __launch_bounds__(128) void k_stage2(const float* __restrict__ gatW,
                                                const float* __restrict__ gatWb,
                                                const float* __restrict__ W1){
    int bi = blockIdx.x, d = threadIdx.x;
    __shared__ float sx[16][DD];
    if (bi < 192){
        int r0 = bi*4;
        #pragma unroll
        for (int ii = 0; ii < 4; ii++) sx[ii][d] = g_h1g[(r0 + ii)*DD + d];
        __syncthreads();
        float wb = gatWb[d], bav = g_bA[d];
        float h[4], ha[4];
        #pragma unroll
        for (int ii = 0; ii < 4; ii++){ h[ii] = wb; ha[ii] = bav; }
        #pragma unroll 8
        for (int k = 0; k < DD; k++){
            float wv  = gatW[k*DD + d];
            float wav = g_WA[k*DD + d];
            #pragma unroll
            for (int ii = 0; ii < 4; ii++){
                h [ii] += sx[ii][k]*wv;
                ha[ii] += sx[ii][k]*wav;
            }
        }
        #pragma unroll
        for (int ii = 0; ii < 4; ii++){
            g_hX [(r0 + ii)*DD + d] = h [ii];
            g_hAX[(r0 + ii)*DD + d] = ha[ii];
        }
    } else {
        int pi = bi - 192;
        int m  = pi / 48;
        int r0 = (pi % 48)*16;
        #pragma unroll
        for (int ii = 0; ii < 16; ii++) sx[ii][d] = g_h2g[(r0 + ii)*DD + d];
        __syncthreads();
        const float* W = W1 + m*2*DD*HH + DD*HH;   // protein half, no bias
        float acc[16];
        #pragma unroll
        for (int ii = 0; ii < 16; ii++) acc[ii] = 0.f;
        #pragma unroll 8
        for (int k = 0; k < DD; k++){
            float wv = W[k*HH + d];
            #pragma unroll
            for (int ii = 0; ii < 16; ii++) acc[ii] = fmaf(sx[ii][k], wv, acc[ii]);
        }
        #pragma unroll
        for (int ii = 0; ii < 16; ii++) g_p2[(m*BB*N2 + r0 + ii)*HH + d] = acc[ii];
    }
}

// ---------------- P = hA @ h^T (and coalesced P^T) : 32x64 tiles, 144 blocks ----------------
__global__ __launch_bounds__(256) void k_e(int cur){
    const float* hb  = g_hX  + cur*BB*N1*DD;
    const float* hab = g_hAX + cur*BB*N1*DD;
    int b = blockIdx.z, j0 = blockIdx.y*32, k0 = blockIdx.x*64;
    __shared__ __align__(16) float sA[64][36];
    __shared__ __align__(16) float sB[64][68];
    int tid = threadIdx.x;
    int tx = tid & 15, ty = tid >> 4;
    float acc[2][4];
    #pragma unroll
    for (int r = 0; r < 2; r++)
        #pragma unroll
        for (int c = 0; c < 4; c++) acc[r][c] = 0.f;
    const float* baseA = hab + (b*N1 + j0)*DD;
    const float* baseB = hb  + (b*N1 + k0)*DD;
    for (int ks = 0; ks < 2; ks++){
        __syncthreads();
        #pragma unroll
        for (int q = 0; q < 2; q++){
            int idx = tid + q*256;
            int row = idx & 31, kq = idx >> 5;
            float4 va = *(const float4*)(baseA + row*DD + ks*64 + kq*4);
            sA[kq*4+0][row] = va.x; sA[kq*4+1][row] = va.y;
            sA[kq*4+2][row] = va.z; sA[kq*4+3][row] = va.w;
        }
        #pragma unroll
        for (int q = 0; q < 4; q++){
            int idx = tid + q*256;
            int row = idx & 63, kq = idx >> 6;
            float4 vb = *(const float4*)(baseB + row*DD + ks*64 + kq*4);
            sB[kq*4+0][row] = vb.x; sB[kq*4+1][row] = vb.y;
            sB[kq*4+2][row] = vb.z; sB[kq*4+3][row] = vb.w;
        }
        __syncthreads();
        #pragma unroll 8
        for (int kk = 0; kk < 64; kk++){
            float2 av = *(const float2*)&sA[kk][ty*2];
            float4 bv = *(const float4*)&sB[kk][tx*4];
            acc[0][0] = fmaf(av.x, bv.x, acc[0][0]);
            acc[0][1] = fmaf(av.x, bv.y, acc[0][1]);
            acc[0][2] = fmaf(av.x, bv.z, acc[0][2]);
            acc[0][3] = fmaf(av.x, bv.w, acc[0][3]);
            acc[1][0] = fmaf(av.y, bv.x, acc[1][0]);
            acc[1][1] = fmaf(av.y, bv.y, acc[1][1]);
            acc[1][2] = fmaf(av.y, bv.z, acc[1][2]);
            acc[1][3] = fmaf(av.y, bv.w, acc[1][3]);
        }
    }
    #pragma unroll
    for (int r = 0; r < 2; r++){
        float4 o = make_float4(acc[r][0], acc[r][1], acc[r][2], acc[r][3]);
        *(float4*)&g_P[(size_t)(b*N1 + j0 + ty*2 + r)*N1 + k0 + tx*4] = o;
    }
    // stage transposed tile into retired sA, then write PT rows coalesced
    __syncthreads();
    float* sT = &sA[0][0];     // 64*36 floats, row stride 36 (16B-aligned rows)
    #pragma unroll
    for (int r = 0; r < 2; r++)
        #pragma unroll
        for (int c = 0; c < 4; c++)
            sT[(tx*4 + c)*36 + ty*2 + r] = acc[r][c];
    __syncthreads();
    #pragma unroll
    for (int q = 0; q < 2; q++){
        int idx = tid + q*256;
        int row = idx >> 3;        // 0..63 (k-tile row)
        int cq  = idx & 7;         // float4 column index 0..7
        float4 v = *(const float4*)&sT[row*36 + cq*4];
        *(float4*)&g_PT[(size_t)(b*N1 + k0 + row)*N1 + j0 + cq*4] = v;
    }
}

// ---------------- column stats via symmetry: m[j], invZ[j] from row j of e (float4) ----------------
__global__ __launch_bounds__(256) void k_stats(const float* __restrict__ adj){
    int w = threadIdx.x >> 5, lane = threadIdx.x & 31;
    int rg = blockIdx.x*8 + w;                 // global row 0..767
    const float4* pr  = (const float4*)(g_P  + (size_t)rg*N1);
    const float4* ptr = (const float4*)(g_PT + (size_t)rg*N1);
    const float4* ar  = (const float4*)(adj  + (size_t)rg*N1);
    float ev[12];
    float mx = -INFINITY;
    #pragma unroll
    for (int t = 0; t < 3; t++){
        int i4 = lane + t*32;
        float4 a = ar[i4], p = pr[i4], q = ptr[i4];
        float e0 = (a.x > 0.f) ? (p.x + q.x) : -9e15f;
        float e1 = (a.y > 0.f) ? (p.y + q.y) : -9e15f;
        float e2 = (a.z > 0.f) ? (p.z + q.z) : -9e15f;
        float e3 = (a.w > 0.f) ? (p.w + q.w) : -9e15f;
        ev[t*4+0] = e0; ev[t*4+1] = e1; ev[t*4+2] = e2; ev[t*4+3] = e3;
        mx = fmaxf(mx, fmaxf(fmaxf(e0, e1), fmaxf(e2, e3)));
    }
    #pragma unroll
    for (int o = 16; o; o >>= 1) mx = fmaxf(mx, __shfl_xor_sync(0xffffffffu, mx, o));
    float sum = 0.f;
    #pragma unroll
    for (int t = 0; t < 12; t++) sum += __expf(ev[t] - mx);
    #pragma unroll
    for (int o = 16; o; o >>= 1) sum += __shfl_xor_sync(0xffffffffu, sum, o);
    if (lane == 0){
        g_m [rg] = mx;
        g_iz[rg] = 1.f/sum;
    }
}

// ---------------- fused: att on the fly, h'=relu(att@h) smem-tiled, 256 threads row-split ----------------
// dynamic smem (floats): s_h[2][64][128]=16384, s_att[4][384]=1536, s_m 384, s_iz 384,
//                        s_g[4][128]=512, sx[4][128]=512, s_c 4  -> 19716 floats
#define FUSE_SMEM (19716*4)
__global__ __launch_bounds__(256) void k_fuse(const float* __restrict__ adj,
                                              const float* __restrict__ gW,
                                              const float* __restrict__ gb,
                                              const float* __restrict__ gatW,
                                              const float* __restrict__ gatWb,
                                              int l, int has_next){
    extern __shared__ __align__(16) float sm[];
    float* s_h   = sm;                  // [2][64][128]
    float* s_att = sm + 16384;          // [4][384]
    float* s_m   = sm + 16384 + 1536;
    float* s_iz  = s_m + 384;
    float* s_g   = s_iz + 384;          // [4][128]
    float* sx    = s_g + 512;           // [4][128]
    float* s_c   = sx + 512;            // [4]
    int r0 = blockIdx.x*4;
    int b  = r0 / N1;
    int tid = threadIdx.x;
    int d = tid & 127, half = tid >> 7;
    const float* hb = g_hX + (l & 1)*BB*N1*DD;
    const float* hbase = hb + b*N1*DD;
    // stage tile 0 (256 threads)
    #pragma unroll
    for (int q = 0; q < 8; q++){
        int idx = tid + q*256;
        int row = idx >> 5, cq = idx & 31;
        *(float4*)&s_h[(size_t)row*DD + cq*4] = *(const float4*)(hbase + row*DD + cq*4);
    }
    for (int idx = tid; idx < N1; idx += 256){
        s_m [idx] = g_m [b*N1 + idx];
        s_iz[idx] = g_iz[b*N1 + idx];
    }
    float xd[2];
    #pragma unroll
    for (int q = 0; q < 2; q++) xd[q] = g_h1g[(r0 + half*2 + q)*DD + d];
    __syncthreads();
    // build attention weights (float4 streams, 256 threads)
    for (int idx4 = tid; idx4 < 4*96; idx4 += 256){
        int ii = idx4 / 96, j4 = idx4 % 96;
        int j  = j4*4;
        float4 a = *(const float4*)(adj  + (size_t)(r0 + ii)*N1 + j);
        float4 p = *(const float4*)(g_P  + (size_t)(r0 + ii)*N1 + j);
        float4 q = *(const float4*)(g_PT + (size_t)(r0 + ii)*N1 + j);
        float4 wv;
        wv.x = (a.x > 0.f) ? __expf(p.x + q.x - s_m[j+0])*s_iz[j+0]*a.x : 0.f;
        wv.y = (a.y > 0.f) ? __expf(p.y + q.y - s_m[j+1])*s_iz[j+1]*a.y : 0.f;
        wv.z = (a.z > 0.f) ? __expf(p.z + q.z - s_m[j+2])*s_iz[j+2]*a.z : 0.f;
        wv.w = (a.w > 0.f) ? __expf(p.w + q.w - s_m[j+3])*s_iz[j+3]*a.w : 0.f;
        *(float4*)&s_att[ii*N1 + j] = wv;
    }
    __syncthreads();
    // mainloop over 6 tiles, double-buffered; each half accumulates its 2 rows
    float hp[2] = {0.f, 0.f};
    const float* awb = s_att + (half*2)*N1;
    for (int t = 0; t < 6; t++){
        if (t < 5){
            const float* src = hbase + (t + 1)*64*DD;
            float* dst = s_h + ((t + 1) & 1)*64*DD;
            #pragma unroll
            for (int q = 0; q < 8; q++){
                int idx = tid + q*256;
                int row = idx >> 5, cq = idx & 31;
                *(float4*)&dst[(size_t)row*DD + cq*4] = *(const float4*)(src + row*DD + cq*4);
            }
        }
        const float* cur = s_h + (t & 1)*64*DD;
        const float* aw  = awb + t*64;
        #pragma unroll 8
        for (int jj = 0; jj < 64; jj++){
            float hv = cur[jj*DD + d];
            hp[0] = fmaf(aw[jj],      hv, hp[0]);
            hp[1] = fmaf(aw[N1 + jj], hv, hp[1]);
        }
        __syncthreads();
    }
    float gw1 = gW[l*2*DD + d], gw2 = gW[l*2*DD + DD + d], gbv = gb[l];
    #pragma unroll
    for (int q = 0; q < 2; q++){
        hp[q] = fmaxf(hp[q], 0.f);
        s_g[(half*2 + q)*DD + d] = fmaf(xd[q], gw1, hp[q]*gw2);
    }
    __syncthreads();
    int w = tid >> 5, lane = tid & 31;
    if (w < 4){   // warp w reduces row w
        float s = s_g[w*DD + lane] + s_g[w*DD + lane+32] + s_g[w*DD + lane+64] + s_g[w*DD + lane+96];
        #pragma unroll
        for (int o = 16; o; o >>= 1) s += __shfl_xor_sync(0xffffffffu, s, o);
        if (lane == 0) s_c[w] = sigmoidf_(s + gbv);
    }
    __syncthreads();
    #pragma unroll
    for (int q = 0; q < 2; q++){
        int row = half*2 + q;
        float coeff = s_c[row];
        float v = coeff*xd[q] + (1.f - coeff)*hp[q];
        g_h1g[(r0 + row)*DD + d] = v;
        sx[row*DD + d] = v;
    }
    if (!has_next) return;
    __syncthreads();
    int nl = l + 1;
    const float* W  = gatW + nl*DD*DD;
    const float* WA = g_WA + nl*DD*DD;
    float wb  = gatWb[nl*DD + d];
    float bav = g_bA [nl*DD + d];
    float h[2], ha[2];
    #pragma unroll
    for (int q = 0; q < 2; q++){ h[q] = wb; ha[q] = bav; }
    const float* sxr = sx + (half*2)*DD;
    #pragma unroll 8
    for (int k = 0; k < DD; k++){
        float wv  = W [k*DD + d];
        float wav = WA[k*DD + d];
        #pragma unroll
        for (int q = 0; q < 2; q++){
            h [q] += sxr[q*DD + k]*wv;
            ha[q] += sxr[q*DD + k]*wav;
        }
    }
    float* ho  = g_hX  + (nl & 1)*BB*N1*DD;
    float* hao = g_hAX + (nl & 1)*BB*N1*DD;
    #pragma unroll
    for (int q = 0; q < 2; q++){
        ho [(r0 + half*2 + q)*DD + d] = h [q];
        hao[(r0 + half*2 + q)*DD + d] = ha[q];
    }
}

// ---------------- ligand pair projections (16 rows/block, 240 blocks) ----------------
__global__ __launch_bounds__(128) void k_proj1(const float* __restrict__ W1,
                                               const float* __restrict__ b1){
    int bi = blockIdx.x;
    int m  = bi / 48;
    int r0 = (bi % 48)*16;
    int hh = threadIdx.x;
    __shared__ float sx[16][DD];
    #pragma unroll
    for (int ii = 0; ii < 16; ii++) sx[ii][hh] = g_h1g[(r0 + ii)*DD + hh];
    __syncthreads();
    const float* W = W1 + m*2*DD*HH;
    float bias = b1[m*HH + hh];
    float acc[16];
    #pragma unroll
    for (int ii = 0; ii < 16; ii++) acc[ii] = bias;
    #pragma unroll 8
    for (int k = 0; k < DD; k++){
        float wv = W[k*HH + hh];
        #pragma unroll
        for (int ii = 0; ii < 16; ii++) acc[ii] = fmaf(sx[ii][k], wv, acc[ii]);
    }
    #pragma unroll
    for (int ii = 0; ii < 16; ii++) g_p1[(m*BB*N1 + r0 + ii)*HH + hh] = acc[ii];
}

// ---------------- pair energies: 32i x 32j tile, 4 i-rows per warp, f32x2 mainloop ----------------
__global__ __launch_bounds__(256) void k_pair(const float* __restrict__ dmv,
                                              const float* __restrict__ c1,
                                              const float* __restrict__ c2,
                                              const float* __restrict__ eps,
                                              const float* __restrict__ sig,
                                              const float* __restrict__ val1,
                                              const float* __restrict__ val2,
                                              const float* __restrict__ nmm1,
                                              const float* __restrict__ nmm2,
                                              const float* __restrict__ W2,
                                              const float* __restrict__ b2,
                                              const float* __restrict__ vdwc){
    int bix = blockIdx.x;          // j tile 0..11
    int biy = blockIdx.y;          // i tile 0..23 (32 rows each)
    int r0  = biy*32;
    int b   = r0 / N1;
    int i1  = r0 % N1;
    int j0  = bix*32;
    __shared__ __align__(16) float s_p1[32][132];
    __shared__ __align__(16) float s_p2[32][132];
    __shared__ __align__(16) float s_w2[5][128];
    __shared__ float s_b2v[5];
    __shared__ float s_red[16];
    int tid = threadIdx.x, lane = tid & 31, w = tid >> 5;
    int j  = lane;
    int ia = w*4;
    for (int idx = tid; idx < 5*DD; idx += 256) s_w2[idx/DD][idx%DD] = W2[idx];
    if (tid < 5) s_b2v[tid] = b2[tid];
    float acc[4][5];
    for (int m = 0; m < 5; m++){
        __syncthreads();
        #pragma unroll
        for (int q = 0; q < 4; q++){
            int idx = tid + q*256;
            int row = idx >> 5, q4 = idx & 31;
            float4 v = *(const float4*)(g_p1 + (size_t)(m*BB*N1 + r0 + row)*HH + q4*4);
            *(float4*)&s_p1[row][q4*4] = v;
        }
        #pragma unroll
        for (int q = 0; q < 4; q++){
            int idx = tid + q*256;
            int row = idx >> 5, q4 = idx & 31;
            float4 v = *(const float4*)(g_p2 + (size_t)(m*BB*N2 + b*N2 + j0 + row)*HH + q4*4);
            *(float4*)&s_p2[row][q4*4] = v;
        }
        __syncthreads();
        u64t al[4], ah[4];
        #pragma unroll
        for (int r = 0; r < 4; r++){ al[r] = 0ULL; ah[r] = 0ULL; }
        #pragma unroll
        for (int hv = 0; hv < 32; hv++){
            ulonglong2 w4  = *(const ulonglong2*)&s_w2[m][hv*4];
            ulonglong2 p2v = *(const ulonglong2*)&s_p2[j][hv*4];
            #pragma unroll
            for (int r = 0; r < 4; r++){
                ulonglong2 pa = *(const ulonglong2*)&s_p1[ia + r][hv*4];
                al[r] = px_fma(px_max0(px_add(pa.x, p2v.x)), w4.x, al[r]);
                ah[r] = px_fma(px_max0(px_add(pa.y, p2v.y)), w4.y, ah[r]);
            }
        }
        #pragma unroll
        for (int r = 0; r < 4; r++)
            acc[r][m] = px_sum(al[r]) + px_sum(ah[r]);
    }
    float vdwc2 = vdwc[0]*vdwc[0];
    float ec = 0.f, ev = 0.f;
    int jl = j0 + j;
    float c2v = c2[b*N2 + jl], v2v = val2[b*N2 + jl], n2v = nmm2[b*N2 + jl];
    #pragma unroll
    for (int q = 0; q < 4; q++){
        int il = i1 + ia + q;
        float v0 = acc[q][0] + s_b2v[0];
        float v1 = acc[q][1] + s_b2v[1];
        float v2 = acc[q][2] + s_b2v[2];
        float v3 = acc[q][3] + s_b2v[3];
        float v4 = acc[q][4] + s_b2v[4];
        int pix = (b*N1 + il)*N2 + jl;
        const float* dv = dmv + (size_t)pix*3;
        float dx = dv[0], dy = dv[1], dz = dv[2];
        float dm = sqrtf(dx*dx + dy*dy + dz*dz + 1e-10f);
        if (dm < 0.5f) dm = 1e10f;
        float l2dm = __log2f(dm);
        float cA  = sigmoidf_(v0);
        float cN  = 2.f*sigmoidf_(v1) + 1.f;
        float q12 = c1[b*N1 + il]*c2v;
        float e_c = cA*q12*exp2f(-cN*l2dm);
        e_c *= val1[b*N1 + il]*v2v;
        e_c = fminf(fmaxf(e_c, -100.f), 100.f);
        float vAv = (0.6f*sigmoidf_(v2) + 0.7f)*vdwc2*eps[pix];
        float vBv = tanhf(v3)*0.6f + 0.7f;
        float vNv = 2.f*sigmoidf_(v4) + 5.f;
        float dm0 = sig[pix]*vBv;
        if (dm0 < 1e-4f) dm0 = 1.f;
        float r  = exp2f(vNv*(__log2f(dm0) - l2dm));
        float e_v = vAv*(r*r - 2.f*r);
        e_v *= nmm1[b*N1 + il]*n2v;
        e_v = fminf(e_v, 100.f);
        ec += e_c; ev += e_v;
    }
    #pragma unroll
    for (int o = 16; o; o >>= 1){
        ec += __shfl_xor_sync(0xffffffffu, ec, o);
        ev += __shfl_xor_sync(0xffffffffu, ev, o);
    }
    if (lane == 0){ s_red[w] = ec; s_red[8 + w] = ev; }
    __syncthreads();
    if (tid == 0){
        float tec = 0.f, tev = 0.f;
        #pragma unroll
        for (int qq = 0; qq < 8; qq++){ tec += s_red[qq]; tev += s_red[8 + qq]; }
        g_pec[biy*12 + bix] = tec;
        g_pev[biy*12 + bix] = tev;
    }
}

// ---------------- finalize ----------------
__global__ __launch_bounds__(DD) void k_final(const float* __restrict__ valid1,
                                              const float* __restrict__ delta_uff,
                                              const float* __restrict__ duff,
                                              const float* __restrict__ iW1,
                                              const float* __restrict__ ib1,
                                              const float* __restrict__ iW2,
                                              const float* __restrict__ ib2,
                                              float* __restrict__ out){
    int b = blockIdx.x, d = threadIdx.x;
    __shared__ float s_hs[DD];
    __shared__ float s_red[DD];
    float hs = 0.f;
    for (int i = 0; i < N1; i++) hs += g_h1g[(b*N1 + i)*DD + d]*valid1[b*N1 + i];
    s_hs[d] = hs;
    __syncthreads();
    float hid = ib1[d];
    #pragma unroll 4
    for (int k = 0; k < DD; k++) hid += s_hs[k]*iW1[k*HH + d];
    hid = fmaxf(hid, 0.f);
    s_red[d] = hid*iW2[d];
    __syncthreads();
    for (int s = 64; s; s >>= 1){ if (d < s) s_red[d] += s_red[d + s]; __syncthreads(); }
    float inter = s_red[0] + ib2[0];
    __syncthreads();
    float tec = 0.f;
    for (int q = d; q < 144; q += DD) tec += g_pec[b*144 + q];
    s_red[d] = tec;
    __syncthreads();
    for (int s = 64; s; s >>= 1){ if (d < s) s_red[d] += s_red[d + s]; __syncthreads(); }
    float tecs = s_red[0];
    __syncthreads();
    float tev = 0.f;
    for (int q = d; q < 144; q += DD) tev += g_pev[b*144 + q];
    s_red[d] = tev;
    __syncthreads();
    for (int s = 64; s; s >>= 1){ if (d < s) s_red[d] += s_red[d + s]; __syncthreads(); }
    if (d == 0){
        out[b*4 + 0] = tecs;
        out[b*4 + 1] = s_red[0];
        out[b*4 + 2] = duff[0]*duff[0]*delta_uff[b];
        out[b*4 + 3] = inter;
    }
}

// ---------------- launch ----------------
// d_in follows setup_inputs() dict insertion order:
//   0:h1 1:h2 2:adj1 3:dmv 4:charge1 5:charge2 6:vdw_epsilon 7:vdw_sigma
//   8:delta_uff 9:valid1 10:valid2 11:no_metal1 12:no_metal2 13:node_W
//   14:gat_W 15:gat_Wb 16:gat_A 17:gat_gW 18:gat_gb 19:pair_W1 20:pair_b1
//   21:pair_W2 22:pair_b2 23:vdw_coeff 24:duff_coeff 25:int_W1 26:int_b1
//   27:int_W2 28:int_b2
extern "C" void kernel_launch(void* const* d_in, const int* in_sizes, int n_in,
                              void* d_out, int out_size){
    const float* h1        = (const float*)d_in[0];
    const float* h2        = (const float*)d_in[1];
    const float* adj1      = (const float*)d_in[2];
    const float* dmv       = (const float*)d_in[3];
    const float* charge1   = (const float*)d_in[4];
    const float* charge2   = (const float*)d_in[5];
    const float* eps       = (const float*)d_in[6];
    const float* sig       = (const float*)d_in[7];
    const float* delta_uff = (const float*)d_in[8];
    const float* valid1    = (const float*)d_in[9];
    const float* valid2    = (const float*)d_in[10];
    const float* nm1       = (const float*)d_in[11];
    const float* nm2       = (const float*)d_in[12];
    const float* nodeW     = (const float*)d_in[13];
    const float* gatW      = (const float*)d_in[14];
    const float* gatWb     = (const float*)d_in[15];
    const float* gatA      = (const float*)d_in[16];
    const float* gatgW     = (const float*)d_in[17];
    const float* gatgb     = (const float*)d_in[18];
    const float* pW1       = (const float*)d_in[19];
    const float* pb1       = (const float*)d_in[20];
    const float* pW2       = (const float*)d_in[21];
    const float* pb2       = (const float*)d_in[22];
    const float* vdwc      = (const float*)d_in[23];
    const float* duffc     = (const float*)d_in[24];
    const float* iW1       = (const float*)d_in[25];
    const float* ib1       = (const float*)d_in[26];
    const float* iW2       = (const float*)d_in[27];
    const float* ib2       = (const float*)d_in[28];
    float* out = (float*)d_out;

    static int attr_set = 0;
    if (!attr_set){
        cudaFuncSetAttribute(k_fuse, cudaFuncAttributeMaxDynamicSharedMemorySize, FUSE_SMEM);
        attr_set = 1;
    }

    k_pre_node<<<LL*DD + (BB*(N1+N2))/4, 128>>>(gatW, gatWb, gatA, h1, h2, nodeW);
    k_stage2<<<192 + 240, 128>>>(gatW, gatWb, pW1);
    for (int l = 0; l < LL; l++){
        k_e    <<<dim3(N1/64, N1/32, BB), 256>>>(l & 1);
        k_stats<<<BB*N1/8, 256>>>(adj1);
        k_fuse <<<BB*N1/4, 256, FUSE_SMEM>>>(adj1, gatgW, gatgb, gatW, gatWb, l, (l < LL-1) ? 1 : 0);
    }
    k_proj1<<<240, 128>>>(pW1, pb1);
    k_pair<<<dim3(N2/32, BB*N1/32), 256>>>(dmv, charge1, charge2, eps, sig,
                                           valid1, valid2, nm1, nm2, pW2, pb2, vdwc);
    k_final<<<BB, DD>>>(valid1, delta_uff, duffc, iW1, ib1, iW2, ib2, out);
}